// round 1
// baseline (speedup 1.0000x reference)
#include <cuda_runtime.h>
#include <math_constants.h>

// ---------------- problem constants ----------------
#define N_API   50000
#define N_FILE  20000
#define N_EDGE  250000
#define N_INP   512
#define N_OUT   256
#define NH      3
#define HD      768   // NH*N_OUT

// ---------------- device scratch (no cudaMalloc allowed) ----------------
__device__ float    d_Wcomb[N_INP * HD];      // Wapi @ Wsrc            [512,768]
__device__ float    d_W2   [N_INP * HD];      // per-head Wcomb_h@Whead_h [512,768]
__device__ float    d_u    [N_INP * NH];      // Wdst_h @ attn_r_h      [512,3]
__device__ float    d_Vl   [N_INP * NH];      // per-head Wcomb_h@attn_l_h
__device__ float    d_Vr   [N_INP * NH];      // Wfile @ u
__device__ float    d_bsrc [HD];
__device__ float    d_bg   [HD];
__device__ float    d_bl   [NH];
__device__ float    d_br   [NH];
__device__ float    d_cbias[N_OUT];
__device__ float    d_g    [(size_t)N_API * HD];   // 153.6 MB
__device__ float    d_el   [N_API * NH];
__device__ float    d_er   [N_FILE * NH];
__device__ float    d_ee   [N_EDGE * NH];          // edge logits, then exp values
__device__ unsigned d_mkey [N_FILE * NH];
__device__ float    d_z    [N_FILE * NH];

// ---------------- helpers: order-preserving float<->uint ----------------
__device__ __forceinline__ unsigned f2o(float f) {
    unsigned u = __float_as_uint(f);
    return (u & 0x80000000u) ? ~u : (u | 0x80000000u);
}
__device__ __forceinline__ float o2f(unsigned u) {
    return __uint_as_float((u & 0x80000000u) ? (u & 0x7FFFFFFFu) : ~u);
}
#define MKEY_NEG_INF 0x007FFFFFu   // f2o(-inf)

// ---------------- generic fp32 SGEMM: C[M,N] = A[M,K]@B[K,N] (+bias) ----
// 128x128 tile, BK=8, 256 threads, 8x8 per thread. N,K must be mult of 128/8.
#define BM 128
#define BN 128
#define BK 8
#define TM 8
#define TN 8

__global__ __launch_bounds__(256, 2)
void sgemm(const float* __restrict__ A, int lda,
           const float* __restrict__ B, int ldb,
           float* __restrict__ C, int ldc,
           int M, int N, int K,
           const float* __restrict__ bias)
{
    __shared__ float As[BK][BM];
    __shared__ float Bs[BK][BN];
    const int tid = threadIdx.x;
    const int bm  = blockIdx.y * BM;
    const int bn  = blockIdx.x * BN;

    const int aRow  = tid >> 1;          // 0..127
    const int aCol4 = (tid & 1) * 4;     // 0 or 4
    const int bRow  = tid >> 5;          // 0..7
    const int bCol4 = (tid & 31) * 4;

    const int ty = tid >> 4, tx = tid & 15;

    float acc[TM][TN];
#pragma unroll
    for (int i = 0; i < TM; i++)
#pragma unroll
        for (int j = 0; j < TN; j++) acc[i][j] = 0.f;

    for (int k0 = 0; k0 < K; k0 += BK) {
        float4 av;
        if (bm + aRow < M)
            av = *(const float4*)(A + (size_t)(bm + aRow) * lda + k0 + aCol4);
        else
            av = make_float4(0.f, 0.f, 0.f, 0.f);
        As[aCol4 + 0][aRow] = av.x;
        As[aCol4 + 1][aRow] = av.y;
        As[aCol4 + 2][aRow] = av.z;
        As[aCol4 + 3][aRow] = av.w;

        float4 bv = *(const float4*)(B + (size_t)(k0 + bRow) * ldb + bn + bCol4);
        *(float4*)(&Bs[bRow][bCol4]) = bv;

        __syncthreads();
#pragma unroll
        for (int k = 0; k < BK; k++) {
            float ra[TM], rb[TN];
#pragma unroll
            for (int i = 0; i < TM; i++) ra[i] = As[k][ty * TM + i];
#pragma unroll
            for (int j = 0; j < TN; j++) rb[j] = Bs[k][tx * TN + j];
#pragma unroll
            for (int i = 0; i < TM; i++)
#pragma unroll
                for (int j = 0; j < TN; j++)
                    acc[i][j] = fmaf(ra[i], rb[j], acc[i][j]);
        }
        __syncthreads();
    }

#pragma unroll
    for (int i = 0; i < TM; i++) {
        int row = bm + ty * TM + i;
        if (row >= M) break;
#pragma unroll
        for (int j = 0; j < TN; j += 4) {
            int col = bn + tx * TN + j;
            float4 v;
            v.x = acc[i][j];     v.y = acc[i][j + 1];
            v.z = acc[i][j + 2]; v.w = acc[i][j + 3];
            if (bias) {
                v.x += bias[col];     v.y += bias[col + 1];
                v.z += bias[col + 2]; v.w += bias[col + 3];
            }
            *(float4*)(C + (size_t)row * ldc + col) = v;
        }
    }
}

// ---------------- tiny precompute kernels ----------------
__global__ void k_bsrc(const float* __restrict__ bapi, const float* __restrict__ Wsrc) {
    int c = blockIdx.x * blockDim.x + threadIdx.x;
    if (c >= HD) return;
    float s = 0.f;
    for (int k = 0; k < N_INP; k++) s = fmaf(bapi[k], Wsrc[k * HD + c], s);
    d_bsrc[c] = s;
}

__global__ void k_u(const float* __restrict__ Wdst, const float* __restrict__ attn_r) {
    int idx = blockIdx.x * blockDim.x + threadIdx.x;
    if (idx >= N_INP * NH) return;
    int k = idx / NH, h = idx % NH;
    float s = 0.f;
    for (int j = 0; j < N_OUT; j++)
        s = fmaf(Wdst[k * HD + h * N_OUT + j], attn_r[h * N_OUT + j], s);
    d_u[idx] = s;
}

__global__ void k_Vl(const float* __restrict__ attn_l) {
    int idx = blockIdx.x * blockDim.x + threadIdx.x;
    if (idx >= N_INP * NH) return;
    int k = idx / NH, h = idx % NH;
    float s = 0.f;
    for (int j = 0; j < N_OUT; j++)
        s = fmaf(d_Wcomb[k * HD + h * N_OUT + j], attn_l[h * N_OUT + j], s);
    d_Vl[idx] = s;
}

__global__ void k_Vr(const float* __restrict__ Wfile) {
    int idx = blockIdx.x * blockDim.x + threadIdx.x;
    if (idx >= N_INP * NH) return;
    int k = idx / NH, h = idx % NH;
    float s = 0.f;
    for (int c = 0; c < N_INP; c++)
        s = fmaf(Wfile[k * N_INP + c], d_u[c * NH + h], s);
    d_Vr[idx] = s;
}

__global__ void k_biases(const float* __restrict__ attn_l,
                         const float* __restrict__ bfile,
                         const float* __restrict__ Whead,
                         const float* __restrict__ gat_bias,
                         const float* __restrict__ bhead)
{
    int t = blockIdx.x * blockDim.x + threadIdx.x;
    if (t < NH) {                                   // bl
        float s = 0.f;
        for (int j = 0; j < N_OUT; j++)
            s = fmaf(d_bsrc[t * N_OUT + j], attn_l[t * N_OUT + j], s);
        d_bl[t] = s;
    } else if (t < 2 * NH) {                        // br
        int h = t - NH;
        float s = 0.f;
        for (int c = 0; c < N_INP; c++)
            s = fmaf(bfile[c], d_u[c * NH + h], s);
        d_br[h] = s;
    } else if (t < 2 * NH + HD) {                   // bg
        int c = t - 2 * NH;
        int h = c / N_OUT;
        float s = 0.f;
        for (int j = 0; j < N_OUT; j++)
            s = fmaf(d_bsrc[h * N_OUT + j], Whead[(h * N_OUT + j) * N_OUT + (c % N_OUT)], s);
        d_bg[c] = s;
    } else if (t < 2 * NH + HD + N_OUT) {           // cbias
        int j2 = t - 2 * NH - HD;
        float s = bhead[j2];
        for (int c = 0; c < HD; c++)
            s = fmaf(gat_bias[c], Whead[c * N_OUT + j2], s);
        d_cbias[j2] = s;
    }
}

// ---------------- node logits: out[n,h] = X[n,:]@V[:,h] + b3[h] --------
__global__ void node_logits(const float* __restrict__ X,
                            const float* __restrict__ V,
                            const float* __restrict__ b3,
                            float* __restrict__ out, int Nn)
{
    __shared__ float sV[N_INP * NH];
    int t = threadIdx.x;
    for (int i = t; i < N_INP * NH; i += blockDim.x) sV[i] = V[i];
    __syncthreads();
    int warp = t >> 5, lane = t & 31;
    int n = blockIdx.x * (blockDim.x >> 5) + warp;
    if (n >= Nn) return;
    const float* x = X + (size_t)n * N_INP;
    float s0 = 0.f, s1 = 0.f, s2 = 0.f;
    for (int k = lane; k < N_INP; k += 32) {
        float xv = x[k];
        s0 = fmaf(xv, sV[k * 3 + 0], s0);
        s1 = fmaf(xv, sV[k * 3 + 1], s1);
        s2 = fmaf(xv, sV[k * 3 + 2], s2);
    }
#pragma unroll
    for (int o = 16; o > 0; o >>= 1) {
        s0 += __shfl_down_sync(0xffffffffu, s0, o);
        s1 += __shfl_down_sync(0xffffffffu, s1, o);
        s2 += __shfl_down_sync(0xffffffffu, s2, o);
    }
    if (lane == 0) {
        out[n * 3 + 0] = s0 + b3[0];
        out[n * 3 + 1] = s1 + b3[1];
        out[n * 3 + 2] = s2 + b3[2];
    }
}

// ---------------- init: mkey=-inf, z=0, out=cbias ----------------
__global__ void k_init(float* __restrict__ out) {
    int i = blockIdx.x * blockDim.x + threadIdx.x;
    if (i < N_FILE * N_OUT) out[i] = d_cbias[i & (N_OUT - 1)];
    if (i < N_FILE * NH) { d_mkey[i] = MKEY_NEG_INF; d_z[i] = 0.f; }
}

// ---------------- edge pass 1: leaky_relu logits + segment max ----------
__global__ void edge_logits(const int* __restrict__ src, const int* __restrict__ dst, int E) {
    int i = blockIdx.x * blockDim.x + threadIdx.x;
    if (i >= E) return;
    int s = src[i], d = dst[i];
#pragma unroll
    for (int h = 0; h < NH; h++) {
        float v = d_el[s * NH + h] + d_er[d * NH + h];
        v = v > 0.f ? v : 0.2f * v;
        d_ee[i * NH + h] = v;
        atomicMax(&d_mkey[d * NH + h], f2o(v));
    }
}

// ---------------- edge pass 2: exp + segment sum ----------------
__global__ void edge_exp(const int* __restrict__ dst, int E) {
    int i = blockIdx.x * blockDim.x + threadIdx.x;
    if (i >= E) return;
    int d = dst[i];
#pragma unroll
    for (int h = 0; h < NH; h++) {
        float m = o2f(d_mkey[d * NH + h]);
        float a = expf(d_ee[i * NH + h] - m);
        d_ee[i * NH + h] = a;
        atomicAdd(&d_z[d * NH + h], a);
    }
}

// ---------------- edge pass 3: weighted scatter of g into out ----------
__global__ __launch_bounds__(N_OUT)
void aggregate(const int* __restrict__ src, const int* __restrict__ dst,
               float* __restrict__ out)
{
    int i = blockIdx.x;              // edge id
    int t = threadIdx.x;             // 0..255  (output column)
    __shared__ float al[NH];
    __shared__ int ss, sd;
    if (t == 0) { ss = src[i]; sd = dst[i]; }
    __syncthreads();
    if (t < NH) al[t] = d_ee[i * NH + t] / d_z[sd * NH + t];
    __syncthreads();
    const float* grow = d_g + (size_t)ss * HD;
    float v = al[0] * grow[t] + al[1] * grow[N_OUT + t] + al[2] * grow[2 * N_OUT + t];
    atomicAdd(&out[(size_t)sd * N_OUT + t], v);
}

// ---------------- launch ----------------
extern "C" void kernel_launch(void* const* d_in, const int* in_sizes, int n_in,
                              void* d_out, int out_size)
{
    const float* emb_api  = (const float*)d_in[0];
    const float* emb_file = (const float*)d_in[1];
    // d_in[2] = e_tensor : unused by the reference
    const int*   src      = (const int*)d_in[3];
    const int*   dst      = (const int*)d_in[4];
    const float* Wapi     = (const float*)d_in[5];
    const float* bapi     = (const float*)d_in[6];
    const float* Wfile    = (const float*)d_in[7];
    const float* bfile    = (const float*)d_in[8];
    const float* Wsrc     = (const float*)d_in[9];
    const float* Wdst     = (const float*)d_in[10];
    const float* attn_l   = (const float*)d_in[11];
    const float* attn_r   = (const float*)d_in[12];
    const float* gat_bias = (const float*)d_in[13];
    const float* Whead    = (const float*)d_in[14];
    const float* bhead    = (const float*)d_in[15];
    float* out = (float*)d_out;

    const int E = in_sizes[3];

    // resolve device-symbol addresses (host side, graph-capture safe: no allocs)
    float *p_Wcomb, *p_W2, *p_Vl, *p_Vr, *p_bl, *p_br, *p_bg, *p_g, *p_el, *p_er;
    cudaGetSymbolAddress((void**)&p_Wcomb, d_Wcomb);
    cudaGetSymbolAddress((void**)&p_W2,    d_W2);
    cudaGetSymbolAddress((void**)&p_Vl,    d_Vl);
    cudaGetSymbolAddress((void**)&p_Vr,    d_Vr);
    cudaGetSymbolAddress((void**)&p_bl,    d_bl);
    cudaGetSymbolAddress((void**)&p_br,    d_br);
    cudaGetSymbolAddress((void**)&p_bg,    d_bg);
    cudaGetSymbolAddress((void**)&p_g,     d_g);
    cudaGetSymbolAddress((void**)&p_el,    d_el);
    cudaGetSymbolAddress((void**)&p_er,    d_er);

    // 1. independent tiny precompute
    k_bsrc<<<(HD + 255) / 256, 256>>>(bapi, Wsrc);
    k_u<<<(N_INP * NH + 255) / 256, 256>>>(Wdst, attn_r);

    // 2. Wcomb = Wapi @ Wsrc            [512,512]@[512,768]
    sgemm<<<dim3(HD / BN, (N_INP + BM - 1) / BM), 256>>>(
        Wapi, N_INP, Wsrc, HD, p_Wcomb, HD, N_INP, HD, N_INP, nullptr);

    // 3. folded attention vectors + bias constants
    k_Vl<<<(N_INP * NH + 255) / 256, 256>>>(attn_l);
    k_Vr<<<(N_INP * NH + 255) / 256, 256>>>(Wfile);
    k_biases<<<((2 * NH + HD + N_OUT) + 255) / 256, 256>>>(attn_l, bfile, Whead, gat_bias, bhead);

    // 4. W2_h = Wcomb_h @ Whead_h       3x [512,256]@[256,256]
    for (int h = 0; h < NH; h++) {
        sgemm<<<dim3(N_OUT / BN, (N_INP + BM - 1) / BM), 256>>>(
            p_Wcomb + h * N_OUT, HD,
            Whead + (size_t)h * N_OUT * N_OUT, N_OUT,
            p_W2 + h * N_OUT, HD,
            N_INP, N_OUT, N_OUT, nullptr);
    }

    // 5. node logits el / er
    node_logits<<<(N_API  + 7) / 8, 256>>>(emb_api,  p_Vl, p_bl, p_el, N_API);
    node_logits<<<(N_FILE + 7) / 8, 256>>>(emb_file, p_Vr, p_br, p_er, N_FILE);

    // 6. the big GEMM: g = emb_api @ W2 + bg   [50000,512]@[512,768]
    sgemm<<<dim3(HD / BN, (N_API + BM - 1) / BM), 256>>>(
        emb_api, N_INP, p_W2, HD, p_g, HD, N_API, HD, N_INP, p_bg);

    // 7. init output + softmax scratch
    k_init<<<(N_FILE * N_OUT + 255) / 256, 256>>>(out);

    // 8-10. edge softmax + aggregation
    edge_logits<<<(E + 255) / 256, 256>>>(src, dst, E);
    edge_exp<<<(E + 255) / 256, 256>>>(dst, E);
    aggregate<<<E, N_OUT>>>(src, dst, out);
}

// round 2
// speedup vs baseline: 1.4568x; 1.4568x over previous
#include <cuda_runtime.h>
#include <math_constants.h>

// ---------------- problem constants ----------------
#define N_API   50000
#define N_FILE  20000
#define N_INP   512
#define N_OUT   256
#define NH      3
#define HD      768   // NH*N_OUT
#define KAGG    1536  // NH*N_INP

// ---------------- device scratch (no cudaMalloc allowed) ----------------
__device__ float d_Wcomb[N_INP * HD];        // Wapi @ Wsrc                  [512,768]
__device__ float d_W2   [KAGG * N_OUT];      // stacked Wcomb_h@Whead_h      [1536,256]
__device__ float d_u    [N_INP * NH];        // Wdst_h @ attn_r_h            [512,3]
__device__ float d_Vl   [N_INP * NH];
__device__ float d_Vr   [N_INP * NH];
__device__ float d_bsrc [HD];
__device__ float d_bl   [NH];
__device__ float d_br   [NH];
__device__ float d_bconst[N_OUT];            // bsrc @ Whead
__device__ float d_cbias [N_OUT];            // gat_bias @ Whead + bhead
__device__ float d_agg  [(size_t)N_FILE * KAGG];   // 122.9 MB
__device__ float d_el   [N_API * NH];
__device__ float d_er   [N_FILE * NH];
__device__ int   d_deg  [N_FILE];
__device__ int   d_cur  [N_FILE];
__device__ int   d_off  [N_FILE + 1];
__device__ float d_hasedge[N_FILE];
__device__ int   d_srcs [262144];            // CSR-sorted src ids (E<=250000)

// ---------------- generic fp32 SGEMM: C[M,N] = A[M,K]@B[K,N] (+epilogue) ----
#define BM 128
#define BN 128
#define BK 8
#define TM 8
#define TN 8

__global__ __launch_bounds__(256, 2)
void sgemm(const float* __restrict__ A, int lda,
           const float* __restrict__ B, int ldb,
           float* __restrict__ C, int ldc,
           int M, int N, int K,
           const float* __restrict__ bias,      // per-col, nullable
           const float* __restrict__ bias2,     // per-col, nullable
           const float* __restrict__ rowflag)   // per-row scale on bias2
{
    __shared__ float As[BK][BM];
    __shared__ float Bs[BK][BN];
    const int tid = threadIdx.x;
    const int bm  = blockIdx.y * BM;
    const int bn  = blockIdx.x * BN;

    const int aRow  = tid >> 1;
    const int aCol4 = (tid & 1) * 4;
    const int bRow  = tid >> 5;
    const int bCol4 = (tid & 31) * 4;
    const int ty = tid >> 4, tx = tid & 15;

    float acc[TM][TN];
#pragma unroll
    for (int i = 0; i < TM; i++)
#pragma unroll
        for (int j = 0; j < TN; j++) acc[i][j] = 0.f;

    for (int k0 = 0; k0 < K; k0 += BK) {
        float4 av;
        if (bm + aRow < M)
            av = *(const float4*)(A + (size_t)(bm + aRow) * lda + k0 + aCol4);
        else
            av = make_float4(0.f, 0.f, 0.f, 0.f);
        As[aCol4 + 0][aRow] = av.x;
        As[aCol4 + 1][aRow] = av.y;
        As[aCol4 + 2][aRow] = av.z;
        As[aCol4 + 3][aRow] = av.w;

        float4 bv = *(const float4*)(B + (size_t)(k0 + bRow) * ldb + bn + bCol4);
        *(float4*)(&Bs[bRow][bCol4]) = bv;

        __syncthreads();
#pragma unroll
        for (int k = 0; k < BK; k++) {
            float ra[TM], rb[TN];
#pragma unroll
            for (int i = 0; i < TM; i++) ra[i] = As[k][ty * TM + i];
#pragma unroll
            for (int j = 0; j < TN; j++) rb[j] = Bs[k][tx * TN + j];
#pragma unroll
            for (int i = 0; i < TM; i++)
#pragma unroll
                for (int j = 0; j < TN; j++)
                    acc[i][j] = fmaf(ra[i], rb[j], acc[i][j]);
        }
        __syncthreads();
    }

#pragma unroll
    for (int i = 0; i < TM; i++) {
        int row = bm + ty * TM + i;
        if (row >= M) break;
        float rf = rowflag ? rowflag[row] : 0.f;
#pragma unroll
        for (int j = 0; j < TN; j += 4) {
            int col = bn + tx * TN + j;
            float4 v;
            v.x = acc[i][j];     v.y = acc[i][j + 1];
            v.z = acc[i][j + 2]; v.w = acc[i][j + 3];
            if (bias) {
                v.x += bias[col];     v.y += bias[col + 1];
                v.z += bias[col + 2]; v.w += bias[col + 3];
            }
            if (bias2) {
                v.x += rf * bias2[col];     v.y += rf * bias2[col + 1];
                v.z += rf * bias2[col + 2]; v.w += rf * bias2[col + 3];
            }
            *(float4*)(C + (size_t)row * ldc + col) = v;
        }
    }
}

// ---------------- tiny precompute ----------------
__global__ void k_bsrc(const float* __restrict__ bapi, const float* __restrict__ Wsrc) {
    int c = blockIdx.x * blockDim.x + threadIdx.x;
    if (c >= HD) return;
    float s = 0.f;
    for (int k = 0; k < N_INP; k++) s = fmaf(bapi[k], Wsrc[k * HD + c], s);
    d_bsrc[c] = s;
}

__global__ void k_u(const float* __restrict__ Wdst, const float* __restrict__ attn_r) {
    int idx = blockIdx.x * blockDim.x + threadIdx.x;
    if (idx >= N_INP * NH) return;
    int k = idx / NH, h = idx % NH;
    float s = 0.f;
    for (int j = 0; j < N_OUT; j++)
        s = fmaf(Wdst[k * HD + h * N_OUT + j], attn_r[h * N_OUT + j], s);
    d_u[idx] = s;
}

__global__ void k_Vl(const float* __restrict__ attn_l) {
    int idx = blockIdx.x * blockDim.x + threadIdx.x;
    if (idx >= N_INP * NH) return;
    int k = idx / NH, h = idx % NH;
    float s = 0.f;
    for (int j = 0; j < N_OUT; j++)
        s = fmaf(d_Wcomb[k * HD + h * N_OUT + j], attn_l[h * N_OUT + j], s);
    d_Vl[idx] = s;
}

__global__ void k_Vr(const float* __restrict__ Wfile) {
    int idx = blockIdx.x * blockDim.x + threadIdx.x;
    if (idx >= N_INP * NH) return;
    int k = idx / NH, h = idx % NH;
    float s = 0.f;
    for (int c = 0; c < N_INP; c++)
        s = fmaf(Wfile[k * N_INP + c], d_u[c * NH + h], s);
    d_Vr[idx] = s;
}

// t<3: bl ; 3..5: br ; 6..261: bconst ; 262..517: cbias
__global__ void k_biases(const float* __restrict__ attn_l,
                         const float* __restrict__ bfile,
                         const float* __restrict__ Whead,
                         const float* __restrict__ gat_bias,
                         const float* __restrict__ bhead)
{
    int t = blockIdx.x * blockDim.x + threadIdx.x;
    if (t < NH) {
        float s = 0.f;
        for (int j = 0; j < N_OUT; j++)
            s = fmaf(d_bsrc[t * N_OUT + j], attn_l[t * N_OUT + j], s);
        d_bl[t] = s;
    } else if (t < 2 * NH) {
        int h = t - NH;
        float s = 0.f;
        for (int c = 0; c < N_INP; c++)
            s = fmaf(bfile[c], d_u[c * NH + h], s);
        d_br[h] = s;
    } else if (t < 2 * NH + N_OUT) {
        int j = t - 2 * NH;
        float s = 0.f;
        for (int c = 0; c < HD; c++)
            s = fmaf(d_bsrc[c], Whead[c * N_OUT + j], s);
        d_bconst[j] = s;
    } else if (t < 2 * NH + 2 * N_OUT) {
        int j = t - 2 * NH - N_OUT;
        float s = bhead[j];
        for (int c = 0; c < HD; c++)
            s = fmaf(gat_bias[c], Whead[c * N_OUT + j], s);
        d_cbias[j] = s;
    }
}

// ---------------- node logits: out[n,h] = X[n,:]@V[:,h] + b3[h] --------
__global__ void node_logits(const float* __restrict__ X,
                            const float* __restrict__ V,
                            const float* __restrict__ b3,
                            float* __restrict__ out, int Nn)
{
    __shared__ float sV[N_INP * NH];
    int t = threadIdx.x;
    for (int i = t; i < N_INP * NH; i += blockDim.x) sV[i] = V[i];
    __syncthreads();
    int warp = t >> 5, lane = t & 31;
    int n = blockIdx.x * (blockDim.x >> 5) + warp;
    if (n >= Nn) return;
    const float* x = X + (size_t)n * N_INP;
    float s0 = 0.f, s1 = 0.f, s2 = 0.f;
    for (int k = lane; k < N_INP; k += 32) {
        float xv = x[k];
        s0 = fmaf(xv, sV[k * 3 + 0], s0);
        s1 = fmaf(xv, sV[k * 3 + 1], s1);
        s2 = fmaf(xv, sV[k * 3 + 2], s2);
    }
#pragma unroll
    for (int o = 16; o > 0; o >>= 1) {
        s0 += __shfl_down_sync(0xffffffffu, s0, o);
        s1 += __shfl_down_sync(0xffffffffu, s1, o);
        s2 += __shfl_down_sync(0xffffffffu, s2, o);
    }
    if (lane == 0) {
        out[n * 3 + 0] = s0 + b3[0];
        out[n * 3 + 1] = s1 + b3[1];
        out[n * 3 + 2] = s2 + b3[2];
    }
}

// ---------------- CSR build ----------------
__global__ void k_zero() {
    int i = blockIdx.x * blockDim.x + threadIdx.x;
    if (i < N_FILE) { d_deg[i] = 0; d_cur[i] = 0; }
}

__global__ void k_count(const int* __restrict__ dst, int E) {
    int i = blockIdx.x * blockDim.x + threadIdx.x;
    if (i < E) atomicAdd(&d_deg[dst[i]], 1);
}

__global__ void k_scan() {   // single block, 512 threads
    __shared__ int part[512];
    int t = threadIdx.x;
    const int per = (N_FILE + 511) / 512;
    int b = t * per;
    int sum = 0;
    for (int i = 0; i < per; i++) {
        int idx = b + i;
        if (idx < N_FILE) sum += d_deg[idx];
    }
    part[t] = sum;
    __syncthreads();
    for (int o = 1; o < 512; o <<= 1) {
        int v = (t >= o) ? part[t - o] : 0;
        __syncthreads();
        part[t] += v;
        __syncthreads();
    }
    int run = part[t] - sum;   // exclusive base
    for (int i = 0; i < per; i++) {
        int idx = b + i;
        if (idx < N_FILE) {
            d_off[idx] = run;
            d_hasedge[idx] = d_deg[idx] ? 1.f : 0.f;
            run += d_deg[idx];
        }
    }
    if (t == 511) d_off[N_FILE] = run;
}

__global__ void k_scatter(const int* __restrict__ src, const int* __restrict__ dst, int E) {
    int i = blockIdx.x * blockDim.x + threadIdx.x;
    if (i >= E) return;
    int d = dst[i];
    int p = atomicAdd(&d_cur[d], 1);
    d_srcs[d_off[d] + p] = src[i];
}

// ---------------- per-dst softmax + embedding aggregation ----------------
__device__ __forceinline__ float lrelu(float v) { return v > 0.f ? v : 0.2f * v; }

__global__ __launch_bounds__(128)
void gat_aggregate(const float* __restrict__ emb)
{
    int d = blockIdx.x;
    int t = threadIdx.x;
    int lane = t & 31, warp = t >> 5;
    int start = d_off[d], end = d_off[d + 1];
    float* aout = d_agg + (size_t)d * KAGG;

    __shared__ float s_er[NH], s_m[NH], s_z[NH];
    __shared__ float red[4][NH];

    if (t < NH) s_er[t] = d_er[d * NH + t];
    __syncthreads();
    float er0 = s_er[0], er1 = s_er[1], er2 = s_er[2];

    // pass 1: per-head max
    float m0 = -CUDART_INF_F, m1 = -CUDART_INF_F, m2 = -CUDART_INF_F;
    for (int e = start + t; e < end; e += 128) {
        int s = d_srcs[e];
        m0 = fmaxf(m0, lrelu(d_el[s * 3 + 0] + er0));
        m1 = fmaxf(m1, lrelu(d_el[s * 3 + 1] + er1));
        m2 = fmaxf(m2, lrelu(d_el[s * 3 + 2] + er2));
    }
#pragma unroll
    for (int o = 16; o > 0; o >>= 1) {
        m0 = fmaxf(m0, __shfl_xor_sync(0xffffffffu, m0, o));
        m1 = fmaxf(m1, __shfl_xor_sync(0xffffffffu, m1, o));
        m2 = fmaxf(m2, __shfl_xor_sync(0xffffffffu, m2, o));
    }
    if (lane == 0) { red[warp][0] = m0; red[warp][1] = m1; red[warp][2] = m2; }
    __syncthreads();
    if (t < NH) s_m[t] = fmaxf(fmaxf(red[0][t], red[1][t]), fmaxf(red[2][t], red[3][t]));
    __syncthreads();
    m0 = s_m[0]; m1 = s_m[1]; m2 = s_m[2];

    // pass 2: per-head sum of exp
    float z0 = 0.f, z1 = 0.f, z2 = 0.f;
    for (int e = start + t; e < end; e += 128) {
        int s = d_srcs[e];
        z0 += __expf(lrelu(d_el[s * 3 + 0] + er0) - m0);
        z1 += __expf(lrelu(d_el[s * 3 + 1] + er1) - m1);
        z2 += __expf(lrelu(d_el[s * 3 + 2] + er2) - m2);
    }
#pragma unroll
    for (int o = 16; o > 0; o >>= 1) {
        z0 += __shfl_xor_sync(0xffffffffu, z0, o);
        z1 += __shfl_xor_sync(0xffffffffu, z1, o);
        z2 += __shfl_xor_sync(0xffffffffu, z2, o);
    }
    if (lane == 0) { red[warp][0] = z0; red[warp][1] = z1; red[warp][2] = z2; }
    __syncthreads();
    if (t < NH) s_z[t] = red[0][t] + red[1][t] + red[2][t] + red[3][t];
    __syncthreads();
    float iz0 = (s_z[0] > 0.f) ? 1.f / s_z[0] : 0.f;
    float iz1 = (s_z[1] > 0.f) ? 1.f / s_z[1] : 0.f;
    float iz2 = (s_z[2] > 0.f) ? 1.f / s_z[2] : 0.f;

    // pass 3: weighted aggregation; thread t owns columns [4t, 4t+4)
    float a00 = 0.f, a01 = 0.f, a02 = 0.f, a03 = 0.f;
    float a10 = 0.f, a11 = 0.f, a12 = 0.f, a13 = 0.f;
    float a20 = 0.f, a21 = 0.f, a22 = 0.f, a23 = 0.f;
    int c4 = t * 4;
    for (int e = start; e < end; e++) {
        int s = d_srcs[e];
        float w0 = __expf(lrelu(d_el[s * 3 + 0] + er0) - m0) * iz0;
        float w1 = __expf(lrelu(d_el[s * 3 + 1] + er1) - m1) * iz1;
        float w2 = __expf(lrelu(d_el[s * 3 + 2] + er2) - m2) * iz2;
        float4 x = *(const float4*)(emb + (size_t)s * N_INP + c4);
        a00 = fmaf(w0, x.x, a00); a01 = fmaf(w0, x.y, a01);
        a02 = fmaf(w0, x.z, a02); a03 = fmaf(w0, x.w, a03);
        a10 = fmaf(w1, x.x, a10); a11 = fmaf(w1, x.y, a11);
        a12 = fmaf(w1, x.z, a12); a13 = fmaf(w1, x.w, a13);
        a20 = fmaf(w2, x.x, a20); a21 = fmaf(w2, x.y, a21);
        a22 = fmaf(w2, x.z, a22); a23 = fmaf(w2, x.w, a23);
    }
    *(float4*)(aout + 0 * N_INP + c4) = make_float4(a00, a01, a02, a03);
    *(float4*)(aout + 1 * N_INP + c4) = make_float4(a10, a11, a12, a13);
    *(float4*)(aout + 2 * N_INP + c4) = make_float4(a20, a21, a22, a23);
}

// ---------------- launch ----------------
extern "C" void kernel_launch(void* const* d_in, const int* in_sizes, int n_in,
                              void* d_out, int out_size)
{
    const float* emb_api  = (const float*)d_in[0];
    const float* emb_file = (const float*)d_in[1];
    const int*   src      = (const int*)d_in[3];
    const int*   dst      = (const int*)d_in[4];
    const float* Wapi     = (const float*)d_in[5];
    const float* bapi     = (const float*)d_in[6];
    const float* Wfile    = (const float*)d_in[7];
    const float* bfile    = (const float*)d_in[8];
    const float* Wsrc     = (const float*)d_in[9];
    const float* Wdst     = (const float*)d_in[10];
    const float* attn_l   = (const float*)d_in[11];
    const float* attn_r   = (const float*)d_in[12];
    const float* gat_bias = (const float*)d_in[13];
    const float* Whead    = (const float*)d_in[14];
    const float* bhead    = (const float*)d_in[15];
    float* out = (float*)d_out;

    const int E = in_sizes[3];

    float *p_Wcomb, *p_W2, *p_Vl, *p_Vr, *p_bl, *p_br, *p_bconst, *p_cbias,
          *p_agg, *p_el, *p_er, *p_hasedge;
    cudaGetSymbolAddress((void**)&p_Wcomb,   d_Wcomb);
    cudaGetSymbolAddress((void**)&p_W2,      d_W2);
    cudaGetSymbolAddress((void**)&p_Vl,      d_Vl);
    cudaGetSymbolAddress((void**)&p_Vr,      d_Vr);
    cudaGetSymbolAddress((void**)&p_bl,      d_bl);
    cudaGetSymbolAddress((void**)&p_br,      d_br);
    cudaGetSymbolAddress((void**)&p_bconst,  d_bconst);
    cudaGetSymbolAddress((void**)&p_cbias,   d_cbias);
    cudaGetSymbolAddress((void**)&p_agg,     d_agg);
    cudaGetSymbolAddress((void**)&p_el,      d_el);
    cudaGetSymbolAddress((void**)&p_er,      d_er);
    cudaGetSymbolAddress((void**)&p_hasedge, d_hasedge);

    // CSR build + independent precompute
    k_zero<<<(N_FILE + 255) / 256, 256>>>();
    k_bsrc<<<(HD + 255) / 256, 256>>>(bapi, Wsrc);
    k_u<<<(N_INP * NH + 255) / 256, 256>>>(Wdst, attn_r);
    k_count<<<(E + 255) / 256, 256>>>(dst, E);
    k_scan<<<1, 512>>>();
    k_scatter<<<(E + 255) / 256, 256>>>(src, dst, E);

    // Wcomb = Wapi @ Wsrc   [512,512]@[512,768]
    sgemm<<<dim3(HD / BN, N_INP / BM), 256>>>(
        Wapi, N_INP, Wsrc, HD, p_Wcomb, HD, N_INP, HD, N_INP,
        nullptr, nullptr, nullptr);

    k_Vl<<<(N_INP * NH + 255) / 256, 256>>>(attn_l);
    k_Vr<<<(N_INP * NH + 255) / 256, 256>>>(Wfile);
    k_biases<<<(2 * NH + 2 * N_OUT + 255) / 256, 256>>>(attn_l, bfile, Whead, gat_bias, bhead);

    // W2stack rows [h*512 .. h*512+511] = Wcomb_h @ Whead_h  ([512,256]@[256,256])
    for (int h = 0; h < NH; h++) {
        sgemm<<<dim3(N_OUT / BN, N_INP / BM), 256>>>(
            p_Wcomb + h * N_OUT, HD,
            Whead + (size_t)h * N_OUT * N_OUT, N_OUT,
            p_W2 + (size_t)h * N_INP * N_OUT, N_OUT,
            N_INP, N_OUT, N_OUT, nullptr, nullptr, nullptr);
    }

    // node logits
    node_logits<<<(N_API  + 7) / 8, 256>>>(emb_api,  p_Vl, p_bl, p_el, N_API);
    node_logits<<<(N_FILE + 7) / 8, 256>>>(emb_file, p_Vr, p_br, p_er, N_FILE);

    // per-dst softmax + aggregation of raw embeddings
    gat_aggregate<<<N_FILE, 128>>>(emb_api);

    // out = agg @ W2stack + cbias + hasedge*bconst   [20000,1536]@[1536,256]
    sgemm<<<dim3(N_OUT / BN, (N_FILE + BM - 1) / BM), 256>>>(
        p_agg, KAGG, p_W2, N_OUT, out, N_OUT,
        N_FILE, N_OUT, KAGG, p_cbias, p_bconst, p_hasedge);
}

// round 4
// speedup vs baseline: 2.5445x; 1.7467x over previous
#include <cuda_runtime.h>
#include <math_constants.h>
#include <cstdint>

// ---------------- problem constants ----------------
#define N_API   50000
#define N_FILE  20000
#define N_INP   512
#define N_OUT   256
#define NH      3
#define HD      768   // NH*N_OUT
#define KAGG    1536  // NH*N_INP
#define M_PAD   20096 // 157*128
#define NCHUNK  48    // KAGG/32

// ---------------- device scratch ----------------
__device__ float d_Wcomb[N_INP * HD];
__device__ float d_W2   [KAGG * N_OUT];           // stacked [1536,256]
__device__ float d_W2T  [N_OUT * KAGG];           // [256,1536] tf32-rounded
__device__ float d_u    [N_INP * NH];
__device__ float d_Vl   [N_INP * NH];
__device__ float d_Vr   [N_INP * NH];
__device__ float d_bsrc [HD];
__device__ float d_bl   [NH];
__device__ float d_br   [NH];
__device__ float d_bconst[N_OUT];
__device__ float d_cbias [N_OUT];
__device__ float d_agg  [(size_t)M_PAD * KAGG];   // padded, tf32-rounded (zero-init tail)
__device__ float d_el   [N_API * NH];
__device__ float d_er   [N_FILE * NH];
__device__ int   d_deg  [N_FILE];
__device__ int   d_cur  [N_FILE];
__device__ int   d_off  [N_FILE + 1];
__device__ float d_hasedge[N_FILE];
__device__ int   d_srcs [262144];

// ---------------- helpers ----------------
__device__ __forceinline__ uint32_t smem_u32(const void* p) {
    uint32_t a;
    asm("{ .reg .u64 t; cvta.to.shared.u64 t, %1; cvt.u32.u64 %0, t; }" : "=r"(a) : "l"(p));
    return a;
}
__device__ __forceinline__ float to_tf32(float x) {
    uint32_t u = __float_as_uint(x), r;
    asm("cvt.rna.tf32.f32 %0, %1;" : "=r"(r) : "r"(u));
    return __uint_as_float(r);
}

#define CP_ASYNC16(dst, src) \
    asm volatile("cp.async.cg.shared.global [%0], [%1], 16;" :: "r"(dst), "l"(src) : "memory")
#define CP_COMMIT()  asm volatile("cp.async.commit_group;" ::: "memory")
#define CP_WAIT0()   asm volatile("cp.async.wait_group 0;" ::: "memory")
#define CP_WAIT1()   asm volatile("cp.async.wait_group 1;" ::: "memory")

__device__ __forceinline__ void mma_tf32(float* c, const uint32_t* a, const uint32_t* b) {
    asm volatile(
        "mma.sync.aligned.m16n8k8.row.col.f32.tf32.tf32.f32 "
        "{%0,%1,%2,%3}, {%4,%5,%6,%7}, {%8,%9}, {%0,%1,%2,%3};"
        : "+f"(c[0]), "+f"(c[1]), "+f"(c[2]), "+f"(c[3])
        : "r"(a[0]), "r"(a[1]), "r"(a[2]), "r"(a[3]), "r"(b[0]), "r"(b[1]));
}

// ---------------- tensor-core tf32 GEMM: C = A @ B^T + biases ----------------
// A: [M_PAD, KAGG] tf32-rounded ; B: [256, KAGG] tf32-rounded ; C: [20000, 256]
// Block 128(M) x 128(N), 8 warps, warp tile 64x32, K-chunk 32, 2-stage cp.async.
#define LDP   36                 // padded row stride (floats): 144B, 16B-aligned
#define TILE_F (128 * LDP)       // floats per tile stage
#define GEMM_SMEM_BYTES (4 * TILE_F * 4)   // As[2] + Bs[2]

__global__ void __launch_bounds__(256)
gemm_mma(const float* __restrict__ A, const float* __restrict__ B,
         float* __restrict__ C,
         const float* __restrict__ cbias,
         const float* __restrict__ bconst,
         const float* __restrict__ hasedge)
{
    extern __shared__ float sm[];
    float* As = sm;                // [2][128][LDP]
    float* Bs = sm + 2 * TILE_F;   // [2][128][LDP]

    const int tid  = threadIdx.x;
    const int wid  = tid >> 5, lane = tid & 31;
    const int wm   = wid & 1;      // 0..1  -> 64-row slice
    const int wn   = wid >> 1;     // 0..3  -> 32-col slice
    const int m0   = blockIdx.y * 128;
    const int n0   = blockIdx.x * 128;

    const int ldRow = tid >> 3;          // 0..31 -> +t*32 rows... (see below)
    const int ldK4  = (tid & 7) * 4;     // k offset in floats

    float acc[4][4][4];
#pragma unroll
    for (int a = 0; a < 4; a++)
#pragma unroll
        for (int b = 0; b < 4; b++)
#pragma unroll
            for (int c = 0; c < 4; c++) acc[a][b][c] = 0.f;

    // ---- tile loader: 128 rows x 32 floats for A and B ----
    // 256 threads * 4 iters: idx = tid + t*256; row = idx>>3 (0..127), k4 = (idx&7)*4
#define LOAD_TILE(kt, s) do {                                                   \
    int _k0 = (kt) * 32;                                                        \
    _Pragma("unroll")                                                           \
    for (int _t = 0; _t < 4; _t++) {                                            \
        int _row = ldRow + _t * 32;                                             \
        const float* _g = A + (size_t)(m0 + _row) * KAGG + _k0 + ldK4;          \
        CP_ASYNC16(smem_u32(As + (s) * TILE_F + _row * LDP + ldK4), _g);        \
    }                                                                           \
    _Pragma("unroll")                                                           \
    for (int _t = 0; _t < 4; _t++) {                                            \
        int _row = ldRow + _t * 32;                                             \
        const float* _g = B + (size_t)(n0 + _row) * KAGG + _k0 + ldK4;          \
        CP_ASYNC16(smem_u32(Bs + (s) * TILE_F + _row * LDP + ldK4), _g);        \
    }                                                                           \
    CP_COMMIT();                                                                \
} while (0)

    LOAD_TILE(0, 0);

    for (int kt = 0; kt < NCHUNK; kt++) {
        int s = kt & 1;
        if (kt + 1 < NCHUNK) { LOAD_TILE(kt + 1, s ^ 1); CP_WAIT1(); }
        else                 { CP_WAIT0(); }
        __syncthreads();

        const float* a_base = As + s * TILE_F + (wm * 64 + (lane >> 2)) * LDP;
        const float* b_base = Bs + s * TILE_F + (wn * 32 + (lane >> 2)) * LDP;

#pragma unroll
        for (int ks = 0; ks < 4; ks++) {
            int kk = ks * 8 + (lane & 3);
            uint32_t afr[4][4];
#pragma unroll
            for (int mi = 0; mi < 4; mi++) {
                const float* ap = a_base + mi * 16 * LDP;
                afr[mi][0] = __float_as_uint(ap[kk]);
                afr[mi][1] = __float_as_uint(ap[8 * LDP + kk]);
                afr[mi][2] = __float_as_uint(ap[kk + 4]);
                afr[mi][3] = __float_as_uint(ap[8 * LDP + kk + 4]);
            }
            uint32_t bfr[4][2];
#pragma unroll
            for (int ni = 0; ni < 4; ni++) {
                const float* bp = b_base + ni * 8 * LDP;
                bfr[ni][0] = __float_as_uint(bp[kk]);
                bfr[ni][1] = __float_as_uint(bp[kk + 4]);
            }
#pragma unroll
            for (int mi = 0; mi < 4; mi++)
#pragma unroll
                for (int ni = 0; ni < 4; ni++)
                    mma_tf32(acc[mi][ni], afr[mi], bfr[ni]);
        }
        __syncthreads();
    }

    // ---- epilogue: C[r, c] = acc + cbias[c] + hasedge[r]*bconst[c] ----
#pragma unroll
    for (int mi = 0; mi < 4; mi++) {
        int rbase = m0 + wm * 64 + mi * 16 + (lane >> 2);
#pragma unroll
        for (int half = 0; half < 2; half++) {
            int r = rbase + half * 8;
            if (r >= N_FILE) continue;
            float he = hasedge[r];
#pragma unroll
            for (int ni = 0; ni < 4; ni++) {
                int c0 = n0 + wn * 32 + ni * 8 + (lane & 3) * 2;
                float v0 = acc[mi][ni][half * 2 + 0] + cbias[c0]     + he * bconst[c0];
                float v1 = acc[mi][ni][half * 2 + 1] + cbias[c0 + 1] + he * bconst[c0 + 1];
                *(float2*)(C + (size_t)r * N_OUT + c0) = make_float2(v0, v1);
            }
        }
    }
}

// ---------------- fp32 SGEMM (precompute-sized), batched via blockIdx.z ----
#define BM 128
#define BN 128
#define BK 8
#define TM 8
#define TN 8

__global__ __launch_bounds__(256, 2)
void sgemm(const float* __restrict__ A, int lda,
           const float* __restrict__ B, int ldb,
           float* __restrict__ C, int ldc,
           int M, int N, int K,
           long sA, long sB, long sC)
{
    A += (long)blockIdx.z * sA;
    B += (long)blockIdx.z * sB;
    C += (long)blockIdx.z * sC;

    __shared__ float As[BK][BM];
    __shared__ float Bs[BK][BN];
    const int tid = threadIdx.x;
    const int bm  = blockIdx.y * BM;
    const int bn  = blockIdx.x * BN;

    const int aRow  = tid >> 1;
    const int aCol4 = (tid & 1) * 4;
    const int bRow  = tid >> 5;
    const int bCol4 = (tid & 31) * 4;
    const int ty = tid >> 4, tx = tid & 15;

    float acc[TM][TN];
#pragma unroll
    for (int i = 0; i < TM; i++)
#pragma unroll
        for (int j = 0; j < TN; j++) acc[i][j] = 0.f;

    for (int k0 = 0; k0 < K; k0 += BK) {
        float4 av;
        if (bm + aRow < M)
            av = *(const float4*)(A + (size_t)(bm + aRow) * lda + k0 + aCol4);
        else
            av = make_float4(0.f, 0.f, 0.f, 0.f);
        As[aCol4 + 0][aRow] = av.x;
        As[aCol4 + 1][aRow] = av.y;
        As[aCol4 + 2][aRow] = av.z;
        As[aCol4 + 3][aRow] = av.w;

        float4 bv = *(const float4*)(B + (size_t)(k0 + bRow) * ldb + bn + bCol4);
        *(float4*)(&Bs[bRow][bCol4]) = bv;

        __syncthreads();
#pragma unroll
        for (int k = 0; k < BK; k++) {
            float ra[TM], rb[TN];
#pragma unroll
            for (int i = 0; i < TM; i++) ra[i] = As[k][ty * TM + i];
#pragma unroll
            for (int j = 0; j < TN; j++) rb[j] = Bs[k][tx * TN + j];
#pragma unroll
            for (int i = 0; i < TM; i++)
#pragma unroll
                for (int j = 0; j < TN; j++)
                    acc[i][j] = fmaf(ra[i], rb[j], acc[i][j]);
        }
        __syncthreads();
    }

#pragma unroll
    for (int i = 0; i < TM; i++) {
        int row = bm + ty * TM + i;
        if (row >= M) break;
#pragma unroll
        for (int j = 0; j < TN; j += 4) {
            int col = bn + tx * TN + j;
            float4 v;
            v.x = acc[i][j];     v.y = acc[i][j + 1];
            v.z = acc[i][j + 2]; v.w = acc[i][j + 3];
            *(float4*)(C + (size_t)row * ldc + col) = v;
        }
    }
}

// ---------------- tiny precompute ----------------
__global__ void k_bsrc(const float* __restrict__ bapi, const float* __restrict__ Wsrc) {
    int c = blockIdx.x * blockDim.x + threadIdx.x;
    if (c >= HD) return;
    float s = 0.f;
    for (int k = 0; k < N_INP; k++) s = fmaf(bapi[k], Wsrc[k * HD + c], s);
    d_bsrc[c] = s;
}

__global__ void k_u(const float* __restrict__ Wdst, const float* __restrict__ attn_r) {
    int idx = blockIdx.x * blockDim.x + threadIdx.x;
    if (idx >= N_INP * NH) return;
    int k = idx / NH, h = idx % NH;
    float s = 0.f;
    for (int j = 0; j < N_OUT; j++)
        s = fmaf(Wdst[k * HD + h * N_OUT + j], attn_r[h * N_OUT + j], s);
    d_u[idx] = s;
}

__global__ void k_Vl(const float* __restrict__ attn_l) {
    int idx = blockIdx.x * blockDim.x + threadIdx.x;
    if (idx >= N_INP * NH) return;
    int k = idx / NH, h = idx % NH;
    float s = 0.f;
    for (int j = 0; j < N_OUT; j++)
        s = fmaf(d_Wcomb[k * HD + h * N_OUT + j], attn_l[h * N_OUT + j], s);
    d_Vl[idx] = s;
}

__global__ void k_Vr(const float* __restrict__ Wfile) {
    int idx = blockIdx.x * blockDim.x + threadIdx.x;
    if (idx >= N_INP * NH) return;
    int k = idx / NH, h = idx % NH;
    float s = 0.f;
    for (int c = 0; c < N_INP; c++)
        s = fmaf(Wfile[k * N_INP + c], d_u[c * NH + h], s);
    d_Vr[idx] = s;
}

__global__ void k_biases(const float* __restrict__ attn_l,
                         const float* __restrict__ bfile,
                         const float* __restrict__ Whead,
                         const float* __restrict__ gat_bias,
                         const float* __restrict__ bhead)
{
    int t = blockIdx.x * blockDim.x + threadIdx.x;
    if (t < NH) {
        float s = 0.f;
        for (int j = 0; j < N_OUT; j++)
            s = fmaf(d_bsrc[t * N_OUT + j], attn_l[t * N_OUT + j], s);
        d_bl[t] = s;
    } else if (t < 2 * NH) {
        int h = t - NH;
        float s = 0.f;
        for (int c = 0; c < N_INP; c++)
            s = fmaf(bfile[c], d_u[c * NH + h], s);
        d_br[h] = s;
    } else if (t < 2 * NH + N_OUT) {
        int j = t - 2 * NH;
        float s = 0.f;
        for (int c = 0; c < HD; c++)
            s = fmaf(d_bsrc[c], Whead[c * N_OUT + j], s);
        d_bconst[j] = s;
    } else if (t < 2 * NH + 2 * N_OUT) {
        int j = t - 2 * NH - N_OUT;
        float s = bhead[j];
        for (int c = 0; c < HD; c++)
            s = fmaf(gat_bias[c], Whead[c * N_OUT + j], s);
        d_cbias[j] = s;
    }
}

// W2T[n,k] = tf32(W2[k,n])
__global__ void k_w2t() {
    int idx = blockIdx.x * blockDim.x + threadIdx.x;
    if (idx >= KAGG * N_OUT) return;
    int n = idx / KAGG, k = idx % KAGG;
    d_W2T[idx] = to_tf32(d_W2[(size_t)k * N_OUT + n]);
}

// ---------------- node logits ----------------
__global__ void node_logits(const float* __restrict__ X,
                            const float* __restrict__ V,
                            const float* __restrict__ b3,
                            float* __restrict__ out, int Nn)
{
    __shared__ float sV[N_INP * NH];
    int t = threadIdx.x;
    for (int i = t; i < N_INP * NH; i += blockDim.x) sV[i] = V[i];
    __syncthreads();
    int warp = t >> 5, lane = t & 31;
    int n = blockIdx.x * (blockDim.x >> 5) + warp;
    if (n >= Nn) return;
    const float* x = X + (size_t)n * N_INP;
    float s0 = 0.f, s1 = 0.f, s2 = 0.f;
    for (int k = lane; k < N_INP; k += 32) {
        float xv = x[k];
        s0 = fmaf(xv, sV[k * 3 + 0], s0);
        s1 = fmaf(xv, sV[k * 3 + 1], s1);
        s2 = fmaf(xv, sV[k * 3 + 2], s2);
    }
#pragma unroll
    for (int o = 16; o > 0; o >>= 1) {
        s0 += __shfl_down_sync(0xffffffffu, s0, o);
        s1 += __shfl_down_sync(0xffffffffu, s1, o);
        s2 += __shfl_down_sync(0xffffffffu, s2, o);
    }
    if (lane == 0) {
        out[n * 3 + 0] = s0 + b3[0];
        out[n * 3 + 1] = s1 + b3[1];
        out[n * 3 + 2] = s2 + b3[2];
    }
}

// ---------------- CSR build ----------------
__global__ void k_zero() {
    int i = blockIdx.x * blockDim.x + threadIdx.x;
    if (i < N_FILE) { d_deg[i] = 0; d_cur[i] = 0; }
}

__global__ void k_count(const int* __restrict__ dst, int E) {
    int i = blockIdx.x * blockDim.x + threadIdx.x;
    if (i < E) atomicAdd(&d_deg[dst[i]], 1);
}

__global__ void k_scan() {
    __shared__ int part[512];
    int t = threadIdx.x;
    const int per = (N_FILE + 511) / 512;
    int b = t * per;
    int sum = 0;
    for (int i = 0; i < per; i++) {
        int idx = b + i;
        if (idx < N_FILE) sum += d_deg[idx];
    }
    part[t] = sum;
    __syncthreads();
    for (int o = 1; o < 512; o <<= 1) {
        int v = (t >= o) ? part[t - o] : 0;
        __syncthreads();
        part[t] += v;
        __syncthreads();
    }
    int run = part[t] - sum;
    for (int i = 0; i < per; i++) {
        int idx = b + i;
        if (idx < N_FILE) {
            d_off[idx] = run;
            d_hasedge[idx] = d_deg[idx] ? 1.f : 0.f;
            run += d_deg[idx];
        }
    }
    if (t == 511) d_off[N_FILE] = run;
}

__global__ void k_scatter(const int* __restrict__ src, const int* __restrict__ dst, int E) {
    int i = blockIdx.x * blockDim.x + threadIdx.x;
    if (i >= E) return;
    int d = dst[i];
    int p = atomicAdd(&d_cur[d], 1);
    d_srcs[d_off[d] + p] = src[i];
}

// ---------------- per-dst softmax + embedding aggregation ----------------
__device__ __forceinline__ float lrelu(float v) { return v > 0.f ? v : 0.2f * v; }

__global__ __launch_bounds__(128)
void gat_aggregate(const float* __restrict__ emb)
{
    int d = blockIdx.x;
    int t = threadIdx.x;
    int lane = t & 31, warp = t >> 5;
    int start = d_off[d], end = d_off[d + 1];
    float* aout = d_agg + (size_t)d * KAGG;

    __shared__ float s_er[NH], s_m[NH], s_z[NH];
    __shared__ float red[4][NH];

    if (t < NH) s_er[t] = d_er[d * NH + t];
    __syncthreads();
    float er0 = s_er[0], er1 = s_er[1], er2 = s_er[2];

    float m0 = -CUDART_INF_F, m1 = -CUDART_INF_F, m2 = -CUDART_INF_F;
    for (int e = start + t; e < end; e += 128) {
        int s = d_srcs[e];
        m0 = fmaxf(m0, lrelu(d_el[s * 3 + 0] + er0));
        m1 = fmaxf(m1, lrelu(d_el[s * 3 + 1] + er1));
        m2 = fmaxf(m2, lrelu(d_el[s * 3 + 2] + er2));
    }
#pragma unroll
    for (int o = 16; o > 0; o >>= 1) {
        m0 = fmaxf(m0, __shfl_xor_sync(0xffffffffu, m0, o));
        m1 = fmaxf(m1, __shfl_xor_sync(0xffffffffu, m1, o));
        m2 = fmaxf(m2, __shfl_xor_sync(0xffffffffu, m2, o));
    }
    if (lane == 0) { red[warp][0] = m0; red[warp][1] = m1; red[warp][2] = m2; }
    __syncthreads();
    if (t < NH) s_m[t] = fmaxf(fmaxf(red[0][t], red[1][t]), fmaxf(red[2][t], red[3][t]));
    __syncthreads();
    m0 = s_m[0]; m1 = s_m[1]; m2 = s_m[2];

    float z0 = 0.f, z1 = 0.f, z2 = 0.f;
    for (int e = start + t; e < end; e += 128) {
        int s = d_srcs[e];
        z0 += __expf(lrelu(d_el[s * 3 + 0] + er0) - m0);
        z1 += __expf(lrelu(d_el[s * 3 + 1] + er1) - m1);
        z2 += __expf(lrelu(d_el[s * 3 + 2] + er2) - m2);
    }
#pragma unroll
    for (int o = 16; o > 0; o >>= 1) {
        z0 += __shfl_xor_sync(0xffffffffu, z0, o);
        z1 += __shfl_xor_sync(0xffffffffu, z1, o);
        z2 += __shfl_xor_sync(0xffffffffu, z2, o);
    }
    if (lane == 0) { red[warp][0] = z0; red[warp][1] = z1; red[warp][2] = z2; }
    __syncthreads();
    if (t < NH) s_z[t] = red[0][t] + red[1][t] + red[2][t] + red[3][t];
    __syncthreads();
    float iz0 = (s_z[0] > 0.f) ? 1.f / s_z[0] : 0.f;
    float iz1 = (s_z[1] > 0.f) ? 1.f / s_z[1] : 0.f;
    float iz2 = (s_z[2] > 0.f) ? 1.f / s_z[2] : 0.f;

    float a00 = 0.f, a01 = 0.f, a02 = 0.f, a03 = 0.f;
    float a10 = 0.f, a11 = 0.f, a12 = 0.f, a13 = 0.f;
    float a20 = 0.f, a21 = 0.f, a22 = 0.f, a23 = 0.f;
    int c4 = t * 4;
    for (int e = start; e < end; e++) {
        int s = d_srcs[e];
        float w0 = __expf(lrelu(d_el[s * 3 + 0] + er0) - m0) * iz0;
        float w1 = __expf(lrelu(d_el[s * 3 + 1] + er1) - m1) * iz1;
        float w2 = __expf(lrelu(d_el[s * 3 + 2] + er2) - m2) * iz2;
        float4 x = *(const float4*)(emb + (size_t)s * N_INP + c4);
        a00 = fmaf(w0, x.x, a00); a01 = fmaf(w0, x.y, a01);
        a02 = fmaf(w0, x.z, a02); a03 = fmaf(w0, x.w, a03);
        a10 = fmaf(w1, x.x, a10); a11 = fmaf(w1, x.y, a11);
        a12 = fmaf(w1, x.z, a12); a13 = fmaf(w1, x.w, a13);
        a20 = fmaf(w2, x.x, a20); a21 = fmaf(w2, x.y, a21);
        a22 = fmaf(w2, x.z, a22); a23 = fmaf(w2, x.w, a23);
    }
    *(float4*)(aout + 0 * N_INP + c4) =
        make_float4(to_tf32(a00), to_tf32(a01), to_tf32(a02), to_tf32(a03));
    *(float4*)(aout + 1 * N_INP + c4) =
        make_float4(to_tf32(a10), to_tf32(a11), to_tf32(a12), to_tf32(a13));
    *(float4*)(aout + 2 * N_INP + c4) =
        make_float4(to_tf32(a20), to_tf32(a21), to_tf32(a22), to_tf32(a23));
}

// ---------------- launch ----------------
extern "C" void kernel_launch(void* const* d_in, const int* in_sizes, int n_in,
                              void* d_out, int out_size)
{
    const float* emb_api  = (const float*)d_in[0];
    const float* emb_file = (const float*)d_in[1];
    const int*   src      = (const int*)d_in[3];
    const int*   dst      = (const int*)d_in[4];
    const float* Wapi     = (const float*)d_in[5];
    const float* bapi     = (const float*)d_in[6];
    const float* Wfile    = (const float*)d_in[7];
    const float* bfile    = (const float*)d_in[8];
    const float* Wsrc     = (const float*)d_in[9];
    const float* Wdst     = (const float*)d_in[10];
    const float* attn_l   = (const float*)d_in[11];
    const float* attn_r   = (const float*)d_in[12];
    const float* gat_bias = (const float*)d_in[13];
    const float* Whead    = (const float*)d_in[14];
    const float* bhead    = (const float*)d_in[15];
    float* out = (float*)d_out;

    const int E = in_sizes[3];

    float *p_Wcomb, *p_W2, *p_W2T, *p_Vl, *p_Vr, *p_bl, *p_br, *p_bconst, *p_cbias,
          *p_agg, *p_el, *p_er, *p_hasedge;
    cudaGetSymbolAddress((void**)&p_Wcomb,   d_Wcomb);
    cudaGetSymbolAddress((void**)&p_W2,      d_W2);
    cudaGetSymbolAddress((void**)&p_W2T,     d_W2T);
    cudaGetSymbolAddress((void**)&p_Vl,      d_Vl);
    cudaGetSymbolAddress((void**)&p_Vr,      d_Vr);
    cudaGetSymbolAddress((void**)&p_bl,      d_bl);
    cudaGetSymbolAddress((void**)&p_br,      d_br);
    cudaGetSymbolAddress((void**)&p_bconst,  d_bconst);
    cudaGetSymbolAddress((void**)&p_cbias,   d_cbias);
    cudaGetSymbolAddress((void**)&p_agg,     d_agg);
    cudaGetSymbolAddress((void**)&p_el,      d_el);
    cudaGetSymbolAddress((void**)&p_er,      d_er);
    cudaGetSymbolAddress((void**)&p_hasedge, d_hasedge);

    cudaFuncSetAttribute(gemm_mma, cudaFuncAttributeMaxDynamicSharedMemorySize, GEMM_SMEM_BYTES);

    // CSR build + independent precompute
    k_zero<<<(N_FILE + 255) / 256, 256>>>();
    k_bsrc<<<(HD + 255) / 256, 256>>>(bapi, Wsrc);
    k_u<<<(N_INP * NH + 255) / 256, 256>>>(Wdst, attn_r);
    k_count<<<(E + 255) / 256, 256>>>(dst, E);
    k_scan<<<1, 512>>>();
    k_scatter<<<(E + 255) / 256, 256>>>(src, dst, E);

    // Wcomb = Wapi @ Wsrc   [512,512]@[512,768]
    sgemm<<<dim3(HD / BN, N_INP / BM, 1), 256>>>(
        Wapi, N_INP, Wsrc, HD, p_Wcomb, HD, N_INP, HD, N_INP, 0, 0, 0);

    k_Vl<<<(N_INP * NH + 255) / 256, 256>>>(attn_l);
    k_Vr<<<(N_INP * NH + 255) / 256, 256>>>(Wfile);
    k_biases<<<(2 * NH + 2 * N_OUT + 255) / 256, 256>>>(attn_l, bfile, Whead, gat_bias, bhead);

    // W2stack_h = Wcomb_h @ Whead_h, 3 heads in one batched launch
    sgemm<<<dim3(N_OUT / BN, N_INP / BM, NH), 256>>>(
        p_Wcomb, HD, Whead, N_OUT, p_W2, N_OUT,
        N_INP, N_OUT, N_OUT,
        (long)N_OUT, (long)N_OUT * N_OUT, (long)N_INP * N_OUT);

    // transpose+round W2 -> W2T
    k_w2t<<<(KAGG * N_OUT + 255) / 256, 256>>>();

    // node logits
    node_logits<<<(N_API  + 7) / 8, 256>>>(emb_api,  p_Vl, p_bl, p_el, N_API);
    node_logits<<<(N_FILE + 7) / 8, 256>>>(emb_file, p_Vr, p_br, p_er, N_FILE);

    // per-dst softmax + aggregation of raw embeddings (tf32-rounded out)
    gat_aggregate<<<N_FILE, 128>>>(emb_api);

    // out = agg @ W2T^T + cbias + hasedge*bconst  via mma.sync tf32
    gemm_mma<<<dim3(N_OUT / 128, M_PAD / 128), 256, GEMM_SMEM_BYTES>>>(
        p_agg, p_W2T, out, p_cbias, p_bconst, p_hasedge);
}

// round 5
// speedup vs baseline: 4.0917x; 1.6081x over previous
#include <cuda_runtime.h>
#include <math_constants.h>
#include <cstdint>

// ---------------- problem constants ----------------
#define N_API   50000
#define N_FILE  20000
#define N_INP   512
#define N_OUT   256
#define NH      3
#define HD      768   // NH*N_OUT
#define KAGG    1536  // NH*N_INP
#define M_PAD   20096 // 157*128
#define NCHUNK  48    // KAGG/32

// ---------------- device scratch ----------------
__device__ float d_Wcomb[N_INP * HD];
__device__ float d_W2   [KAGG * N_OUT];           // stacked [1536,256]
__device__ float d_W2T  [N_OUT * KAGG];           // [256,1536] tf32-rounded
__device__ float d_u    [N_INP * NH];
__device__ float d_Vl   [N_INP * NH];
__device__ float d_Vr   [N_INP * NH];
__device__ float d_bsrc [HD];
__device__ float d_bl   [NH];
__device__ float d_br   [NH];
__device__ float d_bconst[N_OUT];
__device__ float d_cbias [N_OUT];
__device__ float d_agg  [(size_t)M_PAD * KAGG];   // padded; tail rows stay 0
__device__ float d_el   [N_API * 4];              // stride-4 (pad) for LDG.128
__device__ float d_er   [N_FILE * 4];
__device__ int   d_deg  [N_FILE];
__device__ int   d_cur  [N_FILE];
__device__ int   d_off  [N_FILE + 1];
__device__ float d_hasedge[N_FILE];
__device__ int   d_srcs [262144];

// ---------------- helpers ----------------
__device__ __forceinline__ uint32_t smem_u32(const void* p) {
    uint32_t a;
    asm("{ .reg .u64 t; cvta.to.shared.u64 t, %1; cvt.u32.u64 %0, t; }" : "=r"(a) : "l"(p));
    return a;
}
__device__ __forceinline__ float to_tf32(float x) {
    uint32_t u = __float_as_uint(x), r;
    asm("cvt.rna.tf32.f32 %0, %1;" : "=r"(r) : "r"(u));
    return __uint_as_float(r);
}
__device__ __forceinline__ float lrelu(float v) { return v > 0.f ? v : 0.2f * v; }

#define CP_ASYNC16(dst, src) \
    asm volatile("cp.async.cg.shared.global [%0], [%1], 16;" :: "r"(dst), "l"(src) : "memory")
#define CP_COMMIT()  asm volatile("cp.async.commit_group;" ::: "memory")
#define CP_WAIT0()   asm volatile("cp.async.wait_group 0;" ::: "memory")
#define CP_WAIT1()   asm volatile("cp.async.wait_group 1;" ::: "memory")

__device__ __forceinline__ void mma_tf32(float* c, const uint32_t* a, const uint32_t* b) {
    asm volatile(
        "mma.sync.aligned.m16n8k8.row.col.f32.tf32.tf32.f32 "
        "{%0,%1,%2,%3}, {%4,%5,%6,%7}, {%8,%9}, {%0,%1,%2,%3};"
        : "+f"(c[0]), "+f"(c[1]), "+f"(c[2]), "+f"(c[3])
        : "r"(a[0]), "r"(a[1]), "r"(a[2]), "r"(a[3]), "r"(b[0]), "r"(b[1]));
}

// ---------------- tensor-core tf32 GEMM (unchanged, proven) ----------------
#define LDP   36
#define TILE_F (128 * LDP)
#define GEMM_SMEM_BYTES (4 * TILE_F * 4)

__global__ void __launch_bounds__(256)
gemm_mma(const float* __restrict__ A, const float* __restrict__ B,
         float* __restrict__ C,
         const float* __restrict__ cbias,
         const float* __restrict__ bconst,
         const float* __restrict__ hasedge)
{
    extern __shared__ float sm[];
    float* As = sm;
    float* Bs = sm + 2 * TILE_F;

    const int tid  = threadIdx.x;
    const int wid  = tid >> 5, lane = tid & 31;
    const int wm   = wid & 1;
    const int wn   = wid >> 1;
    const int m0   = blockIdx.y * 128;
    const int n0   = blockIdx.x * 128;

    const int ldRow = tid >> 3;
    const int ldK4  = (tid & 7) * 4;

    float acc[4][4][4];
#pragma unroll
    for (int a = 0; a < 4; a++)
#pragma unroll
        for (int b = 0; b < 4; b++)
#pragma unroll
            for (int c = 0; c < 4; c++) acc[a][b][c] = 0.f;

#define LOAD_TILE(kt, s) do {                                                   \
    int _k0 = (kt) * 32;                                                        \
    _Pragma("unroll")                                                           \
    for (int _t = 0; _t < 4; _t++) {                                            \
        int _row = ldRow + _t * 32;                                             \
        const float* _g = A + (size_t)(m0 + _row) * KAGG + _k0 + ldK4;          \
        CP_ASYNC16(smem_u32(As + (s) * TILE_F + _row * LDP + ldK4), _g);        \
    }                                                                           \
    _Pragma("unroll")                                                           \
    for (int _t = 0; _t < 4; _t++) {                                            \
        int _row = ldRow + _t * 32;                                             \
        const float* _g = B + (size_t)(n0 + _row) * KAGG + _k0 + ldK4;          \
        CP_ASYNC16(smem_u32(Bs + (s) * TILE_F + _row * LDP + ldK4), _g);        \
    }                                                                           \
    CP_COMMIT();                                                                \
} while (0)

    LOAD_TILE(0, 0);

    for (int kt = 0; kt < NCHUNK; kt++) {
        int s = kt & 1;
        if (kt + 1 < NCHUNK) { LOAD_TILE(kt + 1, s ^ 1); CP_WAIT1(); }
        else                 { CP_WAIT0(); }
        __syncthreads();

        const float* a_base = As + s * TILE_F + (wm * 64 + (lane >> 2)) * LDP;
        const float* b_base = Bs + s * TILE_F + (wn * 32 + (lane >> 2)) * LDP;

#pragma unroll
        for (int ks = 0; ks < 4; ks++) {
            int kk = ks * 8 + (lane & 3);
            uint32_t afr[4][4];
#pragma unroll
            for (int mi = 0; mi < 4; mi++) {
                const float* ap = a_base + mi * 16 * LDP;
                afr[mi][0] = __float_as_uint(ap[kk]);
                afr[mi][1] = __float_as_uint(ap[8 * LDP + kk]);
                afr[mi][2] = __float_as_uint(ap[kk + 4]);
                afr[mi][3] = __float_as_uint(ap[8 * LDP + kk + 4]);
            }
            uint32_t bfr[4][2];
#pragma unroll
            for (int ni = 0; ni < 4; ni++) {
                const float* bp = b_base + ni * 8 * LDP;
                bfr[ni][0] = __float_as_uint(bp[kk]);
                bfr[ni][1] = __float_as_uint(bp[kk + 4]);
            }
#pragma unroll
            for (int mi = 0; mi < 4; mi++)
#pragma unroll
                for (int ni = 0; ni < 4; ni++)
                    mma_tf32(acc[mi][ni], afr[mi], bfr[ni]);
        }
        __syncthreads();
    }

#pragma unroll
    for (int mi = 0; mi < 4; mi++) {
        int rbase = m0 + wm * 64 + mi * 16 + (lane >> 2);
#pragma unroll
        for (int half = 0; half < 2; half++) {
            int r = rbase + half * 8;
            if (r >= N_FILE) continue;
            float he = hasedge[r];
#pragma unroll
            for (int ni = 0; ni < 4; ni++) {
                int c0 = n0 + wn * 32 + ni * 8 + (lane & 3) * 2;
                float v0 = acc[mi][ni][half * 2 + 0] + cbias[c0]     + he * bconst[c0];
                float v1 = acc[mi][ni][half * 2 + 1] + cbias[c0 + 1] + he * bconst[c0 + 1];
                *(float2*)(C + (size_t)r * N_OUT + c0) = make_float2(v0, v1);
            }
        }
    }
}

// ---------------- fp32 SGEMM (precompute-sized, batched z) ----
#define BM 128
#define BN 128
#define BK 8
#define TM 8
#define TN 8

__global__ __launch_bounds__(256, 2)
void sgemm(const float* __restrict__ A, int lda,
           const float* __restrict__ B, int ldb,
           float* __restrict__ C, int ldc,
           int M, int N, int K,
           long sA, long sB, long sC)
{
    A += (long)blockIdx.z * sA;
    B += (long)blockIdx.z * sB;
    C += (long)blockIdx.z * sC;

    __shared__ float As[BK][BM];
    __shared__ float Bs[BK][BN];
    const int tid = threadIdx.x;
    const int bm  = blockIdx.y * BM;
    const int bn  = blockIdx.x * BN;

    const int aRow  = tid >> 1;
    const int aCol4 = (tid & 1) * 4;
    const int bRow  = tid >> 5;
    const int bCol4 = (tid & 31) * 4;
    const int ty = tid >> 4, tx = tid & 15;

    float acc[TM][TN];
#pragma unroll
    for (int i = 0; i < TM; i++)
#pragma unroll
        for (int j = 0; j < TN; j++) acc[i][j] = 0.f;

    for (int k0 = 0; k0 < K; k0 += BK) {
        float4 av;
        if (bm + aRow < M)
            av = *(const float4*)(A + (size_t)(bm + aRow) * lda + k0 + aCol4);
        else
            av = make_float4(0.f, 0.f, 0.f, 0.f);
        As[aCol4 + 0][aRow] = av.x;
        As[aCol4 + 1][aRow] = av.y;
        As[aCol4 + 2][aRow] = av.z;
        As[aCol4 + 3][aRow] = av.w;

        float4 bv = *(const float4*)(B + (size_t)(k0 + bRow) * ldb + bn + bCol4);
        *(float4*)(&Bs[bRow][bCol4]) = bv;

        __syncthreads();
#pragma unroll
        for (int k = 0; k < BK; k++) {
            float ra[TM], rb[TN];
#pragma unroll
            for (int i = 0; i < TM; i++) ra[i] = As[k][ty * TM + i];
#pragma unroll
            for (int j = 0; j < TN; j++) rb[j] = Bs[k][tx * TN + j];
#pragma unroll
            for (int i = 0; i < TM; i++)
#pragma unroll
                for (int j = 0; j < TN; j++)
                    acc[i][j] = fmaf(ra[i], rb[j], acc[i][j]);
        }
        __syncthreads();
    }

#pragma unroll
    for (int i = 0; i < TM; i++) {
        int row = bm + ty * TM + i;
        if (row >= M) break;
#pragma unroll
        for (int j = 0; j < TN; j += 4) {
            int col = bn + tx * TN + j;
            float4 v;
            v.x = acc[i][j];     v.y = acc[i][j + 1];
            v.z = acc[i][j + 2]; v.w = acc[i][j + 3];
            *(float4*)(C + (size_t)row * ldc + col) = v;
        }
    }
}

// ---------------- coalesced GEVM: y[c] = sum_k x[k]*W[k,c] (+add) ----------
// block = 64 cols x 4 k-slices (256 thr); grid.x = N/64
__global__ __launch_bounds__(256)
void gevm(const float* __restrict__ x, const float* __restrict__ W,
          float* __restrict__ y, int K, int N, const float* __restrict__ add)
{
    int c  = blockIdx.x * 64 + (threadIdx.x & 63);
    int ks = threadIdx.x >> 6;
    int kper = K >> 2;
    int k0 = ks * kper, k1 = k0 + kper;
    float s = 0.f;
    for (int k = k0; k < k1; k++) s = fmaf(x[k], W[(size_t)k * N + c], s);
    __shared__ float sm[4][64];
    sm[ks][threadIdx.x & 63] = s;
    __syncthreads();
    if (ks == 0) {
        int l = threadIdx.x & 63;
        float v = sm[0][l] + sm[1][l] + sm[2][l] + sm[3][l];
        if (add) v += add[c];
        y[c] = v;
    }
}

// ---------------- warp-per-output dot kernels (1536 warps each) ----------
__device__ __forceinline__ float warp_sum(float s) {
#pragma unroll
    for (int o = 16; o > 0; o >>= 1) s += __shfl_down_sync(0xffffffffu, s, o);
    return s;
}

__global__ __launch_bounds__(256)
void k_u(const float* __restrict__ Wdst, const float* __restrict__ attn_r) {
    int wg = blockIdx.x * 8 + (threadIdx.x >> 5);
    int lane = threadIdx.x & 31;
    int k = wg / 3, h = wg - k * 3;
    const float* row = Wdst + (size_t)k * HD + h * N_OUT;
    const float* v   = attn_r + h * N_OUT;
    float s = 0.f;
#pragma unroll
    for (int j = lane; j < N_OUT; j += 32) s = fmaf(row[j], v[j], s);
    s = warp_sum(s);
    if (lane == 0) d_u[k * 3 + h] = s;
}

__global__ __launch_bounds__(256)
void k_Vl(const float* __restrict__ attn_l) {
    int wg = blockIdx.x * 8 + (threadIdx.x >> 5);
    int lane = threadIdx.x & 31;
    int k = wg / 3, h = wg - k * 3;
    const float* row = d_Wcomb + (size_t)k * HD + h * N_OUT;
    const float* v   = attn_l + h * N_OUT;
    float s = 0.f;
#pragma unroll
    for (int j = lane; j < N_OUT; j += 32) s = fmaf(row[j], v[j], s);
    s = warp_sum(s);
    if (lane == 0) d_Vl[k * 3 + h] = s;
}

__global__ __launch_bounds__(256)
void k_Vr(const float* __restrict__ Wfile) {
    int wg = blockIdx.x * 8 + (threadIdx.x >> 5);
    int lane = threadIdx.x & 31;
    int k = wg / 3, h = wg - k * 3;
    const float* row = Wfile + (size_t)k * N_INP;
    float s = 0.f;
#pragma unroll
    for (int c = lane; c < N_INP; c += 32) s = fmaf(row[c], d_u[c * 3 + h], s);
    s = warp_sum(s);
    if (lane == 0) d_Vr[k * 3 + h] = s;
}

// bl[h] = sum_j bsrc[h*256+j]*attn_l[h*256+j]   (3 warps)
__global__ void k_bl(const float* __restrict__ attn_l) {
    int w = threadIdx.x >> 5, lane = threadIdx.x & 31;
    if (w >= NH) return;
    float s = 0.f;
    for (int j = lane; j < N_OUT; j += 32)
        s = fmaf(d_bsrc[w * N_OUT + j], attn_l[w * N_OUT + j], s);
    s = warp_sum(s);
    if (lane == 0) d_bl[w] = s;
}

// br[h] = sum_c bfile[c]*u[c,h]   (3 warps)
__global__ void k_br(const float* __restrict__ bfile) {
    int w = threadIdx.x >> 5, lane = threadIdx.x & 31;
    if (w >= NH) return;
    float s = 0.f;
    for (int c = lane; c < N_INP; c += 32)
        s = fmaf(bfile[c], d_u[c * 3 + w], s);
    s = warp_sum(s);
    if (lane == 0) d_br[w] = s;
}

// ---------------- coalesced transpose + tf32 round: W2T[n,k]=tf32(W2[k,n]) ----
__global__ void k_w2t() {
    __shared__ float tile[32][33];
    int nb = blockIdx.x * 32, kb = blockIdx.y * 32;
    int tx = threadIdx.x, ty = threadIdx.y;   // 32 x 8
#pragma unroll
    for (int j = 0; j < 32; j += 8)
        tile[ty + j][tx] = d_W2[(size_t)(kb + ty + j) * N_OUT + nb + tx];
    __syncthreads();
#pragma unroll
    for (int j = 0; j < 32; j += 8)
        d_W2T[(size_t)(nb + ty + j) * KAGG + kb + tx] = to_tf32(tile[tx][ty + j]);
}

// ---------------- node logits: out4[n] = (X[n]@V + b3, 0) ----------------
__global__ void node_logits(const float* __restrict__ X,
                            const float* __restrict__ V,
                            const float* __restrict__ b3,
                            float* __restrict__ out, int Nn)
{
    __shared__ float sV[N_INP * NH];
    int t = threadIdx.x;
    for (int i = t; i < N_INP * NH; i += blockDim.x) sV[i] = V[i];
    __syncthreads();
    int warp = t >> 5, lane = t & 31;
    int n = blockIdx.x * (blockDim.x >> 5) + warp;
    if (n >= Nn) return;
    const float* x = X + (size_t)n * N_INP;
    float s0 = 0.f, s1 = 0.f, s2 = 0.f;
    for (int k = lane; k < N_INP; k += 32) {
        float xv = x[k];
        s0 = fmaf(xv, sV[k * 3 + 0], s0);
        s1 = fmaf(xv, sV[k * 3 + 1], s1);
        s2 = fmaf(xv, sV[k * 3 + 2], s2);
    }
#pragma unroll
    for (int o = 16; o > 0; o >>= 1) {
        s0 += __shfl_down_sync(0xffffffffu, s0, o);
        s1 += __shfl_down_sync(0xffffffffu, s1, o);
        s2 += __shfl_down_sync(0xffffffffu, s2, o);
    }
    if (lane == 0)
        *(float4*)(out + (size_t)n * 4) = make_float4(s0 + b3[0], s1 + b3[1], s2 + b3[2], 0.f);
}

// ---------------- CSR build ----------------
__global__ void k_zero() {
    int i = blockIdx.x * blockDim.x + threadIdx.x;
    if (i < N_FILE) { d_deg[i] = 0; d_cur[i] = 0; }
}

__global__ void k_count(const int* __restrict__ dst, int E) {
    int i = blockIdx.x * blockDim.x + threadIdx.x;
    if (i < E) atomicAdd(&d_deg[dst[i]], 1);
}

__global__ void k_scan() {
    __shared__ int part[512];
    int t = threadIdx.x;
    const int per = (N_FILE + 511) / 512;
    int b = t * per;
    int sum = 0;
    for (int i = 0; i < per; i++) {
        int idx = b + i;
        if (idx < N_FILE) sum += d_deg[idx];
    }
    part[t] = sum;
    __syncthreads();
    for (int o = 1; o < 512; o <<= 1) {
        int v = (t >= o) ? part[t - o] : 0;
        __syncthreads();
        part[t] += v;
        __syncthreads();
    }
    int run = part[t] - sum;
    for (int i = 0; i < per; i++) {
        int idx = b + i;
        if (idx < N_FILE) {
            d_off[idx] = run;
            d_hasedge[idx] = d_deg[idx] ? 1.f : 0.f;
            run += d_deg[idx];
        }
    }
    if (t == 511) d_off[N_FILE] = run;
}

__global__ void k_scatter(const int* __restrict__ src, const int* __restrict__ dst, int E) {
    int i = blockIdx.x * blockDim.x + threadIdx.x;
    if (i >= E) return;
    int d = dst[i];
    int p = atomicAdd(&d_cur[d], 1);
    d_srcs[d_off[d] + p] = src[i];
}

// ---------------- per-dst softmax + embedding aggregation ----------------
#define GCAP 1024

__global__ __launch_bounds__(128)
void gat_aggregate(const float* __restrict__ emb)
{
    int d = blockIdx.x;
    int t = threadIdx.x;
    int lane = t & 31, warp = t >> 5;
    int start = d_off[d], end = d_off[d + 1];
    int deg = end - start;
    bool cached = (deg <= GCAP);

    __shared__ int   sh_src[GCAP];
    __shared__ float sh_w[GCAP * 3];
    __shared__ float s_er[4], s_m[3], s_iz[3];
    __shared__ float red[4][3];

    if (t < 4) s_er[t] = d_er[(size_t)d * 4 + t];
    __syncthreads();
    float er0 = s_er[0], er1 = s_er[1], er2 = s_er[2];
    const float4* el4 = (const float4*)d_el;

    // pass 1: logits (+ cache) + max
    float m0 = -CUDART_INF_F, m1 = -CUDART_INF_F, m2 = -CUDART_INF_F;
    for (int e = start + t; e < end; e += 128) {
        int s = d_srcs[e];
        float4 L = el4[s];
        float l0 = lrelu(L.x + er0), l1 = lrelu(L.y + er1), l2 = lrelu(L.z + er2);
        if (cached) {
            int i = e - start;
            sh_src[i] = s;
            sh_w[i * 3 + 0] = l0; sh_w[i * 3 + 1] = l1; sh_w[i * 3 + 2] = l2;
        }
        m0 = fmaxf(m0, l0); m1 = fmaxf(m1, l1); m2 = fmaxf(m2, l2);
    }
#pragma unroll
    for (int o = 16; o > 0; o >>= 1) {
        m0 = fmaxf(m0, __shfl_xor_sync(0xffffffffu, m0, o));
        m1 = fmaxf(m1, __shfl_xor_sync(0xffffffffu, m1, o));
        m2 = fmaxf(m2, __shfl_xor_sync(0xffffffffu, m2, o));
    }
    if (lane == 0) { red[warp][0] = m0; red[warp][1] = m1; red[warp][2] = m2; }
    __syncthreads();
    if (t < 3) s_m[t] = fmaxf(fmaxf(red[0][t], red[1][t]), fmaxf(red[2][t], red[3][t]));
    __syncthreads();
    m0 = s_m[0]; m1 = s_m[1]; m2 = s_m[2];

    // pass 2: sum of exp
    float z0 = 0.f, z1 = 0.f, z2 = 0.f;
    for (int e = start + t; e < end; e += 128) {
        float l0, l1, l2;
        if (cached) {
            int i = e - start;
            l0 = sh_w[i * 3 + 0]; l1 = sh_w[i * 3 + 1]; l2 = sh_w[i * 3 + 2];
        } else {
            int s = d_srcs[e];
            float4 L = el4[s];
            l0 = lrelu(L.x + er0); l1 = lrelu(L.y + er1); l2 = lrelu(L.z + er2);
        }
        z0 += __expf(l0 - m0); z1 += __expf(l1 - m1); z2 += __expf(l2 - m2);
    }
#pragma unroll
    for (int o = 16; o > 0; o >>= 1) {
        z0 += __shfl_xor_sync(0xffffffffu, z0, o);
        z1 += __shfl_xor_sync(0xffffffffu, z1, o);
        z2 += __shfl_xor_sync(0xffffffffu, z2, o);
    }
    if (lane == 0) { red[warp][0] = z0; red[warp][1] = z1; red[warp][2] = z2; }
    __syncthreads();
    if (t < 3) {
        float z = red[0][t] + red[1][t] + red[2][t] + red[3][t];
        s_iz[t] = (z > 0.f) ? 1.f / z : 0.f;
    }
    __syncthreads();
    float iz0 = s_iz[0], iz1 = s_iz[1], iz2 = s_iz[2];

    // convert cached logits -> softmax weights (one exp per edge per head)
    if (cached) {
        for (int i = t; i < deg; i += 128) {
            sh_w[i * 3 + 0] = __expf(sh_w[i * 3 + 0] - m0) * iz0;
            sh_w[i * 3 + 1] = __expf(sh_w[i * 3 + 1] - m1) * iz1;
            sh_w[i * 3 + 2] = __expf(sh_w[i * 3 + 2] - m2) * iz2;
        }
    }
    __syncthreads();

    // pass 3: weighted aggregation; thread t owns columns [4t, 4t+4)
    float a00 = 0.f, a01 = 0.f, a02 = 0.f, a03 = 0.f;
    float a10 = 0.f, a11 = 0.f, a12 = 0.f, a13 = 0.f;
    float a20 = 0.f, a21 = 0.f, a22 = 0.f, a23 = 0.f;
    int c4 = t * 4;
    for (int e = start; e < end; e++) {
        int s; float w0, w1, w2;
        if (cached) {
            int i = e - start;
            s  = sh_src[i];
            w0 = sh_w[i * 3 + 0]; w1 = sh_w[i * 3 + 1]; w2 = sh_w[i * 3 + 2];
        } else {
            s = d_srcs[e];
            float4 L = el4[s];
            w0 = __expf(lrelu(L.x + er0) - m0) * iz0;
            w1 = __expf(lrelu(L.y + er1) - m1) * iz1;
            w2 = __expf(lrelu(L.z + er2) - m2) * iz2;
        }
        float4 x = *(const float4*)(emb + (size_t)s * N_INP + c4);
        a00 = fmaf(w0, x.x, a00); a01 = fmaf(w0, x.y, a01);
        a02 = fmaf(w0, x.z, a02); a03 = fmaf(w0, x.w, a03);
        a10 = fmaf(w1, x.x, a10); a11 = fmaf(w1, x.y, a11);
        a12 = fmaf(w1, x.z, a12); a13 = fmaf(w1, x.w, a13);
        a20 = fmaf(w2, x.x, a20); a21 = fmaf(w2, x.y, a21);
        a22 = fmaf(w2, x.z, a22); a23 = fmaf(w2, x.w, a23);
    }
    float* aout = d_agg + (size_t)d * KAGG;
    *(float4*)(aout + 0 * N_INP + c4) =
        make_float4(to_tf32(a00), to_tf32(a01), to_tf32(a02), to_tf32(a03));
    *(float4*)(aout + 1 * N_INP + c4) =
        make_float4(to_tf32(a10), to_tf32(a11), to_tf32(a12), to_tf32(a13));
    *(float4*)(aout + 2 * N_INP + c4) =
        make_float4(to_tf32(a20), to_tf32(a21), to_tf32(a22), to_tf32(a23));
}

// ---------------- launch ----------------
extern "C" void kernel_launch(void* const* d_in, const int* in_sizes, int n_in,
                              void* d_out, int out_size)
{
    const float* emb_api  = (const float*)d_in[0];
    const float* emb_file = (const float*)d_in[1];
    const int*   src      = (const int*)d_in[3];
    const int*   dst      = (const int*)d_in[4];
    const float* Wapi     = (const float*)d_in[5];
    const float* bapi     = (const float*)d_in[6];
    const float* Wfile    = (const float*)d_in[7];
    const float* bfile    = (const float*)d_in[8];
    const float* Wsrc     = (const float*)d_in[9];
    const float* Wdst     = (const float*)d_in[10];
    const float* attn_l   = (const float*)d_in[11];
    const float* attn_r   = (const float*)d_in[12];
    const float* gat_bias = (const float*)d_in[13];
    const float* Whead    = (const float*)d_in[14];
    const float* bhead    = (const float*)d_in[15];
    float* out = (float*)d_out;

    const int E = in_sizes[3];

    float *p_Wcomb, *p_W2, *p_W2T, *p_Vl, *p_Vr, *p_bl, *p_br, *p_bconst, *p_cbias,
          *p_agg, *p_el, *p_er, *p_hasedge, *p_bsrc;
    cudaGetSymbolAddress((void**)&p_Wcomb,   d_Wcomb);
    cudaGetSymbolAddress((void**)&p_W2,      d_W2);
    cudaGetSymbolAddress((void**)&p_W2T,     d_W2T);
    cudaGetSymbolAddress((void**)&p_Vl,      d_Vl);
    cudaGetSymbolAddress((void**)&p_Vr,      d_Vr);
    cudaGetSymbolAddress((void**)&p_bl,      d_bl);
    cudaGetSymbolAddress((void**)&p_br,      d_br);
    cudaGetSymbolAddress((void**)&p_bconst,  d_bconst);
    cudaGetSymbolAddress((void**)&p_cbias,   d_cbias);
    cudaGetSymbolAddress((void**)&p_agg,     d_agg);
    cudaGetSymbolAddress((void**)&p_el,      d_el);
    cudaGetSymbolAddress((void**)&p_er,      d_er);
    cudaGetSymbolAddress((void**)&p_hasedge, d_hasedge);
    cudaGetSymbolAddress((void**)&p_bsrc,    d_bsrc);

    cudaFuncSetAttribute(gemm_mma, cudaFuncAttributeMaxDynamicSharedMemorySize, GEMM_SMEM_BYTES);

    // streams/events for graph-capture fork-join (created once, host-side only)
    static cudaStream_t s1 = nullptr, s2 = nullptr;
    static cudaEvent_t ev0, ev_bsrc, ev_csr, ev_s2;
    if (!s1) {
        cudaStreamCreateWithFlags(&s1, cudaStreamNonBlocking);
        cudaStreamCreateWithFlags(&s2, cudaStreamNonBlocking);
        cudaEventCreateWithFlags(&ev0,     cudaEventDisableTiming);
        cudaEventCreateWithFlags(&ev_bsrc, cudaEventDisableTiming);
        cudaEventCreateWithFlags(&ev_csr,  cudaEventDisableTiming);
        cudaEventCreateWithFlags(&ev_s2,   cudaEventDisableTiming);
    }

    // fork
    cudaEventRecord(ev0, 0);
    cudaStreamWaitEvent(s1, ev0, 0);
    cudaStreamWaitEvent(s2, ev0, 0);

    // ---- s1: CSR build ----
    k_zero   <<<(N_FILE + 255) / 256, 256, 0, s1>>>();
    k_count  <<<(E + 255) / 256, 256, 0, s1>>>(dst, E);
    k_scan   <<<1, 512, 0, s1>>>();
    k_scatter<<<(E + 255) / 256, 256, 0, s1>>>(src, dst, E);
    cudaEventRecord(ev_csr, s1);

    // ---- default: api-side critical path ----
    gevm<<<HD / 64, 256>>>(bapi, Wsrc, p_bsrc, N_INP, HD, nullptr);
    cudaEventRecord(ev_bsrc, 0);
    sgemm<<<dim3(HD / BN, N_INP / BM, 1), 256>>>(
        Wapi, N_INP, Wsrc, HD, p_Wcomb, HD, N_INP, HD, N_INP, 0, 0, 0);
    sgemm<<<dim3(N_OUT / BN, N_INP / BM, NH), 256>>>(
        p_Wcomb, HD, Whead, N_OUT, p_W2, N_OUT,
        N_INP, N_OUT, N_OUT,
        (long)N_OUT, (long)N_OUT * N_OUT, (long)N_INP * N_OUT);
    k_w2t<<<dim3(N_OUT / 32, KAGG / 32), dim3(32, 8)>>>();
    k_Vl<<<192, 256>>>(attn_l);
    k_bl<<<1, 128>>>(attn_l);
    node_logits<<<(N_API + 7) / 8, 256>>>(emb_api, p_Vl, p_bl, p_el, N_API);

    // ---- s2: file-side precompute ----
    k_u<<<192, 256, 0, s2>>>(Wdst, attn_r);
    k_Vr<<<192, 256, 0, s2>>>(Wfile);
    k_br<<<1, 128, 0, s2>>>(bfile);
    gevm<<<N_OUT / 64, 256, 0, s2>>>(gat_bias, Whead, p_cbias, HD, N_OUT, bhead);
    cudaStreamWaitEvent(s2, ev_bsrc, 0);
    gevm<<<N_OUT / 64, 256, 0, s2>>>(p_bsrc, Whead, p_bconst, HD, N_OUT, nullptr);
    node_logits<<<(N_FILE + 7) / 8, 256, 0, s2>>>(emb_file, p_Vr, p_br, p_er, N_FILE);
    cudaEventRecord(ev_s2, s2);

    // join on default
    cudaStreamWaitEvent(0, ev_csr, 0);
    cudaStreamWaitEvent(0, ev_s2, 0);

    // per-dst softmax + aggregation, then tensor-core GEMM
    gat_aggregate<<<N_FILE, 128>>>(emb_api);
    gemm_mma<<<dim3(N_OUT / 128, M_PAD / 128), 256, GEMM_SMEM_BYTES>>>(
        p_agg, p_W2T, out, p_cbias, p_bconst, p_hasedge);
}

// round 6
// speedup vs baseline: 4.1289x; 1.0091x over previous
#include <cuda_runtime.h>
#include <math_constants.h>
#include <cstdint>

// ---------------- problem constants ----------------
#define N_API   50000
#define N_FILE  20000
#define N_INP   512
#define N_OUT   256
#define NH      3
#define HD      768   // NH*N_OUT
#define KAGG    1536  // NH*N_INP
#define M_PAD   20096 // 157*128
#define NCHUNK  48    // KAGG/32

// pipeline chunking: 157 row-blocks = 80 + 77
#define CH0_BLOCKS 80
#define CH1_BLOCKS 77
#define CH0_DST    (CH0_BLOCKS * 128)          // 10240
#define CH1_DST    (N_FILE - CH0_DST)          // 9760

// ---------------- device scratch ----------------
__device__ float d_Wcomb[N_INP * HD];
__device__ float d_W2   [KAGG * N_OUT];
__device__ float d_W2T  [N_OUT * KAGG];
__device__ float d_u    [N_INP * NH];
__device__ float d_Vl   [N_INP * NH];
__device__ float d_Vr   [N_INP * NH];
__device__ float d_bsrc [HD];
__device__ float d_bl   [NH];
__device__ float d_br   [NH];
__device__ float d_bconst[N_OUT];
__device__ float d_cbias [N_OUT];
__device__ float d_agg  [(size_t)M_PAD * KAGG];   // tail rows (>=N_FILE) stay 0
__device__ float d_el   [N_API * 4];              // stride-4 for LDG.128
__device__ float d_er   [N_FILE * 4];
__device__ int   d_deg  [N_FILE];
__device__ int   d_cur  [N_FILE];
__device__ int   d_off  [N_FILE + 1];
__device__ float d_hasedge[N_FILE];
__device__ int   d_srcs [262144];

// ---------------- helpers ----------------
__device__ __forceinline__ uint32_t smem_u32(const void* p) {
    uint32_t a;
    asm("{ .reg .u64 t; cvta.to.shared.u64 t, %1; cvt.u32.u64 %0, t; }" : "=r"(a) : "l"(p));
    return a;
}
__device__ __forceinline__ float to_tf32(float x) {
    uint32_t u = __float_as_uint(x), r;
    asm("cvt.rna.tf32.f32 %0, %1;" : "=r"(r) : "r"(u));
    return __uint_as_float(r);
}
__device__ __forceinline__ float lrelu(float v) { return v > 0.f ? v : 0.2f * v; }

#define CP_ASYNC16(dst, src) \
    asm volatile("cp.async.cg.shared.global [%0], [%1], 16;" :: "r"(dst), "l"(src) : "memory")
#define CP_COMMIT()  asm volatile("cp.async.commit_group;" ::: "memory")
#define CP_WAIT0()   asm volatile("cp.async.wait_group 0;" ::: "memory")
#define CP_WAIT1()   asm volatile("cp.async.wait_group 1;" ::: "memory")

__device__ __forceinline__ void mma_tf32(float* c, const uint32_t* a, const uint32_t* b) {
    asm volatile(
        "mma.sync.aligned.m16n8k8.row.col.f32.tf32.tf32.f32 "
        "{%0,%1,%2,%3}, {%4,%5,%6,%7}, {%8,%9}, {%0,%1,%2,%3};"
        : "+f"(c[0]), "+f"(c[1]), "+f"(c[2]), "+f"(c[3])
        : "r"(a[0]), "r"(a[1]), "r"(a[2]), "r"(a[3]), "r"(b[0]), "r"(b[1]));
}

// ---------------- tensor-core tf32 GEMM (row-block-offset variant) ----------------
#define LDP   36
#define TILE_F (128 * LDP)
#define GEMM_SMEM_BYTES (4 * TILE_F * 4)

__global__ void __launch_bounds__(256)
gemm_mma(const float* __restrict__ A, const float* __restrict__ B,
         float* __restrict__ C,
         const float* __restrict__ cbias,
         const float* __restrict__ bconst,
         const float* __restrict__ hasedge,
         int mb_base)
{
    extern __shared__ float sm[];
    float* As = sm;
    float* Bs = sm + 2 * TILE_F;

    const int tid  = threadIdx.x;
    const int wid  = tid >> 5, lane = tid & 31;
    const int wm   = wid & 1;
    const int wn   = wid >> 1;
    const int m0   = (mb_base + blockIdx.y) * 128;
    const int n0   = blockIdx.x * 128;

    const int ldRow = tid >> 3;
    const int ldK4  = (tid & 7) * 4;

    float acc[4][4][4];
#pragma unroll
    for (int a = 0; a < 4; a++)
#pragma unroll
        for (int b = 0; b < 4; b++)
#pragma unroll
            for (int c = 0; c < 4; c++) acc[a][b][c] = 0.f;

#define LOAD_TILE(kt, s) do {                                                   \
    int _k0 = (kt) * 32;                                                        \
    _Pragma("unroll")                                                           \
    for (int _t = 0; _t < 4; _t++) {                                            \
        int _row = ldRow + _t * 32;                                             \
        const float* _g = A + (size_t)(m0 + _row) * KAGG + _k0 + ldK4;          \
        CP_ASYNC16(smem_u32(As + (s) * TILE_F + _row * LDP + ldK4), _g);        \
    }                                                                           \
    _Pragma("unroll")                                                           \
    for (int _t = 0; _t < 4; _t++) {                                            \
        int _row = ldRow + _t * 32;                                             \
        const float* _g = B + (size_t)(n0 + _row) * KAGG + _k0 + ldK4;          \
        CP_ASYNC16(smem_u32(Bs + (s) * TILE_F + _row * LDP + ldK4), _g);        \
    }                                                                           \
    CP_COMMIT();                                                                \
} while (0)

    LOAD_TILE(0, 0);

    for (int kt = 0; kt < NCHUNK; kt++) {
        int s = kt & 1;
        if (kt + 1 < NCHUNK) { LOAD_TILE(kt + 1, s ^ 1); CP_WAIT1(); }
        else                 { CP_WAIT0(); }
        __syncthreads();

        const float* a_base = As + s * TILE_F + (wm * 64 + (lane >> 2)) * LDP;
        const float* b_base = Bs + s * TILE_F + (wn * 32 + (lane >> 2)) * LDP;

#pragma unroll
        for (int ks = 0; ks < 4; ks++) {
            int kk = ks * 8 + (lane & 3);
            uint32_t afr[4][4];
#pragma unroll
            for (int mi = 0; mi < 4; mi++) {
                const float* ap = a_base + mi * 16 * LDP;
                afr[mi][0] = __float_as_uint(ap[kk]);
                afr[mi][1] = __float_as_uint(ap[8 * LDP + kk]);
                afr[mi][2] = __float_as_uint(ap[kk + 4]);
                afr[mi][3] = __float_as_uint(ap[8 * LDP + kk + 4]);
            }
            uint32_t bfr[4][2];
#pragma unroll
            for (int ni = 0; ni < 4; ni++) {
                const float* bp = b_base + ni * 8 * LDP;
                bfr[ni][0] = __float_as_uint(bp[kk]);
                bfr[ni][1] = __float_as_uint(bp[kk + 4]);
            }
#pragma unroll
            for (int mi = 0; mi < 4; mi++)
#pragma unroll
                for (int ni = 0; ni < 4; ni++)
                    mma_tf32(acc[mi][ni], afr[mi], bfr[ni]);
        }
        __syncthreads();
    }

#pragma unroll
    for (int mi = 0; mi < 4; mi++) {
        int rbase = m0 + wm * 64 + mi * 16 + (lane >> 2);
#pragma unroll
        for (int half = 0; half < 2; half++) {
            int r = rbase + half * 8;
            if (r >= N_FILE) continue;
            float he = hasedge[r];
#pragma unroll
            for (int ni = 0; ni < 4; ni++) {
                int c0 = n0 + wn * 32 + ni * 8 + (lane & 3) * 2;
                float v0 = acc[mi][ni][half * 2 + 0] + cbias[c0]     + he * bconst[c0];
                float v1 = acc[mi][ni][half * 2 + 1] + cbias[c0 + 1] + he * bconst[c0 + 1];
                *(float2*)(C + (size_t)r * N_OUT + c0) = make_float2(v0, v1);
            }
        }
    }
}

// ---------------- fp32 SGEMM (precompute-sized, batched z) ----
#define BM 128
#define BN 128
#define BK 8
#define TM 8
#define TN 8

__global__ __launch_bounds__(256, 2)
void sgemm(const float* __restrict__ A, int lda,
           const float* __restrict__ B, int ldb,
           float* __restrict__ C, int ldc,
           int M, int N, int K,
           long sA, long sB, long sC)
{
    A += (long)blockIdx.z * sA;
    B += (long)blockIdx.z * sB;
    C += (long)blockIdx.z * sC;

    __shared__ float As[BK][BM];
    __shared__ float Bs[BK][BN];
    const int tid = threadIdx.x;
    const int bm  = blockIdx.y * BM;
    const int bn  = blockIdx.x * BN;

    const int aRow  = tid >> 1;
    const int aCol4 = (tid & 1) * 4;
    const int bRow  = tid >> 5;
    const int bCol4 = (tid & 31) * 4;
    const int ty = tid >> 4, tx = tid & 15;

    float acc[TM][TN];
#pragma unroll
    for (int i = 0; i < TM; i++)
#pragma unroll
        for (int j = 0; j < TN; j++) acc[i][j] = 0.f;

    for (int k0 = 0; k0 < K; k0 += BK) {
        float4 av;
        if (bm + aRow < M)
            av = *(const float4*)(A + (size_t)(bm + aRow) * lda + k0 + aCol4);
        else
            av = make_float4(0.f, 0.f, 0.f, 0.f);
        As[aCol4 + 0][aRow] = av.x;
        As[aCol4 + 1][aRow] = av.y;
        As[aCol4 + 2][aRow] = av.z;
        As[aCol4 + 3][aRow] = av.w;

        float4 bv = *(const float4*)(B + (size_t)(k0 + bRow) * ldb + bn + bCol4);
        *(float4*)(&Bs[bRow][bCol4]) = bv;

        __syncthreads();
#pragma unroll
        for (int k = 0; k < BK; k++) {
            float ra[TM], rb[TN];
#pragma unroll
            for (int i = 0; i < TM; i++) ra[i] = As[k][ty * TM + i];
#pragma unroll
            for (int j = 0; j < TN; j++) rb[j] = Bs[k][tx * TN + j];
#pragma unroll
            for (int i = 0; i < TM; i++)
#pragma unroll
                for (int j = 0; j < TN; j++)
                    acc[i][j] = fmaf(ra[i], rb[j], acc[i][j]);
        }
        __syncthreads();
    }

#pragma unroll
    for (int i = 0; i < TM; i++) {
        int row = bm + ty * TM + i;
        if (row >= M) break;
#pragma unroll
        for (int j = 0; j < TN; j += 4) {
            int col = bn + tx * TN + j;
            float4 v;
            v.x = acc[i][j];     v.y = acc[i][j + 1];
            v.z = acc[i][j + 2]; v.w = acc[i][j + 3];
            *(float4*)(C + (size_t)row * ldc + col) = v;
        }
    }
}

// ---------------- coalesced GEVM ----------
__global__ __launch_bounds__(256)
void gevm(const float* __restrict__ x, const float* __restrict__ W,
          float* __restrict__ y, int K, int N, const float* __restrict__ add)
{
    int c  = blockIdx.x * 64 + (threadIdx.x & 63);
    int ks = threadIdx.x >> 6;
    int kper = K >> 2;
    int k0 = ks * kper, k1 = k0 + kper;
    float s = 0.f;
    for (int k = k0; k < k1; k++) s = fmaf(x[k], W[(size_t)k * N + c], s);
    __shared__ float sm[4][64];
    sm[ks][threadIdx.x & 63] = s;
    __syncthreads();
    if (ks == 0) {
        int l = threadIdx.x & 63;
        float v = sm[0][l] + sm[1][l] + sm[2][l] + sm[3][l];
        if (add) v += add[c];
        y[c] = v;
    }
}

// ---------------- warp-per-output dot kernels ----------
__device__ __forceinline__ float warp_sum(float s) {
#pragma unroll
    for (int o = 16; o > 0; o >>= 1) s += __shfl_down_sync(0xffffffffu, s, o);
    return s;
}

__global__ __launch_bounds__(256)
void k_u(const float* __restrict__ Wdst, const float* __restrict__ attn_r) {
    int wg = blockIdx.x * 8 + (threadIdx.x >> 5);
    int lane = threadIdx.x & 31;
    int k = wg / 3, h = wg - k * 3;
    const float* row = Wdst + (size_t)k * HD + h * N_OUT;
    const float* v   = attn_r + h * N_OUT;
    float s = 0.f;
#pragma unroll
    for (int j = lane; j < N_OUT; j += 32) s = fmaf(row[j], v[j], s);
    s = warp_sum(s);
    if (lane == 0) d_u[k * 3 + h] = s;
}

__global__ __launch_bounds__(256)
void k_Vl(const float* __restrict__ attn_l) {
    int wg = blockIdx.x * 8 + (threadIdx.x >> 5);
    int lane = threadIdx.x & 31;
    int k = wg / 3, h = wg - k * 3;
    const float* row = d_Wcomb + (size_t)k * HD + h * N_OUT;
    const float* v   = attn_l + h * N_OUT;
    float s = 0.f;
#pragma unroll
    for (int j = lane; j < N_OUT; j += 32) s = fmaf(row[j], v[j], s);
    s = warp_sum(s);
    if (lane == 0) d_Vl[k * 3 + h] = s;
}

__global__ __launch_bounds__(256)
void k_Vr(const float* __restrict__ Wfile) {
    int wg = blockIdx.x * 8 + (threadIdx.x >> 5);
    int lane = threadIdx.x & 31;
    int k = wg / 3, h = wg - k * 3;
    const float* row = Wfile + (size_t)k * N_INP;
    float s = 0.f;
#pragma unroll
    for (int c = lane; c < N_INP; c += 32) s = fmaf(row[c], d_u[c * 3 + h], s);
    s = warp_sum(s);
    if (lane == 0) d_Vr[k * 3 + h] = s;
}

__global__ void k_bl(const float* __restrict__ attn_l) {
    int w = threadIdx.x >> 5, lane = threadIdx.x & 31;
    if (w >= NH) return;
    float s = 0.f;
    for (int j = lane; j < N_OUT; j += 32)
        s = fmaf(d_bsrc[w * N_OUT + j], attn_l[w * N_OUT + j], s);
    s = warp_sum(s);
    if (lane == 0) d_bl[w] = s;
}

__global__ void k_br(const float* __restrict__ bfile) {
    int w = threadIdx.x >> 5, lane = threadIdx.x & 31;
    if (w >= NH) return;
    float s = 0.f;
    for (int c = lane; c < N_INP; c += 32)
        s = fmaf(bfile[c], d_u[c * 3 + w], s);
    s = warp_sum(s);
    if (lane == 0) d_br[w] = s;
}

// ---------------- transpose + tf32 round ----
__global__ void k_w2t() {
    __shared__ float tile[32][33];
    int nb = blockIdx.x * 32, kb = blockIdx.y * 32;
    int tx = threadIdx.x, ty = threadIdx.y;
#pragma unroll
    for (int j = 0; j < 32; j += 8)
        tile[ty + j][tx] = d_W2[(size_t)(kb + ty + j) * N_OUT + nb + tx];
    __syncthreads();
#pragma unroll
    for (int j = 0; j < 32; j += 8)
        d_W2T[(size_t)(nb + ty + j) * KAGG + kb + tx] = to_tf32(tile[tx][ty + j]);
}

// ---------------- node logits ----------------
__global__ void node_logits(const float* __restrict__ X,
                            const float* __restrict__ V,
                            const float* __restrict__ b3,
                            float* __restrict__ out, int Nn)
{
    __shared__ float sV[N_INP * NH];
    int t = threadIdx.x;
    for (int i = t; i < N_INP * NH; i += blockDim.x) sV[i] = V[i];
    __syncthreads();
    int warp = t >> 5, lane = t & 31;
    int n = blockIdx.x * (blockDim.x >> 5) + warp;
    if (n >= Nn) return;
    const float* x = X + (size_t)n * N_INP;
    float s0 = 0.f, s1 = 0.f, s2 = 0.f;
    for (int k = lane; k < N_INP; k += 32) {
        float xv = x[k];
        s0 = fmaf(xv, sV[k * 3 + 0], s0);
        s1 = fmaf(xv, sV[k * 3 + 1], s1);
        s2 = fmaf(xv, sV[k * 3 + 2], s2);
    }
#pragma unroll
    for (int o = 16; o > 0; o >>= 1) {
        s0 += __shfl_down_sync(0xffffffffu, s0, o);
        s1 += __shfl_down_sync(0xffffffffu, s1, o);
        s2 += __shfl_down_sync(0xffffffffu, s2, o);
    }
    if (lane == 0)
        *(float4*)(out + (size_t)n * 4) = make_float4(s0 + b3[0], s1 + b3[1], s2 + b3[2], 0.f);
}

// ---------------- CSR build ----------------
__global__ void k_zero() {
    int i = blockIdx.x * blockDim.x + threadIdx.x;
    if (i < N_FILE) { d_deg[i] = 0; d_cur[i] = 0; }
}

__global__ void k_count(const int* __restrict__ dst, int E) {
    int i = blockIdx.x * blockDim.x + threadIdx.x;
    if (i < E) atomicAdd(&d_deg[dst[i]], 1);
}

__global__ void k_scan() {
    __shared__ int part[512];
    int t = threadIdx.x;
    const int per = (N_FILE + 511) / 512;
    int b = t * per;
    int sum = 0;
    for (int i = 0; i < per; i++) {
        int idx = b + i;
        if (idx < N_FILE) sum += d_deg[idx];
    }
    part[t] = sum;
    __syncthreads();
    for (int o = 1; o < 512; o <<= 1) {
        int v = (t >= o) ? part[t - o] : 0;
        __syncthreads();
        part[t] += v;
        __syncthreads();
    }
    int run = part[t] - sum;
    for (int i = 0; i < per; i++) {
        int idx = b + i;
        if (idx < N_FILE) {
            d_off[idx] = run;
            d_hasedge[idx] = d_deg[idx] ? 1.f : 0.f;
            run += d_deg[idx];
        }
    }
    if (t == 511) d_off[N_FILE] = run;
}

__global__ void k_scatter(const int* __restrict__ src, const int* __restrict__ dst, int E) {
    int i = blockIdx.x * blockDim.x + threadIdx.x;
    if (i >= E) return;
    int d = dst[i];
    int p = atomicAdd(&d_cur[d], 1);
    d_srcs[d_off[d] + p] = src[i];
}

// ---------------- per-dst softmax + embedding aggregation ----------------
#define GCAP 1024

__global__ __launch_bounds__(128)
void gat_aggregate(const float* __restrict__ emb, int dbase)
{
    int d = dbase + blockIdx.x;
    int t = threadIdx.x;
    int lane = t & 31, warp = t >> 5;
    int start = d_off[d], end = d_off[d + 1];
    int deg = end - start;
    bool cached = (deg <= GCAP);

    __shared__ int   sh_src[GCAP];
    __shared__ float sh_w[GCAP * 3];
    __shared__ float s_er[4], s_m[3], s_iz[3];
    __shared__ float red[4][3];

    if (t < 4) s_er[t] = d_er[(size_t)d * 4 + t];
    __syncthreads();
    float er0 = s_er[0], er1 = s_er[1], er2 = s_er[2];
    const float4* el4 = (const float4*)d_el;

    // pass 1: logits (+ cache) + max
    float m0 = -CUDART_INF_F, m1 = -CUDART_INF_F, m2 = -CUDART_INF_F;
    for (int e = start + t; e < end; e += 128) {
        int s = d_srcs[e];
        float4 L = el4[s];
        float l0 = lrelu(L.x + er0), l1 = lrelu(L.y + er1), l2 = lrelu(L.z + er2);
        if (cached) {
            int i = e - start;
            sh_src[i] = s;
            sh_w[i * 3 + 0] = l0; sh_w[i * 3 + 1] = l1; sh_w[i * 3 + 2] = l2;
        }
        m0 = fmaxf(m0, l0); m1 = fmaxf(m1, l1); m2 = fmaxf(m2, l2);
    }
#pragma unroll
    for (int o = 16; o > 0; o >>= 1) {
        m0 = fmaxf(m0, __shfl_xor_sync(0xffffffffu, m0, o));
        m1 = fmaxf(m1, __shfl_xor_sync(0xffffffffu, m1, o));
        m2 = fmaxf(m2, __shfl_xor_sync(0xffffffffu, m2, o));
    }
    if (lane == 0) { red[warp][0] = m0; red[warp][1] = m1; red[warp][2] = m2; }
    __syncthreads();
    if (t < 3) s_m[t] = fmaxf(fmaxf(red[0][t], red[1][t]), fmaxf(red[2][t], red[3][t]));
    __syncthreads();
    m0 = s_m[0]; m1 = s_m[1]; m2 = s_m[2];

    // pass 2: sum of exp
    float z0 = 0.f, z1 = 0.f, z2 = 0.f;
    for (int e = start + t; e < end; e += 128) {
        float l0, l1, l2;
        if (cached) {
            int i = e - start;
            l0 = sh_w[i * 3 + 0]; l1 = sh_w[i * 3 + 1]; l2 = sh_w[i * 3 + 2];
        } else {
            int s = d_srcs[e];
            float4 L = el4[s];
            l0 = lrelu(L.x + er0); l1 = lrelu(L.y + er1); l2 = lrelu(L.z + er2);
        }
        z0 += __expf(l0 - m0); z1 += __expf(l1 - m1); z2 += __expf(l2 - m2);
    }
#pragma unroll
    for (int o = 16; o > 0; o >>= 1) {
        z0 += __shfl_xor_sync(0xffffffffu, z0, o);
        z1 += __shfl_xor_sync(0xffffffffu, z1, o);
        z2 += __shfl_xor_sync(0xffffffffu, z2, o);
    }
    if (lane == 0) { red[warp][0] = z0; red[warp][1] = z1; red[warp][2] = z2; }
    __syncthreads();
    if (t < 3) {
        float z = red[0][t] + red[1][t] + red[2][t] + red[3][t];
        s_iz[t] = (z > 0.f) ? 1.f / z : 0.f;
    }
    __syncthreads();
    float iz0 = s_iz[0], iz1 = s_iz[1], iz2 = s_iz[2];

    // convert cached logits -> softmax weights
    if (cached) {
        for (int i = t; i < deg; i += 128) {
            sh_w[i * 3 + 0] = __expf(sh_w[i * 3 + 0] - m0) * iz0;
            sh_w[i * 3 + 1] = __expf(sh_w[i * 3 + 1] - m1) * iz1;
            sh_w[i * 3 + 2] = __expf(sh_w[i * 3 + 2] - m2) * iz2;
        }
    }
    __syncthreads();

    // pass 3: weighted aggregation (x2 unrolled for MLP)
    float a00 = 0.f, a01 = 0.f, a02 = 0.f, a03 = 0.f;
    float a10 = 0.f, a11 = 0.f, a12 = 0.f, a13 = 0.f;
    float a20 = 0.f, a21 = 0.f, a22 = 0.f, a23 = 0.f;
    int c4 = t * 4;

    if (cached) {
        int i = 0;
        for (; i + 1 < deg; i += 2) {
            int   sA_ = sh_src[i],        sB_ = sh_src[i + 1];
            float wA0 = sh_w[i * 3 + 0],  wB0 = sh_w[i * 3 + 3];
            float wA1 = sh_w[i * 3 + 1],  wB1 = sh_w[i * 3 + 4];
            float wA2 = sh_w[i * 3 + 2],  wB2 = sh_w[i * 3 + 5];
            float4 xA = *(const float4*)(emb + (size_t)sA_ * N_INP + c4);
            float4 xB = *(const float4*)(emb + (size_t)sB_ * N_INP + c4);
            a00 = fmaf(wA0, xA.x, a00); a01 = fmaf(wA0, xA.y, a01);
            a02 = fmaf(wA0, xA.z, a02); a03 = fmaf(wA0, xA.w, a03);
            a10 = fmaf(wA1, xA.x, a10); a11 = fmaf(wA1, xA.y, a11);
            a12 = fmaf(wA1, xA.z, a12); a13 = fmaf(wA1, xA.w, a13);
            a20 = fmaf(wA2, xA.x, a20); a21 = fmaf(wA2, xA.y, a21);
            a22 = fmaf(wA2, xA.z, a22); a23 = fmaf(wA2, xA.w, a23);
            a00 = fmaf(wB0, xB.x, a00); a01 = fmaf(wB0, xB.y, a01);
            a02 = fmaf(wB0, xB.z, a02); a03 = fmaf(wB0, xB.w, a03);
            a10 = fmaf(wB1, xB.x, a10); a11 = fmaf(wB1, xB.y, a11);
            a12 = fmaf(wB1, xB.z, a12); a13 = fmaf(wB1, xB.w, a13);
            a20 = fmaf(wB2, xB.x, a20); a21 = fmaf(wB2, xB.y, a21);
            a22 = fmaf(wB2, xB.z, a22); a23 = fmaf(wB2, xB.w, a23);
        }
        if (i < deg) {
            int s = sh_src[i];
            float w0 = sh_w[i * 3 + 0], w1 = sh_w[i * 3 + 1], w2 = sh_w[i * 3 + 2];
            float4 x = *(const float4*)(emb + (size_t)s * N_INP + c4);
            a00 = fmaf(w0, x.x, a00); a01 = fmaf(w0, x.y, a01);
            a02 = fmaf(w0, x.z, a02); a03 = fmaf(w0, x.w, a03);
            a10 = fmaf(w1, x.x, a10); a11 = fmaf(w1, x.y, a11);
            a12 = fmaf(w1, x.z, a12); a13 = fmaf(w1, x.w, a13);
            a20 = fmaf(w2, x.x, a20); a21 = fmaf(w2, x.y, a21);
            a22 = fmaf(w2, x.z, a22); a23 = fmaf(w2, x.w, a23);
        }
    } else {
        for (int e = start; e < end; e++) {
            int s = d_srcs[e];
            float4 L = el4[s];
            float w0 = __expf(lrelu(L.x + er0) - m0) * iz0;
            float w1 = __expf(lrelu(L.y + er1) - m1) * iz1;
            float w2 = __expf(lrelu(L.z + er2) - m2) * iz2;
            float4 x = *(const float4*)(emb + (size_t)s * N_INP + c4);
            a00 = fmaf(w0, x.x, a00); a01 = fmaf(w0, x.y, a01);
            a02 = fmaf(w0, x.z, a02); a03 = fmaf(w0, x.w, a03);
            a10 = fmaf(w1, x.x, a10); a11 = fmaf(w1, x.y, a11);
            a12 = fmaf(w1, x.z, a12); a13 = fmaf(w1, x.w, a13);
            a20 = fmaf(w2, x.x, a20); a21 = fmaf(w2, x.y, a21);
            a22 = fmaf(w2, x.z, a22); a23 = fmaf(w2, x.w, a23);
        }
    }

    float* aout = d_agg + (size_t)d * KAGG;
    *(float4*)(aout + 0 * N_INP + c4) =
        make_float4(to_tf32(a00), to_tf32(a01), to_tf32(a02), to_tf32(a03));
    *(float4*)(aout + 1 * N_INP + c4) =
        make_float4(to_tf32(a10), to_tf32(a11), to_tf32(a12), to_tf32(a13));
    *(float4*)(aout + 2 * N_INP + c4) =
        make_float4(to_tf32(a20), to_tf32(a21), to_tf32(a22), to_tf32(a23));
}

// ---------------- launch ----------------
extern "C" void kernel_launch(void* const* d_in, const int* in_sizes, int n_in,
                              void* d_out, int out_size)
{
    const float* emb_api  = (const float*)d_in[0];
    const float* emb_file = (const float*)d_in[1];
    const int*   src      = (const int*)d_in[3];
    const int*   dst      = (const int*)d_in[4];
    const float* Wapi     = (const float*)d_in[5];
    const float* bapi     = (const float*)d_in[6];
    const float* Wfile    = (const float*)d_in[7];
    const float* bfile    = (const float*)d_in[8];
    const float* Wsrc     = (const float*)d_in[9];
    const float* Wdst     = (const float*)d_in[10];
    const float* attn_l   = (const float*)d_in[11];
    const float* attn_r   = (const float*)d_in[12];
    const float* gat_bias = (const float*)d_in[13];
    const float* Whead    = (const float*)d_in[14];
    const float* bhead    = (const float*)d_in[15];
    float* out = (float*)d_out;

    const int E = in_sizes[3];

    float *p_Wcomb, *p_W2, *p_W2T, *p_Vl, *p_Vr, *p_bl, *p_br, *p_bconst, *p_cbias,
          *p_agg, *p_el, *p_er, *p_hasedge, *p_bsrc;
    cudaGetSymbolAddress((void**)&p_Wcomb,   d_Wcomb);
    cudaGetSymbolAddress((void**)&p_W2,      d_W2);
    cudaGetSymbolAddress((void**)&p_W2T,     d_W2T);
    cudaGetSymbolAddress((void**)&p_Vl,      d_Vl);
    cudaGetSymbolAddress((void**)&p_Vr,      d_Vr);
    cudaGetSymbolAddress((void**)&p_bl,      d_bl);
    cudaGetSymbolAddress((void**)&p_br,      d_br);
    cudaGetSymbolAddress((void**)&p_bconst,  d_bconst);
    cudaGetSymbolAddress((void**)&p_cbias,   d_cbias);
    cudaGetSymbolAddress((void**)&p_agg,     d_agg);
    cudaGetSymbolAddress((void**)&p_el,      d_el);
    cudaGetSymbolAddress((void**)&p_er,      d_er);
    cudaGetSymbolAddress((void**)&p_hasedge, d_hasedge);
    cudaGetSymbolAddress((void**)&p_bsrc,    d_bsrc);

    cudaFuncSetAttribute(gemm_mma, cudaFuncAttributeMaxDynamicSharedMemorySize, GEMM_SMEM_BYTES);

    static cudaStream_t s1 = nullptr, s2 = nullptr, s3 = nullptr;
    static cudaEvent_t ev0, ev_bsrc, ev_csr, ev_s2, ev_wcomb, ev_a0, ev_a1, ev_done;
    if (!s1) {
        cudaStreamCreateWithFlags(&s1, cudaStreamNonBlocking);
        cudaStreamCreateWithFlags(&s2, cudaStreamNonBlocking);
        cudaStreamCreateWithFlags(&s3, cudaStreamNonBlocking);
        cudaEventCreateWithFlags(&ev0,     cudaEventDisableTiming);
        cudaEventCreateWithFlags(&ev_bsrc, cudaEventDisableTiming);
        cudaEventCreateWithFlags(&ev_csr,  cudaEventDisableTiming);
        cudaEventCreateWithFlags(&ev_s2,   cudaEventDisableTiming);
        cudaEventCreateWithFlags(&ev_wcomb,cudaEventDisableTiming);
        cudaEventCreateWithFlags(&ev_a0,   cudaEventDisableTiming);
        cudaEventCreateWithFlags(&ev_a1,   cudaEventDisableTiming);
        cudaEventCreateWithFlags(&ev_done, cudaEventDisableTiming);
    }

    // fork
    cudaEventRecord(ev0, 0);
    cudaStreamWaitEvent(s1, ev0, 0);
    cudaStreamWaitEvent(s2, ev0, 0);
    cudaStreamWaitEvent(s3, ev0, 0);

    // ---- s1: CSR build ----
    k_zero   <<<(N_FILE + 255) / 256, 256, 0, s1>>>();
    k_count  <<<(E + 255) / 256, 256, 0, s1>>>(dst, E);
    k_scan   <<<1, 512, 0, s1>>>();
    k_scatter<<<(E + 255) / 256, 256, 0, s1>>>(src, dst, E);
    cudaEventRecord(ev_csr, s1);

    // ---- default: api-side critical path ----
    gevm<<<HD / 64, 256>>>(bapi, Wsrc, p_bsrc, N_INP, HD, nullptr);
    cudaEventRecord(ev_bsrc, 0);
    sgemm<<<dim3(HD / BN, N_INP / BM, 1), 256>>>(
        Wapi, N_INP, Wsrc, HD, p_Wcomb, HD, N_INP, HD, N_INP, 0, 0, 0);
    cudaEventRecord(ev_wcomb, 0);
    k_Vl<<<192, 256>>>(attn_l);
    k_bl<<<1, 128>>>(attn_l);
    node_logits<<<(N_API + 7) / 8, 256>>>(emb_api, p_Vl, p_bl, p_el, N_API);

    // ---- s3: W2 branch (off critical path) ----
    cudaStreamWaitEvent(s3, ev_wcomb, 0);
    sgemm<<<dim3(N_OUT / BN, N_INP / BM, NH), 256, 0, s3>>>(
        p_Wcomb, HD, Whead, N_OUT, p_W2, N_OUT,
        N_INP, N_OUT, N_OUT,
        (long)N_OUT, (long)N_OUT * N_OUT, (long)N_INP * N_OUT);
    k_w2t<<<dim3(N_OUT / 32, KAGG / 32), dim3(32, 8), 0, s3>>>();

    // ---- s2: file-side precompute ----
    k_u<<<192, 256, 0, s2>>>(Wdst, attn_r);
    k_Vr<<<192, 256, 0, s2>>>(Wfile);
    k_br<<<1, 128, 0, s2>>>(bfile);
    gevm<<<N_OUT / 64, 256, 0, s2>>>(gat_bias, Whead, p_cbias, HD, N_OUT, bhead);
    cudaStreamWaitEvent(s2, ev_bsrc, 0);
    gevm<<<N_OUT / 64, 256, 0, s2>>>(p_bsrc, Whead, p_bconst, HD, N_OUT, nullptr);
    node_logits<<<(N_FILE + 7) / 8, 256, 0, s2>>>(emb_file, p_Vr, p_br, p_er, N_FILE);
    cudaEventRecord(ev_s2, s2);

    // ---- default: aggregation chunks (pipelined with gemm on s3) ----
    cudaStreamWaitEvent(0, ev_csr, 0);
    cudaStreamWaitEvent(0, ev_s2, 0);
    gat_aggregate<<<CH0_DST, 128>>>(emb_api, 0);
    cudaEventRecord(ev_a0, 0);
    gat_aggregate<<<CH1_DST, 128>>>(emb_api, CH0_DST);
    cudaEventRecord(ev_a1, 0);

    // ---- s3: gemm chunks ----
    cudaStreamWaitEvent(s3, ev_csr, 0);   // hasedge
    cudaStreamWaitEvent(s3, ev_s2, 0);    // cbias, bconst
    cudaStreamWaitEvent(s3, ev_a0, 0);
    gemm_mma<<<dim3(N_OUT / 128, CH0_BLOCKS), 256, GEMM_SMEM_BYTES, s3>>>(
        p_agg, p_W2T, out, p_cbias, p_bconst, p_hasedge, 0);
    cudaStreamWaitEvent(s3, ev_a1, 0);
    gemm_mma<<<dim3(N_OUT / 128, CH1_BLOCKS), 256, GEMM_SMEM_BYTES, s3>>>(
        p_agg, p_W2T, out, p_cbias, p_bconst, p_hasedge, CH0_BLOCKS);
    cudaEventRecord(ev_done, s3);

    // join everything back to the capture stream
    cudaStreamWaitEvent(0, ev_done, 0);
}

// round 7
// speedup vs baseline: 4.9016x; 1.1871x over previous
#include <cuda_runtime.h>
#include <cuda_fp16.h>
#include <math_constants.h>
#include <cstdint>

// ---------------- problem constants ----------------
#define N_API   50000
#define N_FILE  20000
#define N_INP   512
#define N_OUT   256
#define NH      3
#define HD      768   // NH*N_OUT
#define KAGG    1536  // NH*N_INP
#define M_PAD   20096 // 157*128
#define NCHUNK  48    // KAGG/32 (k-chunk = 32 halfs)

// pipeline chunking: 157 row-blocks = 80 + 77
#define CH0_BLOCKS 80
#define CH1_BLOCKS 77
#define CH0_DST    (CH0_BLOCKS * 128)
#define CH1_DST    (N_FILE - CH0_DST)

// ---------------- device scratch ----------------
__device__ float  d_Wcomb[N_INP * HD];
__device__ float  d_W2   [KAGG * N_OUT];
__device__ __half d_W2Th [N_OUT * KAGG];            // fp16 [256,1536]
__device__ __half d_embh [(size_t)N_API * N_INP];   // fp16 emb_api, 51.2 MB
__device__ __half d_aggh [(size_t)M_PAD * KAGG];    // fp16 agg, 61.7 MB (tail rows stay 0)
__device__ float  d_u    [N_INP * NH];
__device__ float  d_Vl   [N_INP * NH];
__device__ float  d_Vr   [N_INP * NH];
__device__ float  d_bsrc [HD];
__device__ float  d_bl   [NH];
__device__ float  d_br   [NH];
__device__ float  d_bconst[N_OUT];
__device__ float  d_cbias [N_OUT];
__device__ float  d_el   [N_API * 4];
__device__ float  d_er   [N_FILE * 4];
__device__ int    d_deg  [N_FILE];
__device__ int    d_cur  [N_FILE];
__device__ int    d_off  [N_FILE + 1];
__device__ float  d_hasedge[N_FILE];
__device__ int    d_srcs [262144];

// ---------------- helpers ----------------
__device__ __forceinline__ uint32_t smem_u32(const void* p) {
    uint32_t a;
    asm("{ .reg .u64 t; cvta.to.shared.u64 t, %1; cvt.u32.u64 %0, t; }" : "=r"(a) : "l"(p));
    return a;
}
__device__ __forceinline__ float lrelu(float v) { return v > 0.f ? v : 0.2f * v; }

#define CP_ASYNC16(dst, src) \
    asm volatile("cp.async.cg.shared.global [%0], [%1], 16;" :: "r"(dst), "l"(src) : "memory")
#define CP_COMMIT()  asm volatile("cp.async.commit_group;" ::: "memory")
#define CP_WAIT0()   asm volatile("cp.async.wait_group 0;" ::: "memory")
#define CP_WAIT1()   asm volatile("cp.async.wait_group 1;" ::: "memory")

__device__ __forceinline__ void mma_f16(float* c, const uint32_t* a, const uint32_t* b) {
    asm volatile(
        "mma.sync.aligned.m16n8k16.row.col.f32.f16.f16.f32 "
        "{%0,%1,%2,%3}, {%4,%5,%6,%7}, {%8,%9}, {%0,%1,%2,%3};"
        : "+f"(c[0]), "+f"(c[1]), "+f"(c[2]), "+f"(c[3])
        : "r"(a[0]), "r"(a[1]), "r"(a[2]), "r"(a[3]), "r"(b[0]), "r"(b[1]));
}

// ---------------- fp16 tensor-core GEMM: C = A @ B^T + biases ----------------
// A: [M_PAD, KAGG] fp16 ; B: [256, KAGG] fp16 ; C: [20000, 256] fp32
// Block 128M x 128N, 8 warps (warp 64x32), K-chunk 32 halfs, 2-stage cp.async.
#define LDPH   40                 // padded row pitch in halfs: 80B (16B-aligned)
#define TILEH  (128 * LDPH)       // halfs per stage per matrix
#define GEMM_SMEM_BYTES (4 * TILEH * 2)   // 40960 B

__global__ void __launch_bounds__(256, 2)
gemm_mma(const __half* __restrict__ A, const __half* __restrict__ B,
         float* __restrict__ C,
         const float* __restrict__ cbias,
         const float* __restrict__ bconst,
         const float* __restrict__ hasedge,
         int mb_base)
{
    extern __shared__ __half smh[];
    __half* As = smh;
    __half* Bs = smh + 2 * TILEH;

    const int tid  = threadIdx.x;
    const int wid  = tid >> 5, lane = tid & 31;
    const int wm   = wid & 1;
    const int wn   = wid >> 1;
    const int m0   = (mb_base + blockIdx.y) * 128;
    const int n0   = blockIdx.x * 128;

    float acc[4][4][4];
#pragma unroll
    for (int a = 0; a < 4; a++)
#pragma unroll
        for (int b = 0; b < 4; b++)
#pragma unroll
            for (int c = 0; c < 4; c++) acc[a][b][c] = 0.f;

    // loader: per chunk, A: 128 rows x 64B, B: 128 rows x 64B
    // 256 thr x 2 iters: idx = tid + t*256; row = idx>>2 (0..127), seg = idx&3 (16B each)
#define LOAD_TILE(kt, s) do {                                                     \
    int _k0 = (kt) * 32;                                                          \
    _Pragma("unroll")                                                             \
    for (int _t = 0; _t < 2; _t++) {                                              \
        int _idx = tid + _t * 256;                                                \
        int _row = _idx >> 2, _seg = _idx & 3;                                    \
        const __half* _g = A + (size_t)(m0 + _row) * KAGG + _k0 + _seg * 8;       \
        CP_ASYNC16(smem_u32(As + (s) * TILEH + _row * LDPH + _seg * 8), _g);      \
    }                                                                             \
    _Pragma("unroll")                                                             \
    for (int _t = 0; _t < 2; _t++) {                                              \
        int _idx = tid + _t * 256;                                                \
        int _row = _idx >> 2, _seg = _idx & 3;                                    \
        const __half* _g = B + (size_t)(n0 + _row) * KAGG + _k0 + _seg * 8;       \
        CP_ASYNC16(smem_u32(Bs + (s) * TILEH + _row * LDPH + _seg * 8), _g);      \
    }                                                                             \
    CP_COMMIT();                                                                  \
} while (0)

    LOAD_TILE(0, 0);

    for (int kt = 0; kt < NCHUNK; kt++) {
        int s = kt & 1;
        if (kt + 1 < NCHUNK) { LOAD_TILE(kt + 1, s ^ 1); CP_WAIT1(); }
        else                 { CP_WAIT0(); }
        __syncthreads();

        const __half* a_base = As + s * TILEH + (wm * 64 + (lane >> 2)) * LDPH;
        const __half* b_base = Bs + s * TILEH + (wn * 32 + (lane >> 2)) * LDPH;
        const int kc = (lane & 3) * 2;

#pragma unroll
        for (int ks = 0; ks < 2; ks++) {           // two k16 steps per 32-half chunk
            int kk = ks * 16 + kc;
            uint32_t afr[4][4];
#pragma unroll
            for (int mi = 0; mi < 4; mi++) {
                const __half* ap = a_base + mi * 16 * LDPH;
                afr[mi][0] = *(const uint32_t*)(ap + kk);
                afr[mi][1] = *(const uint32_t*)(ap + 8 * LDPH + kk);
                afr[mi][2] = *(const uint32_t*)(ap + kk + 8);
                afr[mi][3] = *(const uint32_t*)(ap + 8 * LDPH + kk + 8);
            }
            uint32_t bfr[4][2];
#pragma unroll
            for (int ni = 0; ni < 4; ni++) {
                const __half* bp = b_base + ni * 8 * LDPH;
                bfr[ni][0] = *(const uint32_t*)(bp + kk);
                bfr[ni][1] = *(const uint32_t*)(bp + kk + 8);
            }
#pragma unroll
            for (int mi = 0; mi < 4; mi++)
#pragma unroll
                for (int ni = 0; ni < 4; ni++)
                    mma_f16(acc[mi][ni], afr[mi], bfr[ni]);
        }
        __syncthreads();
    }

#pragma unroll
    for (int mi = 0; mi < 4; mi++) {
        int rbase = m0 + wm * 64 + mi * 16 + (lane >> 2);
#pragma unroll
        for (int half_ = 0; half_ < 2; half_++) {
            int r = rbase + half_ * 8;
            if (r >= N_FILE) continue;
            float he = hasedge[r];
#pragma unroll
            for (int ni = 0; ni < 4; ni++) {
                int c0 = n0 + wn * 32 + ni * 8 + (lane & 3) * 2;
                float v0 = acc[mi][ni][half_ * 2 + 0] + cbias[c0]     + he * bconst[c0];
                float v1 = acc[mi][ni][half_ * 2 + 1] + cbias[c0 + 1] + he * bconst[c0 + 1];
                *(float2*)(C + (size_t)r * N_OUT + c0) = make_float2(v0, v1);
            }
        }
    }
}

// ---------------- fp32 SGEMM (precompute-sized, batched z) ----
#define BM 128
#define BN 128
#define BK 8
#define TM 8
#define TN 8

__global__ __launch_bounds__(256, 2)
void sgemm(const float* __restrict__ A, int lda,
           const float* __restrict__ B, int ldb,
           float* __restrict__ C, int ldc,
           int M, int N, int K,
           long sA, long sB, long sC)
{
    A += (long)blockIdx.z * sA;
    B += (long)blockIdx.z * sB;
    C += (long)blockIdx.z * sC;

    __shared__ float As[BK][BM];
    __shared__ float Bs[BK][BN];
    const int tid = threadIdx.x;
    const int bm  = blockIdx.y * BM;
    const int bn  = blockIdx.x * BN;

    const int aRow  = tid >> 1;
    const int aCol4 = (tid & 1) * 4;
    const int bRow  = tid >> 5;
    const int bCol4 = (tid & 31) * 4;
    const int ty = tid >> 4, tx = tid & 15;

    float acc[TM][TN];
#pragma unroll
    for (int i = 0; i < TM; i++)
#pragma unroll
        for (int j = 0; j < TN; j++) acc[i][j] = 0.f;

    for (int k0 = 0; k0 < K; k0 += BK) {
        float4 av;
        if (bm + aRow < M)
            av = *(const float4*)(A + (size_t)(bm + aRow) * lda + k0 + aCol4);
        else
            av = make_float4(0.f, 0.f, 0.f, 0.f);
        As[aCol4 + 0][aRow] = av.x;
        As[aCol4 + 1][aRow] = av.y;
        As[aCol4 + 2][aRow] = av.z;
        As[aCol4 + 3][aRow] = av.w;

        float4 bv = *(const float4*)(B + (size_t)(k0 + bRow) * ldb + bn + bCol4);
        *(float4*)(&Bs[bRow][bCol4]) = bv;

        __syncthreads();
#pragma unroll
        for (int k = 0; k < BK; k++) {
            float ra[TM], rb[TN];
#pragma unroll
            for (int i = 0; i < TM; i++) ra[i] = As[k][ty * TM + i];
#pragma unroll
            for (int j = 0; j < TN; j++) rb[j] = Bs[k][tx * TN + j];
#pragma unroll
            for (int i = 0; i < TM; i++)
#pragma unroll
                for (int j = 0; j < TN; j++)
                    acc[i][j] = fmaf(ra[i], rb[j], acc[i][j]);
        }
        __syncthreads();
    }

#pragma unroll
    for (int i = 0; i < TM; i++) {
        int row = bm + ty * TM + i;
        if (row >= M) break;
#pragma unroll
        for (int j = 0; j < TN; j += 4) {
            int col = bn + tx * TN + j;
            float4 v;
            v.x = acc[i][j];     v.y = acc[i][j + 1];
            v.z = acc[i][j + 2]; v.w = acc[i][j + 3];
            *(float4*)(C + (size_t)row * ldc + col) = v;
        }
    }
}

// ---------------- coalesced GEVM ----------
__global__ __launch_bounds__(256)
void gevm(const float* __restrict__ x, const float* __restrict__ W,
          float* __restrict__ y, int K, int N, const float* __restrict__ add)
{
    int c  = blockIdx.x * 64 + (threadIdx.x & 63);
    int ks = threadIdx.x >> 6;
    int kper = K >> 2;
    int k0 = ks * kper, k1 = k0 + kper;
    float s = 0.f;
    for (int k = k0; k < k1; k++) s = fmaf(x[k], W[(size_t)k * N + c], s);
    __shared__ float sm[4][64];
    sm[ks][threadIdx.x & 63] = s;
    __syncthreads();
    if (ks == 0) {
        int l = threadIdx.x & 63;
        float v = sm[0][l] + sm[1][l] + sm[2][l] + sm[3][l];
        if (add) v += add[c];
        y[c] = v;
    }
}

// ---------------- warp-per-output dot kernels ----------
__device__ __forceinline__ float warp_sum(float s) {
#pragma unroll
    for (int o = 16; o > 0; o >>= 1) s += __shfl_down_sync(0xffffffffu, s, o);
    return s;
}

__global__ __launch_bounds__(256)
void k_u(const float* __restrict__ Wdst, const float* __restrict__ attn_r) {
    int wg = blockIdx.x * 8 + (threadIdx.x >> 5);
    int lane = threadIdx.x & 31;
    int k = wg / 3, h = wg - k * 3;
    const float* row = Wdst + (size_t)k * HD + h * N_OUT;
    const float* v   = attn_r + h * N_OUT;
    float s = 0.f;
#pragma unroll
    for (int j = lane; j < N_OUT; j += 32) s = fmaf(row[j], v[j], s);
    s = warp_sum(s);
    if (lane == 0) d_u[k * 3 + h] = s;
}

__global__ __launch_bounds__(256)
void k_Vl(const float* __restrict__ attn_l) {
    int wg = blockIdx.x * 8 + (threadIdx.x >> 5);
    int lane = threadIdx.x & 31;
    int k = wg / 3, h = wg - k * 3;
    const float* row = d_Wcomb + (size_t)k * HD + h * N_OUT;
    const float* v   = attn_l + h * N_OUT;
    float s = 0.f;
#pragma unroll
    for (int j = lane; j < N_OUT; j += 32) s = fmaf(row[j], v[j], s);
    s = warp_sum(s);
    if (lane == 0) d_Vl[k * 3 + h] = s;
}

__global__ __launch_bounds__(256)
void k_Vr(const float* __restrict__ Wfile) {
    int wg = blockIdx.x * 8 + (threadIdx.x >> 5);
    int lane = threadIdx.x & 31;
    int k = wg / 3, h = wg - k * 3;
    const float* row = Wfile + (size_t)k * N_INP;
    float s = 0.f;
#pragma unroll
    for (int c = lane; c < N_INP; c += 32) s = fmaf(row[c], d_u[c * 3 + h], s);
    s = warp_sum(s);
    if (lane == 0) d_Vr[k * 3 + h] = s;
}

__global__ void k_bl(const float* __restrict__ attn_l) {
    int w = threadIdx.x >> 5, lane = threadIdx.x & 31;
    if (w >= NH) return;
    float s = 0.f;
    for (int j = lane; j < N_OUT; j += 32)
        s = fmaf(d_bsrc[w * N_OUT + j], attn_l[w * N_OUT + j], s);
    s = warp_sum(s);
    if (lane == 0) d_bl[w] = s;
}

__global__ void k_br(const float* __restrict__ bfile) {
    int w = threadIdx.x >> 5, lane = threadIdx.x & 31;
    if (w >= NH) return;
    float s = 0.f;
    for (int c = lane; c < N_INP; c += 32)
        s = fmaf(bfile[c], d_u[c * 3 + w], s);
    s = warp_sum(s);
    if (lane == 0) d_br[w] = s;
}

// ---------------- transpose + fp16 round: W2Th[n,k] = h(W2[k,n]) ----
__global__ void k_w2t() {
    __shared__ float tile[32][33];
    int nb = blockIdx.x * 32, kb = blockIdx.y * 32;
    int tx = threadIdx.x, ty = threadIdx.y;
#pragma unroll
    for (int j = 0; j < 32; j += 8)
        tile[ty + j][tx] = d_W2[(size_t)(kb + ty + j) * N_OUT + nb + tx];
    __syncthreads();
#pragma unroll
    for (int j = 0; j < 32; j += 8)
        d_W2Th[(size_t)(nb + ty + j) * KAGG + kb + tx] = __float2half_rn(tile[tx][ty + j]);
}

// ---------------- emb_api -> fp16 (8 floats per thread) ----------------
__global__ __launch_bounds__(256)
void k_emb2h(const float* __restrict__ emb) {
    size_t i = (size_t)blockIdx.x * 256 + threadIdx.x;   // < 3.2M
    const float4* src = (const float4*)(emb) + i * 2;
    float4 f0 = src[0], f1 = src[1];
    __half2 h0 = __floats2half2_rn(f0.x, f0.y);
    __half2 h1 = __floats2half2_rn(f0.z, f0.w);
    __half2 h2 = __floats2half2_rn(f1.x, f1.y);
    __half2 h3 = __floats2half2_rn(f1.z, f1.w);
    uint4 v;
    v.x = *(uint32_t*)&h0; v.y = *(uint32_t*)&h1;
    v.z = *(uint32_t*)&h2; v.w = *(uint32_t*)&h3;
    *((uint4*)d_embh + i) = v;
}

// ---------------- node logits ----------------
__global__ void node_logits(const float* __restrict__ X,
                            const float* __restrict__ V,
                            const float* __restrict__ b3,
                            float* __restrict__ out, int Nn)
{
    __shared__ float sV[N_INP * NH];
    int t = threadIdx.x;
    for (int i = t; i < N_INP * NH; i += blockDim.x) sV[i] = V[i];
    __syncthreads();
    int warp = t >> 5, lane = t & 31;
    int n = blockIdx.x * (blockDim.x >> 5) + warp;
    if (n >= Nn) return;
    const float* x = X + (size_t)n * N_INP;
    float s0 = 0.f, s1 = 0.f, s2 = 0.f;
    for (int k = lane; k < N_INP; k += 32) {
        float xv = x[k];
        s0 = fmaf(xv, sV[k * 3 + 0], s0);
        s1 = fmaf(xv, sV[k * 3 + 1], s1);
        s2 = fmaf(xv, sV[k * 3 + 2], s2);
    }
#pragma unroll
    for (int o = 16; o > 0; o >>= 1) {
        s0 += __shfl_down_sync(0xffffffffu, s0, o);
        s1 += __shfl_down_sync(0xffffffffu, s1, o);
        s2 += __shfl_down_sync(0xffffffffu, s2, o);
    }
    if (lane == 0)
        *(float4*)(out + (size_t)n * 4) = make_float4(s0 + b3[0], s1 + b3[1], s2 + b3[2], 0.f);
}

// ---------------- CSR build ----------------
__global__ void k_zero() {
    int i = blockIdx.x * blockDim.x + threadIdx.x;
    if (i < N_FILE) { d_deg[i] = 0; d_cur[i] = 0; }
}

__global__ void k_count(const int* __restrict__ dst, int E) {
    int i = blockIdx.x * blockDim.x + threadIdx.x;
    if (i < E) atomicAdd(&d_deg[dst[i]], 1);
}

__global__ void k_scan() {
    __shared__ int part[512];
    int t = threadIdx.x;
    const int per = (N_FILE + 511) / 512;
    int b = t * per;
    int sum = 0;
    for (int i = 0; i < per; i++) {
        int idx = b + i;
        if (idx < N_FILE) sum += d_deg[idx];
    }
    part[t] = sum;
    __syncthreads();
    for (int o = 1; o < 512; o <<= 1) {
        int v = (t >= o) ? part[t - o] : 0;
        __syncthreads();
        part[t] += v;
        __syncthreads();
    }
    int run = part[t] - sum;
    for (int i = 0; i < per; i++) {
        int idx = b + i;
        if (idx < N_FILE) {
            d_off[idx] = run;
            d_hasedge[idx] = d_deg[idx] ? 1.f : 0.f;
            run += d_deg[idx];
        }
    }
    if (t == 511) d_off[N_FILE] = run;
}

__global__ void k_scatter(const int* __restrict__ src, const int* __restrict__ dst, int E) {
    int i = blockIdx.x * blockDim.x + threadIdx.x;
    if (i >= E) return;
    int d = dst[i];
    int p = atomicAdd(&d_cur[d], 1);
    d_srcs[d_off[d] + p] = src[i];
}

// ---------------- per-dst softmax + fp16 embedding aggregation ----------------
#define GCAP 1024

__global__ __launch_bounds__(128)
void gat_aggregate(int dbase)
{
    int d = dbase + blockIdx.x;
    int t = threadIdx.x;
    int lane = t & 31, warp = t >> 5;
    int start = d_off[d], end = d_off[d + 1];
    int deg = end - start;
    bool cached = (deg <= GCAP);

    __shared__ int   sh_src[GCAP];
    __shared__ float sh_w[GCAP * 3];
    __shared__ float s_er[4], s_m[3], s_iz[3];
    __shared__ float red[4][3];

    if (t < 4) s_er[t] = d_er[(size_t)d * 4 + t];
    __syncthreads();
    float er0 = s_er[0], er1 = s_er[1], er2 = s_er[2];
    const float4* el4 = (const float4*)d_el;

    // pass 1: logits (+ cache) + max
    float m0 = -CUDART_INF_F, m1 = -CUDART_INF_F, m2 = -CUDART_INF_F;
    for (int e = start + t; e < end; e += 128) {
        int s = d_srcs[e];
        float4 L = el4[s];
        float l0 = lrelu(L.x + er0), l1 = lrelu(L.y + er1), l2 = lrelu(L.z + er2);
        if (cached) {
            int i = e - start;
            sh_src[i] = s;
            sh_w[i * 3 + 0] = l0; sh_w[i * 3 + 1] = l1; sh_w[i * 3 + 2] = l2;
        }
        m0 = fmaxf(m0, l0); m1 = fmaxf(m1, l1); m2 = fmaxf(m2, l2);
    }
#pragma unroll
    for (int o = 16; o > 0; o >>= 1) {
        m0 = fmaxf(m0, __shfl_xor_sync(0xffffffffu, m0, o));
        m1 = fmaxf(m1, __shfl_xor_sync(0xffffffffu, m1, o));
        m2 = fmaxf(m2, __shfl_xor_sync(0xffffffffu, m2, o));
    }
    if (lane == 0) { red[warp][0] = m0; red[warp][1] = m1; red[warp][2] = m2; }
    __syncthreads();
    if (t < 3) s_m[t] = fmaxf(fmaxf(red[0][t], red[1][t]), fmaxf(red[2][t], red[3][t]));
    __syncthreads();
    m0 = s_m[0]; m1 = s_m[1]; m2 = s_m[2];

    // pass 2: sum of exp
    float z0 = 0.f, z1 = 0.f, z2 = 0.f;
    for (int e = start + t; e < end; e += 128) {
        float l0, l1, l2;
        if (cached) {
            int i = e - start;
            l0 = sh_w[i * 3 + 0]; l1 = sh_w[i * 3 + 1]; l2 = sh_w[i * 3 + 2];
        } else {
            int s = d_srcs[e];
            float4 L = el4[s];
            l0 = lrelu(L.x + er0); l1 = lrelu(L.y + er1); l2 = lrelu(L.z + er2);
        }
        z0 += __expf(l0 - m0); z1 += __expf(l1 - m1); z2 += __expf(l2 - m2);
    }
#pragma unroll
    for (int o = 16; o > 0; o >>= 1) {
        z0 += __shfl_xor_sync(0xffffffffu, z0, o);
        z1 += __shfl_xor_sync(0xffffffffu, z1, o);
        z2 += __shfl_xor_sync(0xffffffffu, z2, o);
    }
    if (lane == 0) { red[warp][0] = z0; red[warp][1] = z1; red[warp][2] = z2; }
    __syncthreads();
    if (t < 3) {
        float z = red[0][t] + red[1][t] + red[2][t] + red[3][t];
        s_iz[t] = (z > 0.f) ? 1.f / z : 0.f;
    }
    __syncthreads();
    float iz0 = s_iz[0], iz1 = s_iz[1], iz2 = s_iz[2];

    if (cached) {
        for (int i = t; i < deg; i += 128) {
            sh_w[i * 3 + 0] = __expf(sh_w[i * 3 + 0] - m0) * iz0;
            sh_w[i * 3 + 1] = __expf(sh_w[i * 3 + 1] - m1) * iz1;
            sh_w[i * 3 + 2] = __expf(sh_w[i * 3 + 2] - m2) * iz2;
        }
    }
    __syncthreads();

    // pass 3: weighted aggregation of fp16 rows; thread t owns 4 columns
    float a00 = 0.f, a01 = 0.f, a02 = 0.f, a03 = 0.f;
    float a10 = 0.f, a11 = 0.f, a12 = 0.f, a13 = 0.f;
    float a20 = 0.f, a21 = 0.f, a22 = 0.f, a23 = 0.f;
    int c4 = t * 4;

#define GATHER_FMA(sidx, w0, w1, w2) do {                                      \
    uint2 _v = *(const uint2*)(d_embh + (size_t)(sidx) * N_INP + c4);          \
    float2 _f0 = __half22float2(*(__half2*)&_v.x);                             \
    float2 _f1 = __half22float2(*(__half2*)&_v.y);                             \
    a00 = fmaf(w0, _f0.x, a00); a01 = fmaf(w0, _f0.y, a01);                    \
    a02 = fmaf(w0, _f1.x, a02); a03 = fmaf(w0, _f1.y, a03);                    \
    a10 = fmaf(w1, _f0.x, a10); a11 = fmaf(w1, _f0.y, a11);                    \
    a12 = fmaf(w1, _f1.x, a12); a13 = fmaf(w1, _f1.y, a13);                    \
    a20 = fmaf(w2, _f0.x, a20); a21 = fmaf(w2, _f0.y, a21);                    \
    a22 = fmaf(w2, _f1.x, a22); a23 = fmaf(w2, _f1.y, a23);                    \
} while (0)

    if (cached) {
        int i = 0;
        for (; i + 1 < deg; i += 2) {
            int   sA_ = sh_src[i],       sB_ = sh_src[i + 1];
            float wA0 = sh_w[i * 3 + 0], wB0 = sh_w[i * 3 + 3];
            float wA1 = sh_w[i * 3 + 1], wB1 = sh_w[i * 3 + 4];
            float wA2 = sh_w[i * 3 + 2], wB2 = sh_w[i * 3 + 5];
            GATHER_FMA(sA_, wA0, wA1, wA2);
            GATHER_FMA(sB_, wB0, wB1, wB2);
        }
        if (i < deg) {
            int s = sh_src[i];
            GATHER_FMA(s, sh_w[i * 3 + 0], sh_w[i * 3 + 1], sh_w[i * 3 + 2]);
        }
    } else {
        for (int e = start; e < end; e++) {
            int s = d_srcs[e];
            float4 L = el4[s];
            float w0 = __expf(lrelu(L.x + er0) - m0) * iz0;
            float w1 = __expf(lrelu(L.y + er1) - m1) * iz1;
            float w2 = __expf(lrelu(L.z + er2) - m2) * iz2;
            GATHER_FMA(s, w0, w1, w2);
        }
    }

    __half* aout = d_aggh + (size_t)d * KAGG;
    __half2 o00 = __floats2half2_rn(a00, a01), o01 = __floats2half2_rn(a02, a03);
    __half2 o10 = __floats2half2_rn(a10, a11), o11 = __floats2half2_rn(a12, a13);
    __half2 o20 = __floats2half2_rn(a20, a21), o21 = __floats2half2_rn(a22, a23);
    uint2 w;
    w.x = *(uint32_t*)&o00; w.y = *(uint32_t*)&o01;
    *(uint2*)(aout + 0 * N_INP + c4) = w;
    w.x = *(uint32_t*)&o10; w.y = *(uint32_t*)&o11;
    *(uint2*)(aout + 1 * N_INP + c4) = w;
    w.x = *(uint32_t*)&o20; w.y = *(uint32_t*)&o21;
    *(uint2*)(aout + 2 * N_INP + c4) = w;
}

// ---------------- launch ----------------
extern "C" void kernel_launch(void* const* d_in, const int* in_sizes, int n_in,
                              void* d_out, int out_size)
{
    const float* emb_api  = (const float*)d_in[0];
    const float* emb_file = (const float*)d_in[1];
    const int*   src      = (const int*)d_in[3];
    const int*   dst      = (const int*)d_in[4];
    const float* Wapi     = (const float*)d_in[5];
    const float* bapi     = (const float*)d_in[6];
    const float* Wfile    = (const float*)d_in[7];
    const float* bfile    = (const float*)d_in[8];
    const float* Wsrc     = (const float*)d_in[9];
    const float* Wdst     = (const float*)d_in[10];
    const float* attn_l   = (const float*)d_in[11];
    const float* attn_r   = (const float*)d_in[12];
    const float* gat_bias = (const float*)d_in[13];
    const float* Whead    = (const float*)d_in[14];
    const float* bhead    = (const float*)d_in[15];
    float* out = (float*)d_out;

    const int E = in_sizes[3];

    float *p_Wcomb, *p_W2, *p_Vl, *p_Vr, *p_bl, *p_br, *p_bconst, *p_cbias,
          *p_el, *p_er, *p_hasedge, *p_bsrc;
    __half *p_W2Th, *p_aggh;
    cudaGetSymbolAddress((void**)&p_Wcomb,   d_Wcomb);
    cudaGetSymbolAddress((void**)&p_W2,      d_W2);
    cudaGetSymbolAddress((void**)&p_W2Th,    d_W2Th);
    cudaGetSymbolAddress((void**)&p_aggh,    d_aggh);
    cudaGetSymbolAddress((void**)&p_Vl,      d_Vl);
    cudaGetSymbolAddress((void**)&p_Vr,      d_Vr);
    cudaGetSymbolAddress((void**)&p_bl,      d_bl);
    cudaGetSymbolAddress((void**)&p_br,      d_br);
    cudaGetSymbolAddress((void**)&p_bconst,  d_bconst);
    cudaGetSymbolAddress((void**)&p_cbias,   d_cbias);
    cudaGetSymbolAddress((void**)&p_el,      d_el);
    cudaGetSymbolAddress((void**)&p_er,      d_er);
    cudaGetSymbolAddress((void**)&p_hasedge, d_hasedge);
    cudaGetSymbolAddress((void**)&p_bsrc,    d_bsrc);

    cudaFuncSetAttribute(gemm_mma, cudaFuncAttributeMaxDynamicSharedMemorySize, GEMM_SMEM_BYTES);

    static cudaStream_t s1 = nullptr, s2 = nullptr, s3 = nullptr;
    static cudaEvent_t ev0, ev_bsrc, ev_csr, ev_s2, ev_wcomb, ev_a0, ev_a1, ev_done;
    if (!s1) {
        cudaStreamCreateWithFlags(&s1, cudaStreamNonBlocking);
        cudaStreamCreateWithFlags(&s2, cudaStreamNonBlocking);
        cudaStreamCreateWithFlags(&s3, cudaStreamNonBlocking);
        cudaEventCreateWithFlags(&ev0,     cudaEventDisableTiming);
        cudaEventCreateWithFlags(&ev_bsrc, cudaEventDisableTiming);
        cudaEventCreateWithFlags(&ev_csr,  cudaEventDisableTiming);
        cudaEventCreateWithFlags(&ev_s2,   cudaEventDisableTiming);
        cudaEventCreateWithFlags(&ev_wcomb,cudaEventDisableTiming);
        cudaEventCreateWithFlags(&ev_a0,   cudaEventDisableTiming);
        cudaEventCreateWithFlags(&ev_a1,   cudaEventDisableTiming);
        cudaEventCreateWithFlags(&ev_done, cudaEventDisableTiming);
    }

    // fork
    cudaEventRecord(ev0, 0);
    cudaStreamWaitEvent(s1, ev0, 0);
    cudaStreamWaitEvent(s2, ev0, 0);
    cudaStreamWaitEvent(s3, ev0, 0);

    // ---- s1: emb fp16 conversion + CSR build ----
    k_emb2h <<<(N_API * N_INP / 8 + 255) / 256, 256, 0, s1>>>(emb_api);
    k_zero   <<<(N_FILE + 255) / 256, 256, 0, s1>>>();
    k_count  <<<(E + 255) / 256, 256, 0, s1>>>(dst, E);
    k_scan   <<<1, 512, 0, s1>>>();
    k_scatter<<<(E + 255) / 256, 256, 0, s1>>>(src, dst, E);
    cudaEventRecord(ev_csr, s1);

    // ---- default: api-side critical path ----
    gevm<<<HD / 64, 256>>>(bapi, Wsrc, p_bsrc, N_INP, HD, nullptr);
    cudaEventRecord(ev_bsrc, 0);
    sgemm<<<dim3(HD / BN, N_INP / BM, 1), 256>>>(
        Wapi, N_INP, Wsrc, HD, p_Wcomb, HD, N_INP, HD, N_INP, 0, 0, 0);
    cudaEventRecord(ev_wcomb, 0);
    k_Vl<<<192, 256>>>(attn_l);
    k_bl<<<1, 128>>>(attn_l);
    node_logits<<<(N_API + 7) / 8, 256>>>(emb_api, p_Vl, p_bl, p_el, N_API);

    // ---- s3: W2 branch (off critical path) ----
    cudaStreamWaitEvent(s3, ev_wcomb, 0);
    sgemm<<<dim3(N_OUT / BN, N_INP / BM, NH), 256, 0, s3>>>(
        p_Wcomb, HD, Whead, N_OUT, p_W2, N_OUT,
        N_INP, N_OUT, N_OUT,
        (long)N_OUT, (long)N_OUT * N_OUT, (long)N_INP * N_OUT);
    k_w2t<<<dim3(N_OUT / 32, KAGG / 32), dim3(32, 8), 0, s3>>>();

    // ---- s2: file-side precompute ----
    k_u<<<192, 256, 0, s2>>>(Wdst, attn_r);
    k_Vr<<<192, 256, 0, s2>>>(Wfile);
    k_br<<<1, 128, 0, s2>>>(bfile);
    gevm<<<N_OUT / 64, 256, 0, s2>>>(gat_bias, Whead, p_cbias, HD, N_OUT, bhead);
    cudaStreamWaitEvent(s2, ev_bsrc, 0);
    gevm<<<N_OUT / 64, 256, 0, s2>>>(p_bsrc, Whead, p_bconst, HD, N_OUT, nullptr);
    node_logits<<<(N_FILE + 7) / 8, 256, 0, s2>>>(emb_file, p_Vr, p_br, p_er, N_FILE);
    cudaEventRecord(ev_s2, s2);

    // ---- default: aggregation chunks (pipelined with gemm on s3) ----
    cudaStreamWaitEvent(0, ev_csr, 0);
    cudaStreamWaitEvent(0, ev_s2, 0);
    gat_aggregate<<<CH0_DST, 128>>>(0);
    cudaEventRecord(ev_a0, 0);
    gat_aggregate<<<CH1_DST, 128>>>(CH0_DST);
    cudaEventRecord(ev_a1, 0);

    // ---- s3: gemm chunks ----
    cudaStreamWaitEvent(s3, ev_csr, 0);
    cudaStreamWaitEvent(s3, ev_s2, 0);
    cudaStreamWaitEvent(s3, ev_a0, 0);
    gemm_mma<<<dim3(N_OUT / 128, CH0_BLOCKS), 256, GEMM_SMEM_BYTES, s3>>>(
        p_aggh, p_W2Th, out, p_cbias, p_bconst, p_hasedge, 0);
    cudaStreamWaitEvent(s3, ev_a1, 0);
    gemm_mma<<<dim3(N_OUT / 128, CH1_BLOCKS), 256, GEMM_SMEM_BYTES, s3>>>(
        p_aggh, p_W2Th, out, p_cbias, p_bconst, p_hasedge, CH0_BLOCKS);
    cudaEventRecord(ev_done, s3);

    // join
    cudaStreamWaitEvent(0, ev_done, 0);
}

// round 8
// speedup vs baseline: 4.9493x; 1.0098x over previous
#include <cuda_runtime.h>
#include <cuda_fp16.h>
#include <math_constants.h>
#include <cstdint>

// ---------------- problem constants ----------------
#define N_API   50000
#define N_FILE  20000
#define N_INP   512
#define N_OUT   256
#define NH      3
#define HD      768   // NH*N_OUT
#define KAGG    1536  // NH*N_INP
#define M_PAD   20096 // 157*128
#define NCHUNK  48    // KAGG/32 (k-chunk = 32 halfs)

// pipeline chunking: 157 row-blocks = 80 + 77
#define CH0_BLOCKS 80
#define CH1_BLOCKS 77
#define CH0_DST    (CH0_BLOCKS * 128)
#define CH1_DST    (N_FILE - CH0_DST)

#define SCAN_BLOCKS ((N_FILE + 511) / 512)   // 40

// ---------------- device scratch ----------------
__device__ float  d_Wcomb[N_INP * HD];
__device__ float  d_W2   [KAGG * N_OUT];
__device__ __half d_W2Th [N_OUT * KAGG];
__device__ __half d_embh [(size_t)N_API * N_INP];   // fp16 emb_api, 51.2 MB
__device__ __half d_aggh [(size_t)M_PAD * KAGG];    // fp16 agg (tail rows stay 0)
__device__ float  d_u    [N_INP * NH];
__device__ float  d_Vl   [N_INP * NH];
__device__ float  d_Vr   [N_INP * NH];
__device__ float  d_bsrc [HD];
__device__ float  d_bl   [NH];
__device__ float  d_br   [NH];
__device__ float  d_bconst[N_OUT];
__device__ float  d_cbias [N_OUT];
__device__ float  d_el   [N_API * 4];
__device__ float  d_er   [N_FILE * 4];
__device__ int    d_deg  [N_FILE];
__device__ int    d_cur  [N_FILE];
__device__ int    d_off  [N_FILE + 1];
__device__ int    d_bsum [SCAN_BLOCKS];
__device__ int    d_bbase[SCAN_BLOCKS];
__device__ float  d_hasedge[N_FILE];
__device__ int    d_srcs [262144];

// ---------------- helpers ----------------
__device__ __forceinline__ uint32_t smem_u32(const void* p) {
    uint32_t a;
    asm("{ .reg .u64 t; cvta.to.shared.u64 t, %1; cvt.u32.u64 %0, t; }" : "=r"(a) : "l"(p));
    return a;
}
__device__ __forceinline__ float lrelu(float v) { return v > 0.f ? v : 0.2f * v; }

#define CP_ASYNC16(dst, src) \
    asm volatile("cp.async.cg.shared.global [%0], [%1], 16;" :: "r"(dst), "l"(src) : "memory")
#define CP_COMMIT()  asm volatile("cp.async.commit_group;" ::: "memory")
#define CP_WAIT0()   asm volatile("cp.async.wait_group 0;" ::: "memory")
#define CP_WAIT1()   asm volatile("cp.async.wait_group 1;" ::: "memory")

__device__ __forceinline__ void mma_f16(float* c, const uint32_t* a, const uint32_t* b) {
    asm volatile(
        "mma.sync.aligned.m16n8k16.row.col.f32.f16.f16.f32 "
        "{%0,%1,%2,%3}, {%4,%5,%6,%7}, {%8,%9}, {%0,%1,%2,%3};"
        : "+f"(c[0]), "+f"(c[1]), "+f"(c[2]), "+f"(c[3])
        : "r"(a[0]), "r"(a[1]), "r"(a[2]), "r"(a[3]), "r"(b[0]), "r"(b[1]));
}

// ---------------- fp16 tensor-core GEMM (unchanged, proven) ----------------
#define LDPH   40
#define TILEH  (128 * LDPH)
#define GEMM_SMEM_BYTES (4 * TILEH * 2)

__global__ void __launch_bounds__(256, 2)
gemm_mma(const __half* __restrict__ A, const __half* __restrict__ B,
         float* __restrict__ C,
         const float* __restrict__ cbias,
         const float* __restrict__ bconst,
         const float* __restrict__ hasedge,
         int mb_base)
{
    extern __shared__ __half smh[];
    __half* As = smh;
    __half* Bs = smh + 2 * TILEH;

    const int tid  = threadIdx.x;
    const int wid  = tid >> 5, lane = tid & 31;
    const int wm   = wid & 1;
    const int wn   = wid >> 1;
    const int m0   = (mb_base + blockIdx.y) * 128;
    const int n0   = blockIdx.x * 128;

    float acc[4][4][4];
#pragma unroll
    for (int a = 0; a < 4; a++)
#pragma unroll
        for (int b = 0; b < 4; b++)
#pragma unroll
            for (int c = 0; c < 4; c++) acc[a][b][c] = 0.f;

#define LOAD_TILE(kt, s) do {                                                     \
    int _k0 = (kt) * 32;                                                          \
    _Pragma("unroll")                                                             \
    for (int _t = 0; _t < 2; _t++) {                                              \
        int _idx = tid + _t * 256;                                                \
        int _row = _idx >> 2, _seg = _idx & 3;                                    \
        const __half* _g = A + (size_t)(m0 + _row) * KAGG + _k0 + _seg * 8;       \
        CP_ASYNC16(smem_u32(As + (s) * TILEH + _row * LDPH + _seg * 8), _g);      \
    }                                                                             \
    _Pragma("unroll")                                                             \
    for (int _t = 0; _t < 2; _t++) {                                              \
        int _idx = tid + _t * 256;                                                \
        int _row = _idx >> 2, _seg = _idx & 3;                                    \
        const __half* _g = B + (size_t)(n0 + _row) * KAGG + _k0 + _seg * 8;       \
        CP_ASYNC16(smem_u32(Bs + (s) * TILEH + _row * LDPH + _seg * 8), _g);      \
    }                                                                             \
    CP_COMMIT();                                                                  \
} while (0)

    LOAD_TILE(0, 0);

    for (int kt = 0; kt < NCHUNK; kt++) {
        int s = kt & 1;
        if (kt + 1 < NCHUNK) { LOAD_TILE(kt + 1, s ^ 1); CP_WAIT1(); }
        else                 { CP_WAIT0(); }
        __syncthreads();

        const __half* a_base = As + s * TILEH + (wm * 64 + (lane >> 2)) * LDPH;
        const __half* b_base = Bs + s * TILEH + (wn * 32 + (lane >> 2)) * LDPH;
        const int kc = (lane & 3) * 2;

#pragma unroll
        for (int ks = 0; ks < 2; ks++) {
            int kk = ks * 16 + kc;
            uint32_t afr[4][4];
#pragma unroll
            for (int mi = 0; mi < 4; mi++) {
                const __half* ap = a_base + mi * 16 * LDPH;
                afr[mi][0] = *(const uint32_t*)(ap + kk);
                afr[mi][1] = *(const uint32_t*)(ap + 8 * LDPH + kk);
                afr[mi][2] = *(const uint32_t*)(ap + kk + 8);
                afr[mi][3] = *(const uint32_t*)(ap + 8 * LDPH + kk + 8);
            }
            uint32_t bfr[4][2];
#pragma unroll
            for (int ni = 0; ni < 4; ni++) {
                const __half* bp = b_base + ni * 8 * LDPH;
                bfr[ni][0] = *(const uint32_t*)(bp + kk);
                bfr[ni][1] = *(const uint32_t*)(bp + kk + 8);
            }
#pragma unroll
            for (int mi = 0; mi < 4; mi++)
#pragma unroll
                for (int ni = 0; ni < 4; ni++)
                    mma_f16(acc[mi][ni], afr[mi], bfr[ni]);
        }
        __syncthreads();
    }

#pragma unroll
    for (int mi = 0; mi < 4; mi++) {
        int rbase = m0 + wm * 64 + mi * 16 + (lane >> 2);
#pragma unroll
        for (int half_ = 0; half_ < 2; half_++) {
            int r = rbase + half_ * 8;
            if (r >= N_FILE) continue;
            float he = hasedge[r];
#pragma unroll
            for (int ni = 0; ni < 4; ni++) {
                int c0 = n0 + wn * 32 + ni * 8 + (lane & 3) * 2;
                float v0 = acc[mi][ni][half_ * 2 + 0] + cbias[c0]     + he * bconst[c0];
                float v1 = acc[mi][ni][half_ * 2 + 1] + cbias[c0 + 1] + he * bconst[c0 + 1];
                *(float2*)(C + (size_t)r * N_OUT + c0) = make_float2(v0, v1);
            }
        }
    }
}

// ---------------- fp32 SGEMM (precompute-sized, batched z) ----
#define BM 128
#define BN 128
#define BK 8
#define TM 8
#define TN 8

__global__ __launch_bounds__(256, 2)
void sgemm(const float* __restrict__ A, int lda,
           const float* __restrict__ B, int ldb,
           float* __restrict__ C, int ldc,
           int M, int N, int K,
           long sA, long sB, long sC)
{
    A += (long)blockIdx.z * sA;
    B += (long)blockIdx.z * sB;
    C += (long)blockIdx.z * sC;

    __shared__ float As[BK][BM];
    __shared__ float Bs[BK][BN];
    const int tid = threadIdx.x;
    const int bm  = blockIdx.y * BM;
    const int bn  = blockIdx.x * BN;

    const int aRow  = tid >> 1;
    const int aCol4 = (tid & 1) * 4;
    const int bRow  = tid >> 5;
    const int bCol4 = (tid & 31) * 4;
    const int ty = tid >> 4, tx = tid & 15;

    float acc[TM][TN];
#pragma unroll
    for (int i = 0; i < TM; i++)
#pragma unroll
        for (int j = 0; j < TN; j++) acc[i][j] = 0.f;

    for (int k0 = 0; k0 < K; k0 += BK) {
        float4 av;
        if (bm + aRow < M)
            av = *(const float4*)(A + (size_t)(bm + aRow) * lda + k0 + aCol4);
        else
            av = make_float4(0.f, 0.f, 0.f, 0.f);
        As[aCol4 + 0][aRow] = av.x;
        As[aCol4 + 1][aRow] = av.y;
        As[aCol4 + 2][aRow] = av.z;
        As[aCol4 + 3][aRow] = av.w;

        float4 bv = *(const float4*)(B + (size_t)(k0 + bRow) * ldb + bn + bCol4);
        *(float4*)(&Bs[bRow][bCol4]) = bv;

        __syncthreads();
#pragma unroll
        for (int k = 0; k < BK; k++) {
            float ra[TM], rb[TN];
#pragma unroll
            for (int i = 0; i < TM; i++) ra[i] = As[k][ty * TM + i];
#pragma unroll
            for (int j = 0; j < TN; j++) rb[j] = Bs[k][tx * TN + j];
#pragma unroll
            for (int i = 0; i < TM; i++)
#pragma unroll
                for (int j = 0; j < TN; j++)
                    acc[i][j] = fmaf(ra[i], rb[j], acc[i][j]);
        }
        __syncthreads();
    }

#pragma unroll
    for (int i = 0; i < TM; i++) {
        int row = bm + ty * TM + i;
        if (row >= M) break;
#pragma unroll
        for (int j = 0; j < TN; j += 4) {
            int col = bn + tx * TN + j;
            float4 v;
            v.x = acc[i][j];     v.y = acc[i][j + 1];
            v.z = acc[i][j + 2]; v.w = acc[i][j + 3];
            *(float4*)(C + (size_t)row * ldc + col) = v;
        }
    }
}

// ---------------- coalesced GEVM ----------
__global__ __launch_bounds__(256)
void gevm(const float* __restrict__ x, const float* __restrict__ W,
          float* __restrict__ y, int K, int N, const float* __restrict__ add)
{
    int c  = blockIdx.x * 64 + (threadIdx.x & 63);
    int ks = threadIdx.x >> 6;
    int kper = K >> 2;
    int k0 = ks * kper, k1 = k0 + kper;
    float s = 0.f;
    for (int k = k0; k < k1; k++) s = fmaf(x[k], W[(size_t)k * N + c], s);
    __shared__ float sm[4][64];
    sm[ks][threadIdx.x & 63] = s;
    __syncthreads();
    if (ks == 0) {
        int l = threadIdx.x & 63;
        float v = sm[0][l] + sm[1][l] + sm[2][l] + sm[3][l];
        if (add) v += add[c];
        y[c] = v;
    }
}

// ---------------- warp-per-output dot kernels ----------
__device__ __forceinline__ float warp_sum(float s) {
#pragma unroll
    for (int o = 16; o > 0; o >>= 1) s += __shfl_down_sync(0xffffffffu, s, o);
    return s;
}

__global__ __launch_bounds__(256)
void k_u(const float* __restrict__ Wdst, const float* __restrict__ attn_r) {
    int wg = blockIdx.x * 8 + (threadIdx.x >> 5);
    int lane = threadIdx.x & 31;
    int k = wg / 3, h = wg - k * 3;
    const float* row = Wdst + (size_t)k * HD + h * N_OUT;
    const float* v   = attn_r + h * N_OUT;
    float s = 0.f;
#pragma unroll
    for (int j = lane; j < N_OUT; j += 32) s = fmaf(row[j], v[j], s);
    s = warp_sum(s);
    if (lane == 0) d_u[k * 3 + h] = s;
}

__global__ __launch_bounds__(256)
void k_Vl(const float* __restrict__ attn_l) {
    int wg = blockIdx.x * 8 + (threadIdx.x >> 5);
    int lane = threadIdx.x & 31;
    int k = wg / 3, h = wg - k * 3;
    const float* row = d_Wcomb + (size_t)k * HD + h * N_OUT;
    const float* v   = attn_l + h * N_OUT;
    float s = 0.f;
#pragma unroll
    for (int j = lane; j < N_OUT; j += 32) s = fmaf(row[j], v[j], s);
    s = warp_sum(s);
    if (lane == 0) d_Vl[k * 3 + h] = s;
}

__global__ __launch_bounds__(256)
void k_Vr(const float* __restrict__ Wfile) {
    int wg = blockIdx.x * 8 + (threadIdx.x >> 5);
    int lane = threadIdx.x & 31;
    int k = wg / 3, h = wg - k * 3;
    const float* row = Wfile + (size_t)k * N_INP;
    float s = 0.f;
#pragma unroll
    for (int c = lane; c < N_INP; c += 32) s = fmaf(row[c], d_u[c * 3 + h], s);
    s = warp_sum(s);
    if (lane == 0) d_Vr[k * 3 + h] = s;
}

__global__ void k_bl(const float* __restrict__ attn_l) {
    int w = threadIdx.x >> 5, lane = threadIdx.x & 31;
    if (w >= NH) return;
    float s = 0.f;
    for (int j = lane; j < N_OUT; j += 32)
        s = fmaf(d_bsrc[w * N_OUT + j], attn_l[w * N_OUT + j], s);
    s = warp_sum(s);
    if (lane == 0) d_bl[w] = s;
}

__global__ void k_br(const float* __restrict__ bfile) {
    int w = threadIdx.x >> 5, lane = threadIdx.x & 31;
    if (w >= NH) return;
    float s = 0.f;
    for (int c = lane; c < N_INP; c += 32)
        s = fmaf(bfile[c], d_u[c * 3 + w], s);
    s = warp_sum(s);
    if (lane == 0) d_br[w] = s;
}

// ---------------- transpose + fp16 round ----
__global__ void k_w2t() {
    __shared__ float tile[32][33];
    int nb = blockIdx.x * 32, kb = blockIdx.y * 32;
    int tx = threadIdx.x, ty = threadIdx.y;
#pragma unroll
    for (int j = 0; j < 32; j += 8)
        tile[ty + j][tx] = d_W2[(size_t)(kb + ty + j) * N_OUT + nb + tx];
    __syncthreads();
#pragma unroll
    for (int j = 0; j < 32; j += 8)
        d_W2Th[(size_t)(nb + ty + j) * KAGG + kb + tx] = __float2half_rn(tile[tx][ty + j]);
}

// ---------------- emb_api -> fp16 ----------------
__global__ __launch_bounds__(256)
void k_emb2h(const float* __restrict__ emb) {
    size_t i = (size_t)blockIdx.x * 256 + threadIdx.x;
    const float4* src = (const float4*)(emb) + i * 2;
    float4 f0 = src[0], f1 = src[1];
    __half2 h0 = __floats2half2_rn(f0.x, f0.y);
    __half2 h1 = __floats2half2_rn(f0.z, f0.w);
    __half2 h2 = __floats2half2_rn(f1.x, f1.y);
    __half2 h3 = __floats2half2_rn(f1.z, f1.w);
    uint4 v;
    v.x = *(uint32_t*)&h0; v.y = *(uint32_t*)&h1;
    v.z = *(uint32_t*)&h2; v.w = *(uint32_t*)&h3;
    *((uint4*)d_embh + i) = v;
}

// ---------------- node logits ----------------
__global__ void node_logits(const float* __restrict__ X,
                            const float* __restrict__ V,
                            const float* __restrict__ b3,
                            float* __restrict__ out, int Nn)
{
    __shared__ float sV[N_INP * NH];
    int t = threadIdx.x;
    for (int i = t; i < N_INP * NH; i += blockDim.x) sV[i] = V[i];
    __syncthreads();
    int warp = t >> 5, lane = t & 31;
    int n = blockIdx.x * (blockDim.x >> 5) + warp;
    if (n >= Nn) return;
    const float* x = X + (size_t)n * N_INP;
    float s0 = 0.f, s1 = 0.f, s2 = 0.f;
    for (int k = lane; k < N_INP; k += 32) {
        float xv = x[k];
        s0 = fmaf(xv, sV[k * 3 + 0], s0);
        s1 = fmaf(xv, sV[k * 3 + 1], s1);
        s2 = fmaf(xv, sV[k * 3 + 2], s2);
    }
#pragma unroll
    for (int o = 16; o > 0; o >>= 1) {
        s0 += __shfl_down_sync(0xffffffffu, s0, o);
        s1 += __shfl_down_sync(0xffffffffu, s1, o);
        s2 += __shfl_down_sync(0xffffffffu, s2, o);
    }
    if (lane == 0)
        *(float4*)(out + (size_t)n * 4) = make_float4(s0 + b3[0], s1 + b3[1], s2 + b3[2], 0.f);
}

// ---------------- CSR build (multi-block scan) ----------------
__global__ void k_zero() {
    int i = blockIdx.x * blockDim.x + threadIdx.x;
    if (i < N_FILE) { d_deg[i] = 0; d_cur[i] = 0; }
}

__global__ void k_count(const int* __restrict__ dst, int E) {
    int i = blockIdx.x * blockDim.x + threadIdx.x;
    if (i < E) atomicAdd(&d_deg[dst[i]], 1);
}

// phase 1: per-block exclusive scan of 512-chunks, local offsets + block sums
__global__ void k_scan1() {
    __shared__ int sh[512];
    int i = blockIdx.x * 512 + threadIdx.x;
    int v = (i < N_FILE) ? d_deg[i] : 0;
    sh[threadIdx.x] = v;
    __syncthreads();
    for (int o = 1; o < 512; o <<= 1) {
        int t = (threadIdx.x >= o) ? sh[threadIdx.x - o] : 0;
        __syncthreads();
        sh[threadIdx.x] += t;
        __syncthreads();
    }
    if (i < N_FILE) d_off[i] = sh[threadIdx.x] - v;    // local exclusive
    if (threadIdx.x == 511) d_bsum[blockIdx.x] = sh[511];
}

// phase 2: serial scan of 40 block sums (single thread — 40 adds)
__global__ void k_scan2() {
    if (threadIdx.x == 0) {
        int run = 0;
#pragma unroll
        for (int b = 0; b < SCAN_BLOCKS; b++) { d_bbase[b] = run; run += d_bsum[b]; }
        d_off[N_FILE] = run;
    }
}

// phase 3: add block bases + hasedge flags
__global__ void k_scan3() {
    int i = blockIdx.x * 512 + threadIdx.x;
    if (i < N_FILE) {
        d_off[i] += d_bbase[blockIdx.x];
        d_hasedge[i] = d_deg[i] ? 1.f : 0.f;
    }
}

__global__ void k_scatter(const int* __restrict__ src, const int* __restrict__ dst, int E) {
    int i = blockIdx.x * blockDim.x + threadIdx.x;
    if (i >= E) return;
    int d = dst[i];
    int p = atomicAdd(&d_cur[d], 1);
    d_srcs[d_off[d] + p] = src[i];
}

// ---------------- per-dst softmax + fp16 embedding aggregation ----------------
#define GCAP 1024

__global__ __launch_bounds__(128)
void gat_aggregate(int dbase)
{
    int d = dbase + blockIdx.x;
    int t = threadIdx.x;
    int lane = t & 31, warp = t >> 5;
    int start = d_off[d], end = d_off[d + 1];
    int deg = end - start;
    bool cached = (deg <= GCAP);

    __shared__ int   sh_src[GCAP];
    __shared__ float sh_w[GCAP * 3];
    __shared__ float s_er[4], s_m[3], s_iz[3];
    __shared__ float red[4][3];

    if (t < 4) s_er[t] = d_er[(size_t)d * 4 + t];
    __syncthreads();
    float er0 = s_er[0], er1 = s_er[1], er2 = s_er[2];
    const float4* el4 = (const float4*)d_el;

    float m0 = -CUDART_INF_F, m1 = -CUDART_INF_F, m2 = -CUDART_INF_F;
    for (int e = start + t; e < end; e += 128) {
        int s = d_srcs[e];
        float4 L = el4[s];
        float l0 = lrelu(L.x + er0), l1 = lrelu(L.y + er1), l2 = lrelu(L.z + er2);
        if (cached) {
            int i = e - start;
            sh_src[i] = s;
            sh_w[i * 3 + 0] = l0; sh_w[i * 3 + 1] = l1; sh_w[i * 3 + 2] = l2;
        }
        m0 = fmaxf(m0, l0); m1 = fmaxf(m1, l1); m2 = fmaxf(m2, l2);
    }
#pragma unroll
    for (int o = 16; o > 0; o >>= 1) {
        m0 = fmaxf(m0, __shfl_xor_sync(0xffffffffu, m0, o));
        m1 = fmaxf(m1, __shfl_xor_sync(0xffffffffu, m1, o));
        m2 = fmaxf(m2, __shfl_xor_sync(0xffffffffu, m2, o));
    }
    if (lane == 0) { red[warp][0] = m0; red[warp][1] = m1; red[warp][2] = m2; }
    __syncthreads();
    if (t < 3) s_m[t] = fmaxf(fmaxf(red[0][t], red[1][t]), fmaxf(red[2][t], red[3][t]));
    __syncthreads();
    m0 = s_m[0]; m1 = s_m[1]; m2 = s_m[2];

    float z0 = 0.f, z1 = 0.f, z2 = 0.f;
    for (int e = start + t; e < end; e += 128) {
        float l0, l1, l2;
        if (cached) {
            int i = e - start;
            l0 = sh_w[i * 3 + 0]; l1 = sh_w[i * 3 + 1]; l2 = sh_w[i * 3 + 2];
        } else {
            int s = d_srcs[e];
            float4 L = el4[s];
            l0 = lrelu(L.x + er0); l1 = lrelu(L.y + er1); l2 = lrelu(L.z + er2);
        }
        z0 += __expf(l0 - m0); z1 += __expf(l1 - m1); z2 += __expf(l2 - m2);
    }
#pragma unroll
    for (int o = 16; o > 0; o >>= 1) {
        z0 += __shfl_xor_sync(0xffffffffu, z0, o);
        z1 += __shfl_xor_sync(0xffffffffu, z1, o);
        z2 += __shfl_xor_sync(0xffffffffu, z2, o);
    }
    if (lane == 0) { red[warp][0] = z0; red[warp][1] = z1; red[warp][2] = z2; }
    __syncthreads();
    if (t < 3) {
        float z = red[0][t] + red[1][t] + red[2][t] + red[3][t];
        s_iz[t] = (z > 0.f) ? 1.f / z : 0.f;
    }
    __syncthreads();
    float iz0 = s_iz[0], iz1 = s_iz[1], iz2 = s_iz[2];

    if (cached) {
        for (int i = t; i < deg; i += 128) {
            sh_w[i * 3 + 0] = __expf(sh_w[i * 3 + 0] - m0) * iz0;
            sh_w[i * 3 + 1] = __expf(sh_w[i * 3 + 1] - m1) * iz1;
            sh_w[i * 3 + 2] = __expf(sh_w[i * 3 + 2] - m2) * iz2;
        }
    }
    __syncthreads();

    float a00 = 0.f, a01 = 0.f, a02 = 0.f, a03 = 0.f;
    float a10 = 0.f, a11 = 0.f, a12 = 0.f, a13 = 0.f;
    float a20 = 0.f, a21 = 0.f, a22 = 0.f, a23 = 0.f;
    int c4 = t * 4;

#define GATHER_FMA(sidx, w0, w1, w2) do {                                      \
    uint2 _v = *(const uint2*)(d_embh + (size_t)(sidx) * N_INP + c4);          \
    float2 _f0 = __half22float2(*(__half2*)&_v.x);                             \
    float2 _f1 = __half22float2(*(__half2*)&_v.y);                             \
    a00 = fmaf(w0, _f0.x, a00); a01 = fmaf(w0, _f0.y, a01);                    \
    a02 = fmaf(w0, _f1.x, a02); a03 = fmaf(w0, _f1.y, a03);                    \
    a10 = fmaf(w1, _f0.x, a10); a11 = fmaf(w1, _f0.y, a11);                    \
    a12 = fmaf(w1, _f1.x, a12); a13 = fmaf(w1, _f1.y, a13);                    \
    a20 = fmaf(w2, _f0.x, a20); a21 = fmaf(w2, _f0.y, a21);                    \
    a22 = fmaf(w2, _f1.x, a22); a23 = fmaf(w2, _f1.y, a23);                    \
} while (0)

    if (cached) {
        int i = 0;
        for (; i + 1 < deg; i += 2) {
            int   sA_ = sh_src[i],       sB_ = sh_src[i + 1];
            float wA0 = sh_w[i * 3 + 0], wB0 = sh_w[i * 3 + 3];
            float wA1 = sh_w[i * 3 + 1], wB1 = sh_w[i * 3 + 4];
            float wA2 = sh_w[i * 3 + 2], wB2 = sh_w[i * 3 + 5];
            GATHER_FMA(sA_, wA0, wA1, wA2);
            GATHER_FMA(sB_, wB0, wB1, wB2);
        }
        if (i < deg) {
            int s = sh_src[i];
            GATHER_FMA(s, sh_w[i * 3 + 0], sh_w[i * 3 + 1], sh_w[i * 3 + 2]);
        }
    } else {
        for (int e = start; e < end; e++) {
            int s = d_srcs[e];
            float4 L = el4[s];
            float w0 = __expf(lrelu(L.x + er0) - m0) * iz0;
            float w1 = __expf(lrelu(L.y + er1) - m1) * iz1;
            float w2 = __expf(lrelu(L.z + er2) - m2) * iz2;
            GATHER_FMA(s, w0, w1, w2);
        }
    }

    __half* aout = d_aggh + (size_t)d * KAGG;
    __half2 o00 = __floats2half2_rn(a00, a01), o01 = __floats2half2_rn(a02, a03);
    __half2 o10 = __floats2half2_rn(a10, a11), o11 = __floats2half2_rn(a12, a13);
    __half2 o20 = __floats2half2_rn(a20, a21), o21 = __floats2half2_rn(a22, a23);
    uint2 w;
    w.x = *(uint32_t*)&o00; w.y = *(uint32_t*)&o01;
    *(uint2*)(aout + 0 * N_INP + c4) = w;
    w.x = *(uint32_t*)&o10; w.y = *(uint32_t*)&o11;
    *(uint2*)(aout + 1 * N_INP + c4) = w;
    w.x = *(uint32_t*)&o20; w.y = *(uint32_t*)&o21;
    *(uint2*)(aout + 2 * N_INP + c4) = w;
}

// ---------------- launch ----------------
extern "C" void kernel_launch(void* const* d_in, const int* in_sizes, int n_in,
                              void* d_out, int out_size)
{
    const float* emb_api  = (const float*)d_in[0];
    const float* emb_file = (const float*)d_in[1];
    const int*   src      = (const int*)d_in[3];
    const int*   dst      = (const int*)d_in[4];
    const float* Wapi     = (const float*)d_in[5];
    const float* bapi     = (const float*)d_in[6];
    const float* Wfile    = (const float*)d_in[7];
    const float* bfile    = (const float*)d_in[8];
    const float* Wsrc     = (const float*)d_in[9];
    const float* Wdst     = (const float*)d_in[10];
    const float* attn_l   = (const float*)d_in[11];
    const float* attn_r   = (const float*)d_in[12];
    const float* gat_bias = (const float*)d_in[13];
    const float* Whead    = (const float*)d_in[14];
    const float* bhead    = (const float*)d_in[15];
    float* out = (float*)d_out;

    const int E = in_sizes[3];

    float *p_Wcomb, *p_W2, *p_Vl, *p_Vr, *p_bl, *p_br, *p_bconst, *p_cbias,
          *p_el, *p_er, *p_hasedge, *p_bsrc;
    __half *p_W2Th, *p_aggh;
    cudaGetSymbolAddress((void**)&p_Wcomb,   d_Wcomb);
    cudaGetSymbolAddress((void**)&p_W2,      d_W2);
    cudaGetSymbolAddress((void**)&p_W2Th,    d_W2Th);
    cudaGetSymbolAddress((void**)&p_aggh,    d_aggh);
    cudaGetSymbolAddress((void**)&p_Vl,      d_Vl);
    cudaGetSymbolAddress((void**)&p_Vr,      d_Vr);
    cudaGetSymbolAddress((void**)&p_bl,      d_bl);
    cudaGetSymbolAddress((void**)&p_br,      d_br);
    cudaGetSymbolAddress((void**)&p_bconst,  d_bconst);
    cudaGetSymbolAddress((void**)&p_cbias,   d_cbias);
    cudaGetSymbolAddress((void**)&p_el,      d_el);
    cudaGetSymbolAddress((void**)&p_er,      d_er);
    cudaGetSymbolAddress((void**)&p_hasedge, d_hasedge);
    cudaGetSymbolAddress((void**)&p_bsrc,    d_bsrc);

    cudaFuncSetAttribute(gemm_mma, cudaFuncAttributeMaxDynamicSharedMemorySize, GEMM_SMEM_BYTES);

    static cudaStream_t s1 = nullptr, s2 = nullptr, s3 = nullptr;
    static cudaEvent_t ev0, ev_bsrc, ev_csr, ev_s2, ev_wcomb, ev_emb, ev_a0, ev_a1, ev_done;
    if (!s1) {
        cudaStreamCreateWithFlags(&s1, cudaStreamNonBlocking);
        cudaStreamCreateWithFlags(&s2, cudaStreamNonBlocking);
        cudaStreamCreateWithFlags(&s3, cudaStreamNonBlocking);
        cudaEventCreateWithFlags(&ev0,     cudaEventDisableTiming);
        cudaEventCreateWithFlags(&ev_bsrc, cudaEventDisableTiming);
        cudaEventCreateWithFlags(&ev_csr,  cudaEventDisableTiming);
        cudaEventCreateWithFlags(&ev_s2,   cudaEventDisableTiming);
        cudaEventCreateWithFlags(&ev_wcomb,cudaEventDisableTiming);
        cudaEventCreateWithFlags(&ev_emb,  cudaEventDisableTiming);
        cudaEventCreateWithFlags(&ev_a0,   cudaEventDisableTiming);
        cudaEventCreateWithFlags(&ev_a1,   cudaEventDisableTiming);
        cudaEventCreateWithFlags(&ev_done, cudaEventDisableTiming);
    }

    // fork
    cudaEventRecord(ev0, 0);
    cudaStreamWaitEvent(s1, ev0, 0);
    cudaStreamWaitEvent(s2, ev0, 0);
    cudaStreamWaitEvent(s3, ev0, 0);

    // ---- s1: CSR build only (scan is now multi-block) ----
    k_zero   <<<(N_FILE + 255) / 256, 256, 0, s1>>>();
    k_count  <<<(E + 255) / 256, 256, 0, s1>>>(dst, E);
    k_scan1  <<<SCAN_BLOCKS, 512, 0, s1>>>();
    k_scan2  <<<1, 32, 0, s1>>>();
    k_scan3  <<<SCAN_BLOCKS, 512, 0, s1>>>();
    k_scatter<<<(E + 255) / 256, 256, 0, s1>>>(src, dst, E);
    cudaEventRecord(ev_csr, s1);

    // ---- s3: emb fp16 conversion first (independent), then W2 branch ----
    k_emb2h<<<(N_API * N_INP / 8 + 255) / 256, 256, 0, s3>>>(emb_api);
    cudaEventRecord(ev_emb, s3);

    // ---- default: api-side critical path ----
    gevm<<<HD / 64, 256>>>(bapi, Wsrc, p_bsrc, N_INP, HD, nullptr);
    cudaEventRecord(ev_bsrc, 0);
    sgemm<<<dim3(HD / BN, N_INP / BM, 1), 256>>>(
        Wapi, N_INP, Wsrc, HD, p_Wcomb, HD, N_INP, HD, N_INP, 0, 0, 0);
    cudaEventRecord(ev_wcomb, 0);
    k_Vl<<<192, 256>>>(attn_l);
    k_bl<<<1, 128>>>(attn_l);
    node_logits<<<(N_API + 7) / 8, 256>>>(emb_api, p_Vl, p_bl, p_el, N_API);

    // ---- s3: W2 branch ----
    cudaStreamWaitEvent(s3, ev_wcomb, 0);
    sgemm<<<dim3(N_OUT / BN, N_INP / BM, NH), 256, 0, s3>>>(
        p_Wcomb, HD, Whead, N_OUT, p_W2, N_OUT,
        N_INP, N_OUT, N_OUT,
        (long)N_OUT, (long)N_OUT * N_OUT, (long)N_INP * N_OUT);
    k_w2t<<<dim3(N_OUT / 32, KAGG / 32), dim3(32, 8), 0, s3>>>();

    // ---- s2: file-side precompute ----
    k_u<<<192, 256, 0, s2>>>(Wdst, attn_r);
    k_Vr<<<192, 256, 0, s2>>>(Wfile);
    k_br<<<1, 128, 0, s2>>>(bfile);
    gevm<<<N_OUT / 64, 256, 0, s2>>>(gat_bias, Whead, p_cbias, HD, N_OUT, bhead);
    cudaStreamWaitEvent(s2, ev_bsrc, 0);
    gevm<<<N_OUT / 64, 256, 0, s2>>>(p_bsrc, Whead, p_bconst, HD, N_OUT, nullptr);
    node_logits<<<(N_FILE + 7) / 8, 256, 0, s2>>>(emb_file, p_Vr, p_br, p_er, N_FILE);
    cudaEventRecord(ev_s2, s2);

    // ---- default: aggregation chunks (pipelined with gemm on s3) ----
    cudaStreamWaitEvent(0, ev_csr, 0);
    cudaStreamWaitEvent(0, ev_s2, 0);
    cudaStreamWaitEvent(0, ev_emb, 0);
    gat_aggregate<<<CH0_DST, 128>>>(0);
    cudaEventRecord(ev_a0, 0);
    gat_aggregate<<<CH1_DST, 128>>>(CH0_DST);
    cudaEventRecord(ev_a1, 0);

    // ---- s3: gemm chunks ----
    cudaStreamWaitEvent(s3, ev_csr, 0);
    cudaStreamWaitEvent(s3, ev_s2, 0);
    cudaStreamWaitEvent(s3, ev_a0, 0);
    gemm_mma<<<dim3(N_OUT / 128, CH0_BLOCKS), 256, GEMM_SMEM_BYTES, s3>>>(
        p_aggh, p_W2Th, out, p_cbias, p_bconst, p_hasedge, 0);
    cudaStreamWaitEvent(s3, ev_a1, 0);
    gemm_mma<<<dim3(N_OUT / 128, CH1_BLOCKS), 256, GEMM_SMEM_BYTES, s3>>>(
        p_aggh, p_W2Th, out, p_cbias, p_bconst, p_hasedge, CH0_BLOCKS);
    cudaEventRecord(ev_done, s3);

    // join
    cudaStreamWaitEvent(0, ev_done, 0);
}

// round 9
// speedup vs baseline: 5.2391x; 1.0585x over previous
#include <cuda_runtime.h>
#include <cuda_fp16.h>
#include <math_constants.h>
#include <cstdint>

// ---------------- problem constants ----------------
#define N_API   50000
#define N_FILE  20000
#define N_INP   512
#define N_OUT   256
#define NH      3
#define HD      768   // NH*N_OUT
#define KAGG    1536  // NH*N_INP
#define M_PAD   20096 // 157*128
#define NCHUNK  48    // KAGG/32 (k-chunk = 32 halfs)

// pipeline chunking: 157 row-blocks = 80 + 77
#define CH0_BLOCKS 80
#define CH1_BLOCKS 77
#define CH0_DST    (CH0_BLOCKS * 128)
#define CH1_DST    (N_FILE - CH0_DST)

#define SCAN_BLOCKS ((N_FILE + 511) / 512)   // 40

// ---------------- device scratch ----------------
__device__ float  d_Wcomb[N_INP * HD];
__device__ float  d_W2   [KAGG * N_OUT];
__device__ __half d_W2Th [N_OUT * KAGG];
__device__ __half d_embh [(size_t)N_API * N_INP];   // fp16 emb_api
__device__ __half d_aggh [(size_t)M_PAD * KAGG];    // fp16 agg (tail rows stay 0)
__device__ float  d_u    [N_INP * NH];
__device__ float  d_vli  [N_INP * NH];              // Wsrc_h @ attn_l_h
__device__ float  d_Vl   [N_INP * NH];
__device__ float  d_Vr   [N_INP * NH];
__device__ float  d_bsrc [HD];
__device__ float  d_bl   [NH];
__device__ float  d_br   [NH];
__device__ float  d_bconst[N_OUT];
__device__ float  d_cbias [N_OUT];
__device__ float  d_el   [N_API * 4];
__device__ float  d_er   [N_FILE * 4];
__device__ int    d_deg  [N_FILE];
__device__ int    d_cur  [N_FILE];
__device__ int    d_off  [N_FILE + 1];
__device__ int    d_bsum [SCAN_BLOCKS];
__device__ int    d_bbase[SCAN_BLOCKS];
__device__ float  d_hasedge[N_FILE];
__device__ int    d_srcs [262144];

// ---------------- helpers ----------------
__device__ __forceinline__ uint32_t smem_u32(const void* p) {
    uint32_t a;
    asm("{ .reg .u64 t; cvta.to.shared.u64 t, %1; cvt.u32.u64 %0, t; }" : "=r"(a) : "l"(p));
    return a;
}
__device__ __forceinline__ float lrelu(float v) { return v > 0.f ? v : 0.2f * v; }

#define CP_ASYNC16(dst, src) \
    asm volatile("cp.async.cg.shared.global [%0], [%1], 16;" :: "r"(dst), "l"(src) : "memory")
#define CP_COMMIT()  asm volatile("cp.async.commit_group;" ::: "memory")
#define CP_WAIT0()   asm volatile("cp.async.wait_group 0;" ::: "memory")
#define CP_WAIT1()   asm volatile("cp.async.wait_group 1;" ::: "memory")

__device__ __forceinline__ void mma_f16(float* c, const uint32_t* a, const uint32_t* b) {
    asm volatile(
        "mma.sync.aligned.m16n8k16.row.col.f32.f16.f16.f32 "
        "{%0,%1,%2,%3}, {%4,%5,%6,%7}, {%8,%9}, {%0,%1,%2,%3};"
        : "+f"(c[0]), "+f"(c[1]), "+f"(c[2]), "+f"(c[3])
        : "r"(a[0]), "r"(a[1]), "r"(a[2]), "r"(a[3]), "r"(b[0]), "r"(b[1]));
}

// ---------------- fp16 tensor-core GEMM (unchanged, proven) ----------------
#define LDPH   40
#define TILEH  (128 * LDPH)
#define GEMM_SMEM_BYTES (4 * TILEH * 2)

__global__ void __launch_bounds__(256, 2)
gemm_mma(const __half* __restrict__ A, const __half* __restrict__ B,
         float* __restrict__ C,
         const float* __restrict__ cbias,
         const float* __restrict__ bconst,
         const float* __restrict__ hasedge,
         int mb_base)
{
    extern __shared__ __half smh[];
    __half* As = smh;
    __half* Bs = smh + 2 * TILEH;

    const int tid  = threadIdx.x;
    const int wid  = tid >> 5, lane = tid & 31;
    const int wm   = wid & 1;
    const int wn   = wid >> 1;
    const int m0   = (mb_base + blockIdx.y) * 128;
    const int n0   = blockIdx.x * 128;

    float acc[4][4][4];
#pragma unroll
    for (int a = 0; a < 4; a++)
#pragma unroll
        for (int b = 0; b < 4; b++)
#pragma unroll
            for (int c = 0; c < 4; c++) acc[a][b][c] = 0.f;

#define LOAD_TILE(kt, s) do {                                                     \
    int _k0 = (kt) * 32;                                                          \
    _Pragma("unroll")                                                             \
    for (int _t = 0; _t < 2; _t++) {                                              \
        int _idx = tid + _t * 256;                                                \
        int _row = _idx >> 2, _seg = _idx & 3;                                    \
        const __half* _g = A + (size_t)(m0 + _row) * KAGG + _k0 + _seg * 8;       \
        CP_ASYNC16(smem_u32(As + (s) * TILEH + _row * LDPH + _seg * 8), _g);      \
    }                                                                             \
    _Pragma("unroll")                                                             \
    for (int _t = 0; _t < 2; _t++) {                                              \
        int _idx = tid + _t * 256;                                                \
        int _row = _idx >> 2, _seg = _idx & 3;                                    \
        const __half* _g = B + (size_t)(n0 + _row) * KAGG + _k0 + _seg * 8;       \
        CP_ASYNC16(smem_u32(Bs + (s) * TILEH + _row * LDPH + _seg * 8), _g);      \
    }                                                                             \
    CP_COMMIT();                                                                  \
} while (0)

    LOAD_TILE(0, 0);

    for (int kt = 0; kt < NCHUNK; kt++) {
        int s = kt & 1;
        if (kt + 1 < NCHUNK) { LOAD_TILE(kt + 1, s ^ 1); CP_WAIT1(); }
        else                 { CP_WAIT0(); }
        __syncthreads();

        const __half* a_base = As + s * TILEH + (wm * 64 + (lane >> 2)) * LDPH;
        const __half* b_base = Bs + s * TILEH + (wn * 32 + (lane >> 2)) * LDPH;
        const int kc = (lane & 3) * 2;

#pragma unroll
        for (int ks = 0; ks < 2; ks++) {
            int kk = ks * 16 + kc;
            uint32_t afr[4][4];
#pragma unroll
            for (int mi = 0; mi < 4; mi++) {
                const __half* ap = a_base + mi * 16 * LDPH;
                afr[mi][0] = *(const uint32_t*)(ap + kk);
                afr[mi][1] = *(const uint32_t*)(ap + 8 * LDPH + kk);
                afr[mi][2] = *(const uint32_t*)(ap + kk + 8);
                afr[mi][3] = *(const uint32_t*)(ap + 8 * LDPH + kk + 8);
            }
            uint32_t bfr[4][2];
#pragma unroll
            for (int ni = 0; ni < 4; ni++) {
                const __half* bp = b_base + ni * 8 * LDPH;
                bfr[ni][0] = *(const uint32_t*)(bp + kk);
                bfr[ni][1] = *(const uint32_t*)(bp + kk + 8);
            }
#pragma unroll
            for (int mi = 0; mi < 4; mi++)
#pragma unroll
                for (int ni = 0; ni < 4; ni++)
                    mma_f16(acc[mi][ni], afr[mi], bfr[ni]);
        }
        __syncthreads();
    }

#pragma unroll
    for (int mi = 0; mi < 4; mi++) {
        int rbase = m0 + wm * 64 + mi * 16 + (lane >> 2);
#pragma unroll
        for (int half_ = 0; half_ < 2; half_++) {
            int r = rbase + half_ * 8;
            if (r >= N_FILE) continue;
            float he = hasedge[r];
#pragma unroll
            for (int ni = 0; ni < 4; ni++) {
                int c0 = n0 + wn * 32 + ni * 8 + (lane & 3) * 2;
                float v0 = acc[mi][ni][half_ * 2 + 0] + cbias[c0]     + he * bconst[c0];
                float v1 = acc[mi][ni][half_ * 2 + 1] + cbias[c0 + 1] + he * bconst[c0 + 1];
                *(float2*)(C + (size_t)r * N_OUT + c0) = make_float2(v0, v1);
            }
        }
    }
}

// ---------------- fp32 SGEMM (precompute-sized, batched z) ----
#define BM 128
#define BN 128
#define BK 8
#define TM 8
#define TN 8

__global__ __launch_bounds__(256, 2)
void sgemm(const float* __restrict__ A, int lda,
           const float* __restrict__ B, int ldb,
           float* __restrict__ C, int ldc,
           int M, int N, int K,
           long sA, long sB, long sC)
{
    A += (long)blockIdx.z * sA;
    B += (long)blockIdx.z * sB;
    C += (long)blockIdx.z * sC;

    __shared__ float As[BK][BM];
    __shared__ float Bs[BK][BN];
    const int tid = threadIdx.x;
    const int bm  = blockIdx.y * BM;
    const int bn  = blockIdx.x * BN;

    const int aRow  = tid >> 1;
    const int aCol4 = (tid & 1) * 4;
    const int bRow  = tid >> 5;
    const int bCol4 = (tid & 31) * 4;
    const int ty = tid >> 4, tx = tid & 15;

    float acc[TM][TN];
#pragma unroll
    for (int i = 0; i < TM; i++)
#pragma unroll
        for (int j = 0; j < TN; j++) acc[i][j] = 0.f;

    for (int k0 = 0; k0 < K; k0 += BK) {
        float4 av;
        if (bm + aRow < M)
            av = *(const float4*)(A + (size_t)(bm + aRow) * lda + k0 + aCol4);
        else
            av = make_float4(0.f, 0.f, 0.f, 0.f);
        As[aCol4 + 0][aRow] = av.x;
        As[aCol4 + 1][aRow] = av.y;
        As[aCol4 + 2][aRow] = av.z;
        As[aCol4 + 3][aRow] = av.w;

        float4 bv = *(const float4*)(B + (size_t)(k0 + bRow) * ldb + bn + bCol4);
        *(float4*)(&Bs[bRow][bCol4]) = bv;

        __syncthreads();
#pragma unroll
        for (int k = 0; k < BK; k++) {
            float ra[TM], rb[TN];
#pragma unroll
            for (int i = 0; i < TM; i++) ra[i] = As[k][ty * TM + i];
#pragma unroll
            for (int j = 0; j < TN; j++) rb[j] = Bs[k][tx * TN + j];
#pragma unroll
            for (int i = 0; i < TM; i++)
#pragma unroll
                for (int j = 0; j < TN; j++)
                    acc[i][j] = fmaf(ra[i], rb[j], acc[i][j]);
        }
        __syncthreads();
    }

#pragma unroll
    for (int i = 0; i < TM; i++) {
        int row = bm + ty * TM + i;
        if (row >= M) break;
#pragma unroll
        for (int j = 0; j < TN; j += 4) {
            int col = bn + tx * TN + j;
            float4 v;
            v.x = acc[i][j];     v.y = acc[i][j + 1];
            v.z = acc[i][j + 2]; v.w = acc[i][j + 3];
            *(float4*)(C + (size_t)row * ldc + col) = v;
        }
    }
}

// ---------------- coalesced GEVM ----------
__global__ __launch_bounds__(256)
void gevm(const float* __restrict__ x, const float* __restrict__ W,
          float* __restrict__ y, int K, int N, const float* __restrict__ add)
{
    int c  = blockIdx.x * 64 + (threadIdx.x & 63);
    int ks = threadIdx.x >> 6;
    int kper = K >> 2;
    int k0 = ks * kper, k1 = k0 + kper;
    float s = 0.f;
    for (int k = k0; k < k1; k++) s = fmaf(x[k], W[(size_t)k * N + c], s);
    __shared__ float sm[4][64];
    sm[ks][threadIdx.x & 63] = s;
    __syncthreads();
    if (ks == 0) {
        int l = threadIdx.x & 63;
        float v = sm[0][l] + sm[1][l] + sm[2][l] + sm[3][l];
        if (add) v += add[c];
        y[c] = v;
    }
}

// ---------------- generic warp-per-output dot kernels ----------
__device__ __forceinline__ float warp_sum(float s) {
#pragma unroll
    for (int o = 16; o > 0; o >>= 1) s += __shfl_down_sync(0xffffffffu, s, o);
    return s;
}

// out[k*3+h] = sum_j W[k*HD + h*256 + j] * v[h*256 + j]   (k<512, h<3; 1536 warps)
__global__ __launch_bounds__(256)
void k_hdot(const float* __restrict__ W, const float* __restrict__ v,
            float* __restrict__ out) {
    int wg = blockIdx.x * 8 + (threadIdx.x >> 5);
    int lane = threadIdx.x & 31;
    int k = wg / 3, h = wg - k * 3;
    const float* row = W + (size_t)k * HD + h * N_OUT;
    const float* vv  = v + h * N_OUT;
    float s = 0.f;
#pragma unroll
    for (int j = lane; j < N_OUT; j += 32) s = fmaf(row[j], vv[j], s);
    s = warp_sum(s);
    if (lane == 0) out[k * 3 + h] = s;
}

// out[k*3+h] = sum_c M[k*512 + c] * vec[c*3 + h]   (1536 warps)
__global__ __launch_bounds__(256)
void k_mat3(const float* __restrict__ M, const float* __restrict__ vec,
            float* __restrict__ out) {
    int wg = blockIdx.x * 8 + (threadIdx.x >> 5);
    int lane = threadIdx.x & 31;
    int k = wg / 3, h = wg - k * 3;
    const float* row = M + (size_t)k * N_INP;
    float s = 0.f;
#pragma unroll
    for (int c = lane; c < N_INP; c += 32) s = fmaf(row[c], vec[c * 3 + h], s);
    s = warp_sum(s);
    if (lane == 0) out[k * 3 + h] = s;
}

// out3[h] = sum_c b[c] * vec[c*3+h]   (3 warps)
__global__ void k_b3(const float* __restrict__ b, const float* __restrict__ vec,
                     float* __restrict__ out3) {
    int w = threadIdx.x >> 5, lane = threadIdx.x & 31;
    if (w >= NH) return;
    float s = 0.f;
    for (int c = lane; c < N_INP; c += 32)
        s = fmaf(b[c], vec[c * 3 + w], s);
    s = warp_sum(s);
    if (lane == 0) out3[w] = s;
}

// ---------------- transpose + fp16 round ----
__global__ void k_w2t() {
    __shared__ float tile[32][33];
    int nb = blockIdx.x * 32, kb = blockIdx.y * 32;
    int tx = threadIdx.x, ty = threadIdx.y;
#pragma unroll
    for (int j = 0; j < 32; j += 8)
        tile[ty + j][tx] = d_W2[(size_t)(kb + ty + j) * N_OUT + nb + tx];
    __syncthreads();
#pragma unroll
    for (int j = 0; j < 32; j += 8)
        d_W2Th[(size_t)(nb + ty + j) * KAGG + kb + tx] = __float2half_rn(tile[tx][ty + j]);
}

// ---------------- emb_api -> fp16 ----------------
__global__ __launch_bounds__(256)
void k_emb2h(const float* __restrict__ emb) {
    size_t i = (size_t)blockIdx.x * 256 + threadIdx.x;
    const float4* src = (const float4*)(emb) + i * 2;
    float4 f0 = src[0], f1 = src[1];
    __half2 h0 = __floats2half2_rn(f0.x, f0.y);
    __half2 h1 = __floats2half2_rn(f0.z, f0.w);
    __half2 h2 = __floats2half2_rn(f1.x, f1.y);
    __half2 h3 = __floats2half2_rn(f1.z, f1.w);
    uint4 v;
    v.x = *(uint32_t*)&h0; v.y = *(uint32_t*)&h1;
    v.z = *(uint32_t*)&h2; v.w = *(uint32_t*)&h3;
    *((uint4*)d_embh + i) = v;
}

// ---------------- node logits ----------------
__global__ void node_logits(const float* __restrict__ X,
                            const float* __restrict__ V,
                            const float* __restrict__ b3,
                            float* __restrict__ out, int Nn)
{
    __shared__ float sV[N_INP * NH];
    int t = threadIdx.x;
    for (int i = t; i < N_INP * NH; i += blockDim.x) sV[i] = V[i];
    __syncthreads();
    int warp = t >> 5, lane = t & 31;
    int n = blockIdx.x * (blockDim.x >> 5) + warp;
    if (n >= Nn) return;
    const float* x = X + (size_t)n * N_INP;
    float s0 = 0.f, s1 = 0.f, s2 = 0.f;
    for (int k = lane; k < N_INP; k += 32) {
        float xv = x[k];
        s0 = fmaf(xv, sV[k * 3 + 0], s0);
        s1 = fmaf(xv, sV[k * 3 + 1], s1);
        s2 = fmaf(xv, sV[k * 3 + 2], s2);
    }
#pragma unroll
    for (int o = 16; o > 0; o >>= 1) {
        s0 += __shfl_down_sync(0xffffffffu, s0, o);
        s1 += __shfl_down_sync(0xffffffffu, s1, o);
        s2 += __shfl_down_sync(0xffffffffu, s2, o);
    }
    if (lane == 0)
        *(float4*)(out + (size_t)n * 4) = make_float4(s0 + b3[0], s1 + b3[1], s2 + b3[2], 0.f);
}

// ---------------- CSR build (multi-block scan) ----------------
__global__ void k_zero() {
    int i = blockIdx.x * blockDim.x + threadIdx.x;
    if (i < N_FILE) { d_deg[i] = 0; d_cur[i] = 0; }
}

__global__ void k_count(const int* __restrict__ dst, int E) {
    int i = blockIdx.x * blockDim.x + threadIdx.x;
    if (i < E) atomicAdd(&d_deg[dst[i]], 1);
}

__global__ void k_scan1() {
    __shared__ int sh[512];
    int i = blockIdx.x * 512 + threadIdx.x;
    int v = (i < N_FILE) ? d_deg[i] : 0;
    sh[threadIdx.x] = v;
    __syncthreads();
    for (int o = 1; o < 512; o <<= 1) {
        int t = (threadIdx.x >= o) ? sh[threadIdx.x - o] : 0;
        __syncthreads();
        sh[threadIdx.x] += t;
        __syncthreads();
    }
    if (i < N_FILE) d_off[i] = sh[threadIdx.x] - v;
    if (threadIdx.x == 511) d_bsum[blockIdx.x] = sh[511];
}

__global__ void k_scan2() {
    if (threadIdx.x == 0) {
        int run = 0;
#pragma unroll
        for (int b = 0; b < SCAN_BLOCKS; b++) { d_bbase[b] = run; run += d_bsum[b]; }
        d_off[N_FILE] = run;
    }
}

__global__ void k_scan3() {
    int i = blockIdx.x * 512 + threadIdx.x;
    if (i < N_FILE) {
        d_off[i] += d_bbase[blockIdx.x];
        d_hasedge[i] = d_deg[i] ? 1.f : 0.f;
    }
}

__global__ void k_scatter(const int* __restrict__ src, const int* __restrict__ dst, int E) {
    int i = blockIdx.x * blockDim.x + threadIdx.x;
    if (i >= E) return;
    int d = dst[i];
    int p = atomicAdd(&d_cur[d], 1);
    d_srcs[d_off[d] + p] = src[i];
}

// ---------------- per-dst softmax + fp16 embedding aggregation ----------------
#define GCAP 1024

__global__ __launch_bounds__(128)
void gat_aggregate(int dbase)
{
    int d = dbase + blockIdx.x;
    int t = threadIdx.x;
    int lane = t & 31, warp = t >> 5;
    int start = d_off[d], end = d_off[d + 1];
    int deg = end - start;
    bool cached = (deg <= GCAP);

    __shared__ int   sh_src[GCAP];
    __shared__ float sh_w[GCAP * 3];
    __shared__ float s_er[4], s_m[3], s_iz[3];
    __shared__ float red[4][3];

    if (t < 4) s_er[t] = d_er[(size_t)d * 4 + t];
    __syncthreads();
    float er0 = s_er[0], er1 = s_er[1], er2 = s_er[2];
    const float4* el4 = (const float4*)d_el;

    float m0 = -CUDART_INF_F, m1 = -CUDART_INF_F, m2 = -CUDART_INF_F;
    for (int e = start + t; e < end; e += 128) {
        int s = d_srcs[e];
        float4 L = el4[s];
        float l0 = lrelu(L.x + er0), l1 = lrelu(L.y + er1), l2 = lrelu(L.z + er2);
        if (cached) {
            int i = e - start;
            sh_src[i] = s;
            sh_w[i * 3 + 0] = l0; sh_w[i * 3 + 1] = l1; sh_w[i * 3 + 2] = l2;
        }
        m0 = fmaxf(m0, l0); m1 = fmaxf(m1, l1); m2 = fmaxf(m2, l2);
    }
#pragma unroll
    for (int o = 16; o > 0; o >>= 1) {
        m0 = fmaxf(m0, __shfl_xor_sync(0xffffffffu, m0, o));
        m1 = fmaxf(m1, __shfl_xor_sync(0xffffffffu, m1, o));
        m2 = fmaxf(m2, __shfl_xor_sync(0xffffffffu, m2, o));
    }
    if (lane == 0) { red[warp][0] = m0; red[warp][1] = m1; red[warp][2] = m2; }
    __syncthreads();
    if (t < 3) s_m[t] = fmaxf(fmaxf(red[0][t], red[1][t]), fmaxf(red[2][t], red[3][t]));
    __syncthreads();
    m0 = s_m[0]; m1 = s_m[1]; m2 = s_m[2];

    float z0 = 0.f, z1 = 0.f, z2 = 0.f;
    for (int e = start + t; e < end; e += 128) {
        float l0, l1, l2;
        if (cached) {
            int i = e - start;
            l0 = sh_w[i * 3 + 0]; l1 = sh_w[i * 3 + 1]; l2 = sh_w[i * 3 + 2];
        } else {
            int s = d_srcs[e];
            float4 L = el4[s];
            l0 = lrelu(L.x + er0); l1 = lrelu(L.y + er1); l2 = lrelu(L.z + er2);
        }
        z0 += __expf(l0 - m0); z1 += __expf(l1 - m1); z2 += __expf(l2 - m2);
    }
#pragma unroll
    for (int o = 16; o > 0; o >>= 1) {
        z0 += __shfl_xor_sync(0xffffffffu, z0, o);
        z1 += __shfl_xor_sync(0xffffffffu, z1, o);
        z2 += __shfl_xor_sync(0xffffffffu, z2, o);
    }
    if (lane == 0) { red[warp][0] = z0; red[warp][1] = z1; red[warp][2] = z2; }
    __syncthreads();
    if (t < 3) {
        float z = red[0][t] + red[1][t] + red[2][t] + red[3][t];
        s_iz[t] = (z > 0.f) ? 1.f / z : 0.f;
    }
    __syncthreads();
    float iz0 = s_iz[0], iz1 = s_iz[1], iz2 = s_iz[2];

    if (cached) {
        for (int i = t; i < deg; i += 128) {
            sh_w[i * 3 + 0] = __expf(sh_w[i * 3 + 0] - m0) * iz0;
            sh_w[i * 3 + 1] = __expf(sh_w[i * 3 + 1] - m1) * iz1;
            sh_w[i * 3 + 2] = __expf(sh_w[i * 3 + 2] - m2) * iz2;
        }
    }
    __syncthreads();

    float a00 = 0.f, a01 = 0.f, a02 = 0.f, a03 = 0.f;
    float a10 = 0.f, a11 = 0.f, a12 = 0.f, a13 = 0.f;
    float a20 = 0.f, a21 = 0.f, a22 = 0.f, a23 = 0.f;
    int c4 = t * 4;

#define GATHER_FMA(sidx, w0, w1, w2) do {                                      \
    uint2 _v = *(const uint2*)(d_embh + (size_t)(sidx) * N_INP + c4);          \
    float2 _f0 = __half22float2(*(__half2*)&_v.x);                             \
    float2 _f1 = __half22float2(*(__half2*)&_v.y);                             \
    a00 = fmaf(w0, _f0.x, a00); a01 = fmaf(w0, _f0.y, a01);                    \
    a02 = fmaf(w0, _f1.x, a02); a03 = fmaf(w0, _f1.y, a03);                    \
    a10 = fmaf(w1, _f0.x, a10); a11 = fmaf(w1, _f0.y, a11);                    \
    a12 = fmaf(w1, _f1.x, a12); a13 = fmaf(w1, _f1.y, a13);                    \
    a20 = fmaf(w2, _f0.x, a20); a21 = fmaf(w2, _f0.y, a21);                    \
    a22 = fmaf(w2, _f1.x, a22); a23 = fmaf(w2, _f1.y, a23);                    \
} while (0)

    if (cached) {
        int i = 0;
        for (; i + 1 < deg; i += 2) {
            int   sA_ = sh_src[i],       sB_ = sh_src[i + 1];
            float wA0 = sh_w[i * 3 + 0], wB0 = sh_w[i * 3 + 3];
            float wA1 = sh_w[i * 3 + 1], wB1 = sh_w[i * 3 + 4];
            float wA2 = sh_w[i * 3 + 2], wB2 = sh_w[i * 3 + 5];
            GATHER_FMA(sA_, wA0, wA1, wA2);
            GATHER_FMA(sB_, wB0, wB1, wB2);
        }
        if (i < deg) {
            int s = sh_src[i];
            GATHER_FMA(s, sh_w[i * 3 + 0], sh_w[i * 3 + 1], sh_w[i * 3 + 2]);
        }
    } else {
        for (int e = start; e < end; e++) {
            int s = d_srcs[e];
            float4 L = el4[s];
            float w0 = __expf(lrelu(L.x + er0) - m0) * iz0;
            float w1 = __expf(lrelu(L.y + er1) - m1) * iz1;
            float w2 = __expf(lrelu(L.z + er2) - m2) * iz2;
            GATHER_FMA(s, w0, w1, w2);
        }
    }

    __half* aout = d_aggh + (size_t)d * KAGG;
    __half2 o00 = __floats2half2_rn(a00, a01), o01 = __floats2half2_rn(a02, a03);
    __half2 o10 = __floats2half2_rn(a10, a11), o11 = __floats2half2_rn(a12, a13);
    __half2 o20 = __floats2half2_rn(a20, a21), o21 = __floats2half2_rn(a22, a23);
    uint2 w;
    w.x = *(uint32_t*)&o00; w.y = *(uint32_t*)&o01;
    *(uint2*)(aout + 0 * N_INP + c4) = w;
    w.x = *(uint32_t*)&o10; w.y = *(uint32_t*)&o11;
    *(uint2*)(aout + 1 * N_INP + c4) = w;
    w.x = *(uint32_t*)&o20; w.y = *(uint32_t*)&o21;
    *(uint2*)(aout + 2 * N_INP + c4) = w;
}

// ---------------- launch ----------------
extern "C" void kernel_launch(void* const* d_in, const int* in_sizes, int n_in,
                              void* d_out, int out_size)
{
    const float* emb_api  = (const float*)d_in[0];
    const float* emb_file = (const float*)d_in[1];
    const int*   src      = (const int*)d_in[3];
    const int*   dst      = (const int*)d_in[4];
    const float* Wapi     = (const float*)d_in[5];
    const float* bapi     = (const float*)d_in[6];
    const float* Wfile    = (const float*)d_in[7];
    const float* bfile    = (const float*)d_in[8];
    const float* Wsrc     = (const float*)d_in[9];
    const float* Wdst     = (const float*)d_in[10];
    const float* attn_l   = (const float*)d_in[11];
    const float* attn_r   = (const float*)d_in[12];
    const float* gat_bias = (const float*)d_in[13];
    const float* Whead    = (const float*)d_in[14];
    const float* bhead    = (const float*)d_in[15];
    float* out = (float*)d_out;

    const int E = in_sizes[3];

    float *p_Wcomb, *p_W2, *p_u, *p_vli, *p_Vl, *p_Vr, *p_bl, *p_br, *p_bconst,
          *p_cbias, *p_el, *p_er, *p_hasedge, *p_bsrc;
    __half *p_W2Th, *p_aggh;
    cudaGetSymbolAddress((void**)&p_Wcomb,   d_Wcomb);
    cudaGetSymbolAddress((void**)&p_W2,      d_W2);
    cudaGetSymbolAddress((void**)&p_W2Th,    d_W2Th);
    cudaGetSymbolAddress((void**)&p_aggh,    d_aggh);
    cudaGetSymbolAddress((void**)&p_u,       d_u);
    cudaGetSymbolAddress((void**)&p_vli,     d_vli);
    cudaGetSymbolAddress((void**)&p_Vl,      d_Vl);
    cudaGetSymbolAddress((void**)&p_Vr,      d_Vr);
    cudaGetSymbolAddress((void**)&p_bl,      d_bl);
    cudaGetSymbolAddress((void**)&p_br,      d_br);
    cudaGetSymbolAddress((void**)&p_bconst,  d_bconst);
    cudaGetSymbolAddress((void**)&p_cbias,   d_cbias);
    cudaGetSymbolAddress((void**)&p_el,      d_el);
    cudaGetSymbolAddress((void**)&p_er,      d_er);
    cudaGetSymbolAddress((void**)&p_hasedge, d_hasedge);
    cudaGetSymbolAddress((void**)&p_bsrc,    d_bsrc);

    cudaFuncSetAttribute(gemm_mma, cudaFuncAttributeMaxDynamicSharedMemorySize, GEMM_SMEM_BYTES);

    static cudaStream_t s1 = nullptr, s2 = nullptr, s3 = nullptr;
    static cudaEvent_t ev0, ev_csr, ev_s2, ev_emb, ev_a0, ev_a1, ev_done;
    if (!s1) {
        cudaStreamCreateWithFlags(&s1, cudaStreamNonBlocking);
        cudaStreamCreateWithFlags(&s2, cudaStreamNonBlocking);
        cudaStreamCreateWithFlags(&s3, cudaStreamNonBlocking);
        cudaEventCreateWithFlags(&ev0,     cudaEventDisableTiming);
        cudaEventCreateWithFlags(&ev_csr,  cudaEventDisableTiming);
        cudaEventCreateWithFlags(&ev_s2,   cudaEventDisableTiming);
        cudaEventCreateWithFlags(&ev_emb,  cudaEventDisableTiming);
        cudaEventCreateWithFlags(&ev_a0,   cudaEventDisableTiming);
        cudaEventCreateWithFlags(&ev_a1,   cudaEventDisableTiming);
        cudaEventCreateWithFlags(&ev_done, cudaEventDisableTiming);
    }

    // fork
    cudaEventRecord(ev0, 0);
    cudaStreamWaitEvent(s1, ev0, 0);
    cudaStreamWaitEvent(s2, ev0, 0);
    cudaStreamWaitEvent(s3, ev0, 0);

    // ---- s1: CSR build ----
    k_zero   <<<(N_FILE + 255) / 256, 256, 0, s1>>>();
    k_count  <<<(E + 255) / 256, 256, 0, s1>>>(dst, E);
    k_scan1  <<<SCAN_BLOCKS, 512, 0, s1>>>();
    k_scan2  <<<1, 32, 0, s1>>>();
    k_scan3  <<<SCAN_BLOCKS, 512, 0, s1>>>();
    k_scatter<<<(E + 255) / 256, 256, 0, s1>>>(src, dst, E);
    cudaEventRecord(ev_csr, s1);

    // ---- default: api-side logit path (Wcomb no longer on this path!) ----
    k_hdot<<<192, 256>>>(Wsrc, attn_l, p_vli);      // vli = Wsrc_h @ attn_l_h
    k_mat3<<<192, 256>>>(Wapi, p_vli, p_Vl);        // Vl  = Wapi @ vli
    k_b3<<<1, 128>>>(bapi, p_vli, p_bl);            // bl  = bapi . vli
    node_logits<<<(N_API + 7) / 8, 256>>>(emb_api, p_Vl, p_bl, p_el, N_API);

    // ---- s3: emb fp16 conversion, then Wcomb -> W2 -> w2t (fully off-path) ----
    k_emb2h<<<(N_API * N_INP / 8 + 255) / 256, 256, 0, s3>>>(emb_api);
    cudaEventRecord(ev_emb, s3);
    sgemm<<<dim3(HD / BN, N_INP / BM, 1), 256, 0, s3>>>(
        Wapi, N_INP, Wsrc, HD, p_Wcomb, HD, N_INP, HD, N_INP, 0, 0, 0);
    sgemm<<<dim3(N_OUT / BN, N_INP / BM, NH), 256, 0, s3>>>(
        p_Wcomb, HD, Whead, N_OUT, p_W2, N_OUT,
        N_INP, N_OUT, N_OUT,
        (long)N_OUT, (long)N_OUT * N_OUT, (long)N_INP * N_OUT);
    k_w2t<<<dim3(N_OUT / 32, KAGG / 32), dim3(32, 8), 0, s3>>>();

    // ---- s2: file-side precompute + gemm epilogue constants ----
    k_hdot<<<192, 256, 0, s2>>>(Wdst, attn_r, p_u); // u = Wdst_h @ attn_r_h
    k_mat3<<<192, 256, 0, s2>>>(Wfile, p_u, p_Vr);  // Vr = Wfile @ u
    k_b3<<<1, 128, 0, s2>>>(bfile, p_u, p_br);      // br = bfile . u
    node_logits<<<(N_FILE + 7) / 8, 256, 0, s2>>>(emb_file, p_Vr, p_br, p_er, N_FILE);
    gevm<<<HD / 64, 256, 0, s2>>>(bapi, Wsrc, p_bsrc, N_INP, HD, nullptr);
    gevm<<<N_OUT / 64, 256, 0, s2>>>(gat_bias, Whead, p_cbias, HD, N_OUT, bhead);
    gevm<<<N_OUT / 64, 256, 0, s2>>>(p_bsrc, Whead, p_bconst, HD, N_OUT, nullptr);
    cudaEventRecord(ev_s2, s2);

    // ---- default: aggregation chunks ----
    cudaStreamWaitEvent(0, ev_csr, 0);
    cudaStreamWaitEvent(0, ev_s2, 0);
    cudaStreamWaitEvent(0, ev_emb, 0);
    gat_aggregate<<<CH0_DST, 128>>>(0);
    cudaEventRecord(ev_a0, 0);
    gat_aggregate<<<CH1_DST, 128>>>(CH0_DST);
    cudaEventRecord(ev_a1, 0);

    // ---- s3: gemm chunks (W2Th ready well before ev_a0) ----
    cudaStreamWaitEvent(s3, ev_csr, 0);
    cudaStreamWaitEvent(s3, ev_s2, 0);
    cudaStreamWaitEvent(s3, ev_a0, 0);
    gemm_mma<<<dim3(N_OUT / 128, CH0_BLOCKS), 256, GEMM_SMEM_BYTES, s3>>>(
        p_aggh, p_W2Th, out, p_cbias, p_bconst, p_hasedge, 0);
    cudaStreamWaitEvent(s3, ev_a1, 0);
    gemm_mma<<<dim3(N_OUT / 128, CH1_BLOCKS), 256, GEMM_SMEM_BYTES, s3>>>(
        p_aggh, p_W2Th, out, p_cbias, p_bconst, p_hasedge, CH0_BLOCKS);
    cudaEventRecord(ev_done, s3);

    // join
    cudaStreamWaitEvent(0, ev_done, 0);
}

// round 10
// speedup vs baseline: 6.1982x; 1.1831x over previous
#include <cuda_runtime.h>
#include <cuda_fp16.h>
#include <math_constants.h>
#include <cstdint>

// ---------------- problem constants ----------------
#define N_API   50000
#define N_FILE  20000
#define N_INP   512
#define N_OUT   256
#define NH      3
#define HD      768   // NH*N_OUT
#define KAGG    1536  // NH*N_INP
#define M_PAD   20096 // 157*128
#define NCHUNK  48    // KAGG/32 (k-chunk = 32 halfs)

// pipeline chunking: 157 row-blocks = 80 + 77
#define CH0_BLOCKS 80
#define CH1_BLOCKS 77
#define CH0_DST    (CH0_BLOCKS * 128)
#define CH1_DST    (N_FILE - CH0_DST)

#define SCAN_BLOCKS ((N_FILE + 511) / 512)   // 40

// ---------------- device scratch ----------------
__device__ float  d_Wcomb[N_INP * HD];
__device__ float  d_W2   [KAGG * N_OUT];
__device__ __half d_W2Th [N_OUT * KAGG];
__device__ __half d_embh [(size_t)N_API * N_INP];   // fp16 emb_api
__device__ __half d_aggh [(size_t)M_PAD * KAGG];    // fp16 agg (tail rows stay 0)
__device__ float  d_u    [N_INP * NH];
__device__ float  d_vli  [N_INP * NH];
__device__ float  d_Vl   [N_INP * NH];
__device__ float  d_Vr   [N_INP * NH];
__device__ float  d_bsrc [HD];
__device__ float  d_bl   [NH];
__device__ float  d_br   [NH];
__device__ float  d_bconst[N_OUT];
__device__ float  d_cbias [N_OUT];
__device__ float  d_el   [N_API * 4];
__device__ float  d_er   [N_FILE * 4];
__device__ int    d_deg  [N_FILE];
__device__ int    d_cur  [N_FILE];
__device__ int    d_off  [N_FILE + 1];
__device__ int    d_bsum [SCAN_BLOCKS];
__device__ int    d_bbase[SCAN_BLOCKS];
__device__ float  d_hasedge[N_FILE];
__device__ int    d_srcs [262144];

// ---------------- helpers ----------------
__device__ __forceinline__ uint32_t smem_u32(const void* p) {
    uint32_t a;
    asm("{ .reg .u64 t; cvta.to.shared.u64 t, %1; cvt.u32.u64 %0, t; }" : "=r"(a) : "l"(p));
    return a;
}
__device__ __forceinline__ float lrelu(float v) { return v > 0.f ? v : 0.2f * v; }

#define CP_ASYNC16(dst, src) \
    asm volatile("cp.async.cg.shared.global [%0], [%1], 16;" :: "r"(dst), "l"(src) : "memory")
#define CP_COMMIT()  asm volatile("cp.async.commit_group;" ::: "memory")
#define CP_WAIT0()   asm volatile("cp.async.wait_group 0;" ::: "memory")
#define CP_WAIT1()   asm volatile("cp.async.wait_group 1;" ::: "memory")

#define LDSM_X4(r0, r1, r2, r3, addr) \
    asm volatile("ldmatrix.sync.aligned.m8n8.x4.shared.b16 {%0,%1,%2,%3}, [%4];" \
                 : "=r"(r0), "=r"(r1), "=r"(r2), "=r"(r3) : "r"(addr))

__device__ __forceinline__ void mma_f16(float* c, const uint32_t* a, const uint32_t* b) {
    asm volatile(
        "mma.sync.aligned.m16n8k16.row.col.f32.f16.f16.f32 "
        "{%0,%1,%2,%3}, {%4,%5,%6,%7}, {%8,%9}, {%0,%1,%2,%3};"
        : "+f"(c[0]), "+f"(c[1]), "+f"(c[2]), "+f"(c[3])
        : "r"(a[0]), "r"(a[1]), "r"(a[2]), "r"(a[3]), "r"(b[0]), "r"(b[1]));
}

// ---------------- fp16 tensor-core GEMM with ldmatrix fragments ----------------
#define LDPH   40
#define TILEH  (128 * LDPH)
#define GEMM_SMEM_BYTES (4 * TILEH * 2)

__global__ void __launch_bounds__(256, 2)
gemm_mma(const __half* __restrict__ A, const __half* __restrict__ B,
         float* __restrict__ C,
         const float* __restrict__ cbias,
         const float* __restrict__ bconst,
         const float* __restrict__ hasedge,
         int mb_base)
{
    extern __shared__ __half smh[];
    __half* As = smh;
    __half* Bs = smh + 2 * TILEH;

    const int tid  = threadIdx.x;
    const int wid  = tid >> 5, lane = tid & 31;
    const int wm   = wid & 1;
    const int wn   = wid >> 1;
    const int m0   = (mb_base + blockIdx.y) * 128;
    const int n0   = blockIdx.x * 128;

    const uint32_t As_u = smem_u32(As);
    const uint32_t Bs_u = smem_u32(Bs);

    // ldmatrix lane address offsets (bytes)
    // A x4: lanes 0-7 rows 0-7 col+0 | 8-15 rows 8-15 col+0 | 16-23 rows 0-7 col+8 | 24-31 rows 8-15 col+8
    const uint32_t aOff = (uint32_t)(((wm * 64 + (lane & 15)) * LDPH + (lane >> 4) * 8) * 2);
    // B x4: lanes 0-7 n 0-7 col+0 | 8-15 n 0-7 col+8 | 16-23 n 8-15 col+0 | 24-31 n 8-15 col+8
    const uint32_t bOff = (uint32_t)(((wn * 32 + (lane & 7) + (lane >> 4) * 8) * LDPH
                                      + ((lane >> 3) & 1) * 8) * 2);

    float acc[4][4][4];
#pragma unroll
    for (int a = 0; a < 4; a++)
#pragma unroll
        for (int b = 0; b < 4; b++)
#pragma unroll
            for (int c = 0; c < 4; c++) acc[a][b][c] = 0.f;

#define LOAD_TILE(kt, s) do {                                                     \
    int _k0 = (kt) * 32;                                                          \
    _Pragma("unroll")                                                             \
    for (int _t = 0; _t < 2; _t++) {                                              \
        int _idx = tid + _t * 256;                                                \
        int _row = _idx >> 2, _seg = _idx & 3;                                    \
        const __half* _g = A + (size_t)(m0 + _row) * KAGG + _k0 + _seg * 8;       \
        CP_ASYNC16(As_u + (uint32_t)(((s) * TILEH + _row * LDPH + _seg * 8) * 2), _g); \
    }                                                                             \
    _Pragma("unroll")                                                             \
    for (int _t = 0; _t < 2; _t++) {                                              \
        int _idx = tid + _t * 256;                                                \
        int _row = _idx >> 2, _seg = _idx & 3;                                    \
        const __half* _g = B + (size_t)(n0 + _row) * KAGG + _k0 + _seg * 8;       \
        CP_ASYNC16(Bs_u + (uint32_t)(((s) * TILEH + _row * LDPH + _seg * 8) * 2), _g); \
    }                                                                             \
    CP_COMMIT();                                                                  \
} while (0)

    LOAD_TILE(0, 0);

    for (int kt = 0; kt < NCHUNK; kt++) {
        int s = kt & 1;
        if (kt + 1 < NCHUNK) { LOAD_TILE(kt + 1, s ^ 1); CP_WAIT1(); }
        else                 { CP_WAIT0(); }
        __syncthreads();

        const uint32_t aBase = As_u + (uint32_t)(s * TILEH * 2) + aOff;
        const uint32_t bBase = Bs_u + (uint32_t)(s * TILEH * 2) + bOff;

#pragma unroll
        for (int ks = 0; ks < 2; ks++) {
            const uint32_t kByte = (uint32_t)(ks * 32);   // 16 halfs
            uint32_t afr[4][4];
#pragma unroll
            for (int mi = 0; mi < 4; mi++)
                LDSM_X4(afr[mi][0], afr[mi][1], afr[mi][2], afr[mi][3],
                        aBase + (uint32_t)(mi * 16 * LDPH * 2) + kByte);
            uint32_t bfr[4][2];
#pragma unroll
            for (int nj = 0; nj < 2; nj++)
                LDSM_X4(bfr[nj * 2][0], bfr[nj * 2][1], bfr[nj * 2 + 1][0], bfr[nj * 2 + 1][1],
                        bBase + (uint32_t)(nj * 16 * LDPH * 2) + kByte);
#pragma unroll
            for (int mi = 0; mi < 4; mi++)
#pragma unroll
                for (int ni = 0; ni < 4; ni++)
                    mma_f16(acc[mi][ni], afr[mi], bfr[ni]);
        }
        __syncthreads();
    }

#pragma unroll
    for (int mi = 0; mi < 4; mi++) {
        int rbase = m0 + wm * 64 + mi * 16 + (lane >> 2);
#pragma unroll
        for (int half_ = 0; half_ < 2; half_++) {
            int r = rbase + half_ * 8;
            if (r >= N_FILE) continue;
            float he = hasedge[r];
#pragma unroll
            for (int ni = 0; ni < 4; ni++) {
                int c0 = n0 + wn * 32 + ni * 8 + (lane & 3) * 2;
                float v0 = acc[mi][ni][half_ * 2 + 0] + cbias[c0]     + he * bconst[c0];
                float v1 = acc[mi][ni][half_ * 2 + 1] + cbias[c0 + 1] + he * bconst[c0 + 1];
                *(float2*)(C + (size_t)r * N_OUT + c0) = make_float2(v0, v1);
            }
        }
    }
}

// ---------------- fp32 SGEMM (precompute-sized, batched z) ----
#define BM 128
#define BN 128
#define BK 8
#define TM 8
#define TN 8

__global__ __launch_bounds__(256, 2)
void sgemm(const float* __restrict__ A, int lda,
           const float* __restrict__ B, int ldb,
           float* __restrict__ C, int ldc,
           int M, int N, int K,
           long sA, long sB, long sC)
{
    A += (long)blockIdx.z * sA;
    B += (long)blockIdx.z * sB;
    C += (long)blockIdx.z * sC;

    __shared__ float As[BK][BM];
    __shared__ float Bs[BK][BN];
    const int tid = threadIdx.x;
    const int bm  = blockIdx.y * BM;
    const int bn  = blockIdx.x * BN;

    const int aRow  = tid >> 1;
    const int aCol4 = (tid & 1) * 4;
    const int bRow  = tid >> 5;
    const int bCol4 = (tid & 31) * 4;
    const int ty = tid >> 4, tx = tid & 15;

    float acc[TM][TN];
#pragma unroll
    for (int i = 0; i < TM; i++)
#pragma unroll
        for (int j = 0; j < TN; j++) acc[i][j] = 0.f;

    for (int k0 = 0; k0 < K; k0 += BK) {
        float4 av;
        if (bm + aRow < M)
            av = *(const float4*)(A + (size_t)(bm + aRow) * lda + k0 + aCol4);
        else
            av = make_float4(0.f, 0.f, 0.f, 0.f);
        As[aCol4 + 0][aRow] = av.x;
        As[aCol4 + 1][aRow] = av.y;
        As[aCol4 + 2][aRow] = av.z;
        As[aCol4 + 3][aRow] = av.w;

        float4 bv = *(const float4*)(B + (size_t)(k0 + bRow) * ldb + bn + bCol4);
        *(float4*)(&Bs[bRow][bCol4]) = bv;

        __syncthreads();
#pragma unroll
        for (int k = 0; k < BK; k++) {
            float ra[TM], rb[TN];
#pragma unroll
            for (int i = 0; i < TM; i++) ra[i] = As[k][ty * TM + i];
#pragma unroll
            for (int j = 0; j < TN; j++) rb[j] = Bs[k][tx * TN + j];
#pragma unroll
            for (int i = 0; i < TM; i++)
#pragma unroll
                for (int j = 0; j < TN; j++)
                    acc[i][j] = fmaf(ra[i], rb[j], acc[i][j]);
        }
        __syncthreads();
    }

#pragma unroll
    for (int i = 0; i < TM; i++) {
        int row = bm + ty * TM + i;
        if (row >= M) break;
#pragma unroll
        for (int j = 0; j < TN; j += 4) {
            int col = bn + tx * TN + j;
            float4 v;
            v.x = acc[i][j];     v.y = acc[i][j + 1];
            v.z = acc[i][j + 2]; v.w = acc[i][j + 3];
            *(float4*)(C + (size_t)row * ldc + col) = v;
        }
    }
}

// ---------------- coalesced GEVM ----------
__global__ __launch_bounds__(256)
void gevm(const float* __restrict__ x, const float* __restrict__ W,
          float* __restrict__ y, int K, int N, const float* __restrict__ add)
{
    int c  = blockIdx.x * 64 + (threadIdx.x & 63);
    int ks = threadIdx.x >> 6;
    int kper = K >> 2;
    int k0 = ks * kper, k1 = k0 + kper;
    float s = 0.f;
    for (int k = k0; k < k1; k++) s = fmaf(x[k], W[(size_t)k * N + c], s);
    __shared__ float sm[4][64];
    sm[ks][threadIdx.x & 63] = s;
    __syncthreads();
    if (ks == 0) {
        int l = threadIdx.x & 63;
        float v = sm[0][l] + sm[1][l] + sm[2][l] + sm[3][l];
        if (add) v += add[c];
        y[c] = v;
    }
}

// ---------------- generic warp-per-output dot kernels ----------
__device__ __forceinline__ float warp_sum(float s) {
#pragma unroll
    for (int o = 16; o > 0; o >>= 1) s += __shfl_down_sync(0xffffffffu, s, o);
    return s;
}

__global__ __launch_bounds__(256)
void k_hdot(const float* __restrict__ W, const float* __restrict__ v,
            float* __restrict__ out) {
    int wg = blockIdx.x * 8 + (threadIdx.x >> 5);
    int lane = threadIdx.x & 31;
    int k = wg / 3, h = wg - k * 3;
    const float* row = W + (size_t)k * HD + h * N_OUT;
    const float* vv  = v + h * N_OUT;
    float s = 0.f;
#pragma unroll
    for (int j = lane; j < N_OUT; j += 32) s = fmaf(row[j], vv[j], s);
    s = warp_sum(s);
    if (lane == 0) out[k * 3 + h] = s;
}

__global__ __launch_bounds__(256)
void k_mat3(const float* __restrict__ M, const float* __restrict__ vec,
            float* __restrict__ out) {
    int wg = blockIdx.x * 8 + (threadIdx.x >> 5);
    int lane = threadIdx.x & 31;
    int k = wg / 3, h = wg - k * 3;
    const float* row = M + (size_t)k * N_INP;
    float s = 0.f;
#pragma unroll
    for (int c = lane; c < N_INP; c += 32) s = fmaf(row[c], vec[c * 3 + h], s);
    s = warp_sum(s);
    if (lane == 0) out[k * 3 + h] = s;
}

__global__ void k_b3(const float* __restrict__ b, const float* __restrict__ vec,
                     float* __restrict__ out3) {
    int w = threadIdx.x >> 5, lane = threadIdx.x & 31;
    if (w >= NH) return;
    float s = 0.f;
    for (int c = lane; c < N_INP; c += 32)
        s = fmaf(b[c], vec[c * 3 + w], s);
    s = warp_sum(s);
    if (lane == 0) out3[w] = s;
}

// ---------------- transpose + fp16 round ----
__global__ void k_w2t() {
    __shared__ float tile[32][33];
    int nb = blockIdx.x * 32, kb = blockIdx.y * 32;
    int tx = threadIdx.x, ty = threadIdx.y;
#pragma unroll
    for (int j = 0; j < 32; j += 8)
        tile[ty + j][tx] = d_W2[(size_t)(kb + ty + j) * N_OUT + nb + tx];
    __syncthreads();
#pragma unroll
    for (int j = 0; j < 32; j += 8)
        d_W2Th[(size_t)(nb + ty + j) * KAGG + kb + tx] = __float2half_rn(tile[tx][ty + j]);
}

// ---------------- FUSED: emb_api fp32 -> fp16 + api node logits ----------------
// warp per node: read fp32 row once, write fp16 row, compute 3 attention dots.
__global__ __launch_bounds__(256)
void k_embel(const float* __restrict__ emb,
             const float* __restrict__ V,      // [512,3] (k*3+h)
             const float* __restrict__ b3)
{
    __shared__ float sv0[N_INP], sv1[N_INP], sv2[N_INP];
    __shared__ float sb[NH];
    int t = threadIdx.x;
    for (int i = t; i < N_INP; i += 256) {
        sv0[i] = V[i * 3 + 0];
        sv1[i] = V[i * 3 + 1];
        sv2[i] = V[i * 3 + 2];
    }
    if (t < NH) sb[t] = b3[t];
    __syncthreads();

    int wid = t >> 5, lane = t & 31;
    int n = blockIdx.x * 8 + wid;                  // 6250 blocks exactly covers 50000
    const float2* x2 = (const float2*)(emb + (size_t)n * N_INP);
    __half2* o2 = (__half2*)(d_embh + (size_t)n * N_INP);

    float s0 = 0.f, s1 = 0.f, s2 = 0.f;
#pragma unroll
    for (int j = 0; j < 8; j++) {
        int idx = j * 32 + lane;                   // float2 index; k = 2*idx
        float2 xv = x2[idx];
        o2[idx] = __floats2half2_rn(xv.x, xv.y);
        int k = idx * 2;
        float2 v0 = *(const float2*)&sv0[k];
        float2 v1 = *(const float2*)&sv1[k];
        float2 v2 = *(const float2*)&sv2[k];
        s0 = fmaf(xv.x, v0.x, fmaf(xv.y, v0.y, s0));
        s1 = fmaf(xv.x, v1.x, fmaf(xv.y, v1.y, s1));
        s2 = fmaf(xv.x, v2.x, fmaf(xv.y, v2.y, s2));
    }
    s0 = warp_sum(s0); s1 = warp_sum(s1); s2 = warp_sum(s2);
    if (lane == 0)
        *(float4*)(d_el + (size_t)n * 4) = make_float4(s0 + sb[0], s1 + sb[1], s2 + sb[2], 0.f);
}

// ---------------- node logits (file side) ----------------
__global__ void node_logits(const float* __restrict__ X,
                            const float* __restrict__ V,
                            const float* __restrict__ b3,
                            float* __restrict__ out, int Nn)
{
    __shared__ float sV[N_INP * NH];
    int t = threadIdx.x;
    for (int i = t; i < N_INP * NH; i += blockDim.x) sV[i] = V[i];
    __syncthreads();
    int warp = t >> 5, lane = t & 31;
    int n = blockIdx.x * (blockDim.x >> 5) + warp;
    if (n >= Nn) return;
    const float* x = X + (size_t)n * N_INP;
    float s0 = 0.f, s1 = 0.f, s2 = 0.f;
    for (int k = lane; k < N_INP; k += 32) {
        float xv = x[k];
        s0 = fmaf(xv, sV[k * 3 + 0], s0);
        s1 = fmaf(xv, sV[k * 3 + 1], s1);
        s2 = fmaf(xv, sV[k * 3 + 2], s2);
    }
#pragma unroll
    for (int o = 16; o > 0; o >>= 1) {
        s0 += __shfl_down_sync(0xffffffffu, s0, o);
        s1 += __shfl_down_sync(0xffffffffu, s1, o);
        s2 += __shfl_down_sync(0xffffffffu, s2, o);
    }
    if (lane == 0)
        *(float4*)(out + (size_t)n * 4) = make_float4(s0 + b3[0], s1 + b3[1], s2 + b3[2], 0.f);
}

// ---------------- CSR build (multi-block scan) ----------------
__global__ void k_zero() {
    int i = blockIdx.x * blockDim.x + threadIdx.x;
    if (i < N_FILE) { d_deg[i] = 0; d_cur[i] = 0; }
}

__global__ void k_count(const int* __restrict__ dst, int E) {
    int i = blockIdx.x * blockDim.x + threadIdx.x;
    if (i < E) atomicAdd(&d_deg[dst[i]], 1);
}

__global__ void k_scan1() {
    __shared__ int sh[512];
    int i = blockIdx.x * 512 + threadIdx.x;
    int v = (i < N_FILE) ? d_deg[i] : 0;
    sh[threadIdx.x] = v;
    __syncthreads();
    for (int o = 1; o < 512; o <<= 1) {
        int t = (threadIdx.x >= o) ? sh[threadIdx.x - o] : 0;
        __syncthreads();
        sh[threadIdx.x] += t;
        __syncthreads();
    }
    if (i < N_FILE) d_off[i] = sh[threadIdx.x] - v;
    if (threadIdx.x == 511) d_bsum[blockIdx.x] = sh[511];
}

__global__ void k_scan2() {
    if (threadIdx.x == 0) {
        int run = 0;
#pragma unroll
        for (int b = 0; b < SCAN_BLOCKS; b++) { d_bbase[b] = run; run += d_bsum[b]; }
        d_off[N_FILE] = run;
    }
}

__global__ void k_scan3() {
    int i = blockIdx.x * 512 + threadIdx.x;
    if (i < N_FILE) {
        d_off[i] += d_bbase[blockIdx.x];
        d_hasedge[i] = d_deg[i] ? 1.f : 0.f;
    }
}

__global__ void k_scatter(const int* __restrict__ src, const int* __restrict__ dst, int E) {
    int i = blockIdx.x * blockDim.x + threadIdx.x;
    if (i >= E) return;
    int d = dst[i];
    int p = atomicAdd(&d_cur[d], 1);
    d_srcs[d_off[d] + p] = src[i];
}

// ---------------- per-dst softmax + fp16 embedding aggregation ----------------
#define GCAP 1024

__global__ __launch_bounds__(128)
void gat_aggregate(int dbase)
{
    int d = dbase + blockIdx.x;
    int t = threadIdx.x;
    int lane = t & 31, warp = t >> 5;
    int start = d_off[d], end = d_off[d + 1];
    int deg = end - start;
    bool cached = (deg <= GCAP);

    __shared__ int   sh_src[GCAP];
    __shared__ float sh_w[GCAP * 3];
    __shared__ float s_er[4], s_m[3], s_iz[3];
    __shared__ float red[4][3];

    if (t < 4) s_er[t] = d_er[(size_t)d * 4 + t];
    __syncthreads();
    float er0 = s_er[0], er1 = s_er[1], er2 = s_er[2];
    const float4* el4 = (const float4*)d_el;

    float m0 = -CUDART_INF_F, m1 = -CUDART_INF_F, m2 = -CUDART_INF_F;
    for (int e = start + t; e < end; e += 128) {
        int s = d_srcs[e];
        float4 L = el4[s];
        float l0 = lrelu(L.x + er0), l1 = lrelu(L.y + er1), l2 = lrelu(L.z + er2);
        if (cached) {
            int i = e - start;
            sh_src[i] = s;
            sh_w[i * 3 + 0] = l0; sh_w[i * 3 + 1] = l1; sh_w[i * 3 + 2] = l2;
        }
        m0 = fmaxf(m0, l0); m1 = fmaxf(m1, l1); m2 = fmaxf(m2, l2);
    }
#pragma unroll
    for (int o = 16; o > 0; o >>= 1) {
        m0 = fmaxf(m0, __shfl_xor_sync(0xffffffffu, m0, o));
        m1 = fmaxf(m1, __shfl_xor_sync(0xffffffffu, m1, o));
        m2 = fmaxf(m2, __shfl_xor_sync(0xffffffffu, m2, o));
    }
    if (lane == 0) { red[warp][0] = m0; red[warp][1] = m1; red[warp][2] = m2; }
    __syncthreads();
    if (t < 3) s_m[t] = fmaxf(fmaxf(red[0][t], red[1][t]), fmaxf(red[2][t], red[3][t]));
    __syncthreads();
    m0 = s_m[0]; m1 = s_m[1]; m2 = s_m[2];

    float z0 = 0.f, z1 = 0.f, z2 = 0.f;
    for (int e = start + t; e < end; e += 128) {
        float l0, l1, l2;
        if (cached) {
            int i = e - start;
            l0 = sh_w[i * 3 + 0]; l1 = sh_w[i * 3 + 1]; l2 = sh_w[i * 3 + 2];
        } else {
            int s = d_srcs[e];
            float4 L = el4[s];
            l0 = lrelu(L.x + er0); l1 = lrelu(L.y + er1); l2 = lrelu(L.z + er2);
        }
        z0 += __expf(l0 - m0); z1 += __expf(l1 - m1); z2 += __expf(l2 - m2);
    }
#pragma unroll
    for (int o = 16; o > 0; o >>= 1) {
        z0 += __shfl_xor_sync(0xffffffffu, z0, o);
        z1 += __shfl_xor_sync(0xffffffffu, z1, o);
        z2 += __shfl_xor_sync(0xffffffffu, z2, o);
    }
    if (lane == 0) { red[warp][0] = z0; red[warp][1] = z1; red[warp][2] = z2; }
    __syncthreads();
    if (t < 3) {
        float z = red[0][t] + red[1][t] + red[2][t] + red[3][t];
        s_iz[t] = (z > 0.f) ? 1.f / z : 0.f;
    }
    __syncthreads();
    float iz0 = s_iz[0], iz1 = s_iz[1], iz2 = s_iz[2];

    if (cached) {
        for (int i = t; i < deg; i += 128) {
            sh_w[i * 3 + 0] = __expf(sh_w[i * 3 + 0] - m0) * iz0;
            sh_w[i * 3 + 1] = __expf(sh_w[i * 3 + 1] - m1) * iz1;
            sh_w[i * 3 + 2] = __expf(sh_w[i * 3 + 2] - m2) * iz2;
        }
    }
    __syncthreads();

    float a00 = 0.f, a01 = 0.f, a02 = 0.f, a03 = 0.f;
    float a10 = 0.f, a11 = 0.f, a12 = 0.f, a13 = 0.f;
    float a20 = 0.f, a21 = 0.f, a22 = 0.f, a23 = 0.f;
    int c4 = t * 4;

#define GATHER_FMA(sidx, w0, w1, w2) do {                                      \
    uint2 _v = *(const uint2*)(d_embh + (size_t)(sidx) * N_INP + c4);          \
    float2 _f0 = __half22float2(*(__half2*)&_v.x);                             \
    float2 _f1 = __half22float2(*(__half2*)&_v.y);                             \
    a00 = fmaf(w0, _f0.x, a00); a01 = fmaf(w0, _f0.y, a01);                    \
    a02 = fmaf(w0, _f1.x, a02); a03 = fmaf(w0, _f1.y, a03);                    \
    a10 = fmaf(w1, _f0.x, a10); a11 = fmaf(w1, _f0.y, a11);                    \
    a12 = fmaf(w1, _f1.x, a12); a13 = fmaf(w1, _f1.y, a13);                    \
    a20 = fmaf(w2, _f0.x, a20); a21 = fmaf(w2, _f0.y, a21);                    \
    a22 = fmaf(w2, _f1.x, a22); a23 = fmaf(w2, _f1.y, a23);                    \
} while (0)

    if (cached) {
        int i = 0;
        for (; i + 1 < deg; i += 2) {
            int   sA_ = sh_src[i],       sB_ = sh_src[i + 1];
            float wA0 = sh_w[i * 3 + 0], wB0 = sh_w[i * 3 + 3];
            float wA1 = sh_w[i * 3 + 1], wB1 = sh_w[i * 3 + 4];
            float wA2 = sh_w[i * 3 + 2], wB2 = sh_w[i * 3 + 5];
            GATHER_FMA(sA_, wA0, wA1, wA2);
            GATHER_FMA(sB_, wB0, wB1, wB2);
        }
        if (i < deg) {
            int s = sh_src[i];
            GATHER_FMA(s, sh_w[i * 3 + 0], sh_w[i * 3 + 1], sh_w[i * 3 + 2]);
        }
    } else {
        for (int e = start; e < end; e++) {
            int s = d_srcs[e];
            float4 L = el4[s];
            float w0 = __expf(lrelu(L.x + er0) - m0) * iz0;
            float w1 = __expf(lrelu(L.y + er1) - m1) * iz1;
            float w2 = __expf(lrelu(L.z + er2) - m2) * iz2;
            GATHER_FMA(s, w0, w1, w2);
        }
    }

    __half* aout = d_aggh + (size_t)d * KAGG;
    __half2 o00 = __floats2half2_rn(a00, a01), o01 = __floats2half2_rn(a02, a03);
    __half2 o10 = __floats2half2_rn(a10, a11), o11 = __floats2half2_rn(a12, a13);
    __half2 o20 = __floats2half2_rn(a20, a21), o21 = __floats2half2_rn(a22, a23);
    uint2 w;
    w.x = *(uint32_t*)&o00; w.y = *(uint32_t*)&o01;
    *(uint2*)(aout + 0 * N_INP + c4) = w;
    w.x = *(uint32_t*)&o10; w.y = *(uint32_t*)&o11;
    *(uint2*)(aout + 1 * N_INP + c4) = w;
    w.x = *(uint32_t*)&o20; w.y = *(uint32_t*)&o21;
    *(uint2*)(aout + 2 * N_INP + c4) = w;
}

// ---------------- launch ----------------
extern "C" void kernel_launch(void* const* d_in, const int* in_sizes, int n_in,
                              void* d_out, int out_size)
{
    const float* emb_api  = (const float*)d_in[0];
    const float* emb_file = (const float*)d_in[1];
    const int*   src      = (const int*)d_in[3];
    const int*   dst      = (const int*)d_in[4];
    const float* Wapi     = (const float*)d_in[5];
    const float* bapi     = (const float*)d_in[6];
    const float* Wfile    = (const float*)d_in[7];
    const float* bfile    = (const float*)d_in[8];
    const float* Wsrc     = (const float*)d_in[9];
    const float* Wdst     = (const float*)d_in[10];
    const float* attn_l   = (const float*)d_in[11];
    const float* attn_r   = (const float*)d_in[12];
    const float* gat_bias = (const float*)d_in[13];
    const float* Whead    = (const float*)d_in[14];
    const float* bhead    = (const float*)d_in[15];
    float* out = (float*)d_out;

    const int E = in_sizes[3];

    float *p_Wcomb, *p_W2, *p_u, *p_vli, *p_Vl, *p_Vr, *p_bl, *p_br, *p_bconst,
          *p_cbias, *p_er, *p_hasedge, *p_bsrc;
    __half *p_W2Th, *p_aggh;
    cudaGetSymbolAddress((void**)&p_Wcomb,   d_Wcomb);
    cudaGetSymbolAddress((void**)&p_W2,      d_W2);
    cudaGetSymbolAddress((void**)&p_W2Th,    d_W2Th);
    cudaGetSymbolAddress((void**)&p_aggh,    d_aggh);
    cudaGetSymbolAddress((void**)&p_u,       d_u);
    cudaGetSymbolAddress((void**)&p_vli,     d_vli);
    cudaGetSymbolAddress((void**)&p_Vl,      d_Vl);
    cudaGetSymbolAddress((void**)&p_Vr,      d_Vr);
    cudaGetSymbolAddress((void**)&p_bl,      d_bl);
    cudaGetSymbolAddress((void**)&p_br,      d_br);
    cudaGetSymbolAddress((void**)&p_bconst,  d_bconst);
    cudaGetSymbolAddress((void**)&p_cbias,   d_cbias);
    cudaGetSymbolAddress((void**)&p_er,      d_er);
    cudaGetSymbolAddress((void**)&p_hasedge, d_hasedge);
    cudaGetSymbolAddress((void**)&p_bsrc,    d_bsrc);

    cudaFuncSetAttribute(gemm_mma, cudaFuncAttributeMaxDynamicSharedMemorySize, GEMM_SMEM_BYTES);

    static cudaStream_t s1 = nullptr, s2 = nullptr, s3 = nullptr;
    static cudaEvent_t ev0, ev_csr, ev_s2, ev_a0, ev_a1, ev_done;
    if (!s1) {
        cudaStreamCreateWithFlags(&s1, cudaStreamNonBlocking);
        cudaStreamCreateWithFlags(&s2, cudaStreamNonBlocking);
        cudaStreamCreateWithFlags(&s3, cudaStreamNonBlocking);
        cudaEventCreateWithFlags(&ev0,     cudaEventDisableTiming);
        cudaEventCreateWithFlags(&ev_csr,  cudaEventDisableTiming);
        cudaEventCreateWithFlags(&ev_s2,   cudaEventDisableTiming);
        cudaEventCreateWithFlags(&ev_a0,   cudaEventDisableTiming);
        cudaEventCreateWithFlags(&ev_a1,   cudaEventDisableTiming);
        cudaEventCreateWithFlags(&ev_done, cudaEventDisableTiming);
    }

    // fork
    cudaEventRecord(ev0, 0);
    cudaStreamWaitEvent(s1, ev0, 0);
    cudaStreamWaitEvent(s2, ev0, 0);
    cudaStreamWaitEvent(s3, ev0, 0);

    // ---- s1: CSR build ----
    k_zero   <<<(N_FILE + 255) / 256, 256, 0, s1>>>();
    k_count  <<<(E + 255) / 256, 256, 0, s1>>>(dst, E);
    k_scan1  <<<SCAN_BLOCKS, 512, 0, s1>>>();
    k_scan2  <<<1, 32, 0, s1>>>();
    k_scan3  <<<SCAN_BLOCKS, 512, 0, s1>>>();
    k_scatter<<<(E + 255) / 256, 256, 0, s1>>>(src, dst, E);
    cudaEventRecord(ev_csr, s1);

    // ---- default: api logit path + fused fp16 conversion ----
    k_hdot<<<192, 256>>>(Wsrc, attn_l, p_vli);          // vli = Wsrc_h @ attn_l_h
    k_mat3<<<192, 256>>>(Wapi, p_vli, p_Vl);            // Vl  = Wapi @ vli
    k_b3<<<1, 128>>>(bapi, p_vli, p_bl);                 // bl  = bapi . vli
    k_embel<<<N_API / 8, 256>>>(emb_api, p_Vl, p_bl);    // embh + el in ONE pass

    // ---- s3: Wcomb -> W2 -> w2t (independent of default; starts at t=0) ----
    sgemm<<<dim3(HD / BN, N_INP / BM, 1), 256, 0, s3>>>(
        Wapi, N_INP, Wsrc, HD, p_Wcomb, HD, N_INP, HD, N_INP, 0, 0, 0);
    sgemm<<<dim3(N_OUT / BN, N_INP / BM, NH), 256, 0, s3>>>(
        p_Wcomb, HD, Whead, N_OUT, p_W2, N_OUT,
        N_INP, N_OUT, N_OUT,
        (long)N_OUT, (long)N_OUT * N_OUT, (long)N_INP * N_OUT);
    k_w2t<<<dim3(N_OUT / 32, KAGG / 32), dim3(32, 8), 0, s3>>>();

    // ---- s2: file-side precompute + gemm epilogue constants ----
    k_hdot<<<192, 256, 0, s2>>>(Wdst, attn_r, p_u);
    k_mat3<<<192, 256, 0, s2>>>(Wfile, p_u, p_Vr);
    k_b3<<<1, 128, 0, s2>>>(bfile, p_u, p_br);
    node_logits<<<(N_FILE + 7) / 8, 256, 0, s2>>>(emb_file, p_Vr, p_br, p_er, N_FILE);
    gevm<<<HD / 64, 256, 0, s2>>>(bapi, Wsrc, p_bsrc, N_INP, HD, nullptr);
    gevm<<<N_OUT / 64, 256, 0, s2>>>(gat_bias, Whead, p_cbias, HD, N_OUT, bhead);
    gevm<<<N_OUT / 64, 256, 0, s2>>>(p_bsrc, Whead, p_bconst, HD, N_OUT, nullptr);
    cudaEventRecord(ev_s2, s2);

    // ---- default: aggregation chunks ----
    cudaStreamWaitEvent(0, ev_csr, 0);
    cudaStreamWaitEvent(0, ev_s2, 0);
    gat_aggregate<<<CH0_DST, 128>>>(0);
    cudaEventRecord(ev_a0, 0);
    gat_aggregate<<<CH1_DST, 128>>>(CH0_DST);
    cudaEventRecord(ev_a1, 0);

    // ---- s3: gemm chunks ----
    cudaStreamWaitEvent(s3, ev_csr, 0);
    cudaStreamWaitEvent(s3, ev_s2, 0);
    cudaStreamWaitEvent(s3, ev_a0, 0);
    gemm_mma<<<dim3(N_OUT / 128, CH0_BLOCKS), 256, GEMM_SMEM_BYTES, s3>>>(
        p_aggh, p_W2Th, out, p_cbias, p_bconst, p_hasedge, 0);
    cudaStreamWaitEvent(s3, ev_a1, 0);
    gemm_mma<<<dim3(N_OUT / 128, CH1_BLOCKS), 256, GEMM_SMEM_BYTES, s3>>>(
        p_aggh, p_W2Th, out, p_cbias, p_bconst, p_hasedge, CH0_BLOCKS);
    cudaEventRecord(ev_done, s3);

    // join
    cudaStreamWaitEvent(0, ev_done, 0);
}